// round 1
// baseline (speedup 1.0000x reference)
#include <cuda_runtime.h>
#include <math.h>

#define DM 768
#define NH 12
#define DH 64
#define BB 4
#define TT 2048
#define MROWS (BB*TT)   // 8192

// Scratch (device globals — no allocation allowed)
__device__ float g_q[BB*NH*TT*DH];
__device__ float g_k[BB*NH*TT*DH];
__device__ float g_v[BB*NH*TT*DH];
__device__ float g_y[BB*TT*DM];

// ---------------------------------------------------------------------------
// SGEMM: C[M,N] = A[M,K] @ W[N,K]^T + bias  (both operands K-major, "NT" gemm)
// 128x128 block tile, BK=8, 256 threads, 8x8 micro-tile split as 4+4 (offset 64)
// PERMUTE=1: store to [B, H, T, Dh] (for q/k/v). PERMUTE=0: row-major [M, N].
// ---------------------------------------------------------------------------
template<int PERMUTE>
__global__ __launch_bounds__(256)
void sgemm_nt(const float* __restrict__ A, const float* __restrict__ W,
              const float* __restrict__ bias, float* __restrict__ C)
{
    __shared__ float As[8][132];
    __shared__ float Bs[8][132];

    const int tid = threadIdx.x;
    const int tx = tid & 15;
    const int ty = tid >> 4;
    const int m0 = blockIdx.y * 128;
    const int n0 = blockIdx.x * 128;

    const int lrow = tid >> 1;        // 0..127
    const int lk   = (tid & 1) * 4;   // 0 or 4

    const float* Ap = A + (m0 + lrow) * DM + lk;
    const float* Wr = W + (n0 + lrow) * DM + lk;

    float acc[8][8];
    #pragma unroll
    for (int i = 0; i < 8; i++)
        #pragma unroll
        for (int j = 0; j < 8; j++) acc[i][j] = 0.f;

    for (int k0 = 0; k0 < DM; k0 += 8) {
        float4 av = *reinterpret_cast<const float4*>(Ap + k0);
        float4 wv = *reinterpret_cast<const float4*>(Wr + k0);
        As[lk+0][lrow] = av.x; As[lk+1][lrow] = av.y;
        As[lk+2][lrow] = av.z; As[lk+3][lrow] = av.w;
        Bs[lk+0][lrow] = wv.x; Bs[lk+1][lrow] = wv.y;
        Bs[lk+2][lrow] = wv.z; Bs[lk+3][lrow] = wv.w;
        __syncthreads();

        #pragma unroll
        for (int kk = 0; kk < 8; kk++) {
            float a[8], b[8];
            *reinterpret_cast<float4*>(&a[0]) = *reinterpret_cast<const float4*>(&As[kk][ty*4]);
            *reinterpret_cast<float4*>(&a[4]) = *reinterpret_cast<const float4*>(&As[kk][ty*4+64]);
            *reinterpret_cast<float4*>(&b[0]) = *reinterpret_cast<const float4*>(&Bs[kk][tx*4]);
            *reinterpret_cast<float4*>(&b[4]) = *reinterpret_cast<const float4*>(&Bs[kk][tx*4+64]);
            #pragma unroll
            for (int i = 0; i < 8; i++)
                #pragma unroll
                for (int j = 0; j < 8; j++)
                    acc[i][j] = fmaf(a[i], b[j], acc[i][j]);
        }
        __syncthreads();
    }

    #pragma unroll
    for (int hi = 0; hi < 2; hi++) {
        #pragma unroll
        for (int ii = 0; ii < 4; ii++) {
            const int row = m0 + ty*4 + hi*64 + ii;
            const int bb  = row >> 11;     // /2048
            const int t   = row & 2047;
            #pragma unroll
            for (int hj = 0; hj < 2; hj++) {
                const int col = n0 + tx*4 + hj*64;
                float4 val;
                val.x = acc[hi*4+ii][hj*4+0] + bias[col+0];
                val.y = acc[hi*4+ii][hj*4+1] + bias[col+1];
                val.z = acc[hi*4+ii][hj*4+2] + bias[col+2];
                val.w = acc[hi*4+ii][hj*4+3] + bias[col+3];
                if (PERMUTE) {
                    const int h = col >> 6;
                    const int d = col & 63;
                    *reinterpret_cast<float4*>(&C[((bb*NH + h)*TT + t)*DH + d]) = val;
                } else {
                    *reinterpret_cast<float4*>(&C[row*DM + col]) = val;
                }
            }
        }
    }
}

// ---------------------------------------------------------------------------
// Flash-attention (fp32, causal). One block per (q-block of 64 rows, b*h).
// Br=64, Bc=32, 256 threads. Thread owns 2 rows; S micro-tile 2x4, PV 2x8.
// Smem: Q[64][65], K/P^T[32][65], V[32][65] = 33280 B (static).
// ---------------------------------------------------------------------------
__global__ __launch_bounds__(256)
void attn_kernel(const float* __restrict__ q, const float* __restrict__ k,
                 const float* __restrict__ v, float* __restrict__ y)
{
    __shared__ float Qs[64][65];
    __shared__ float Ks[32][65];   // reused as P^T after S is consumed
    __shared__ float Vs[32][65];

    const int tid = threadIdx.x;
    const int qb  = blockIdx.x;    // 0..31
    const int bh  = blockIdx.y;    // 0..47
    const int rp  = tid >> 3;      // 0..31 (row pair)
    const int oct = tid & 7;       // 0..7
    const int r0  = rp * 2;

    const float* qg = q + (size_t)(bh * TT + qb * 64) * DH;
    const float* kg = k + (size_t)bh * TT * DH;
    const float* vg = v + (size_t)bh * TT * DH;

    // Load Q tile (64x64)
    {
        const int row = tid >> 2;
        const int d0  = (tid & 3) * 16;
        #pragma unroll
        for (int i = 0; i < 4; i++) {
            float4 t4 = *reinterpret_cast<const float4*>(qg + row * DH + d0 + i*4);
            Qs[row][d0+i*4+0] = t4.x;
            Qs[row][d0+i*4+1] = t4.y;
            Qs[row][d0+i*4+2] = t4.z;
            Qs[row][d0+i*4+3] = t4.w;
        }
    }

    float o[2][8];
    #pragma unroll
    for (int rr = 0; rr < 2; rr++)
        #pragma unroll
        for (int dd = 0; dd < 8; dd++) o[rr][dd] = 0.f;
    float m[2] = {-1e30f, -1e30f};
    float l[2] = {0.f, 0.f};

    const int rg0 = qb*64 + r0;
    const int nkb = qb*2 + 2;

    for (int kb = 0; kb < nkb; kb++) {
        __syncthreads();   // previous P^T / V consumers done
        // Load K and V tiles (32x64 each)
        {
            const int c  = tid >> 3;
            const int d0 = oct * 8;
            const float* kp = kg + (size_t)(kb*32 + c) * DH + d0;
            const float* vp = vg + (size_t)(kb*32 + c) * DH + d0;
            float4 ka = *reinterpret_cast<const float4*>(kp);
            float4 kb4 = *reinterpret_cast<const float4*>(kp + 4);
            float4 va = *reinterpret_cast<const float4*>(vp);
            float4 vb = *reinterpret_cast<const float4*>(vp + 4);
            Ks[c][d0+0]=ka.x; Ks[c][d0+1]=ka.y; Ks[c][d0+2]=ka.z; Ks[c][d0+3]=ka.w;
            Ks[c][d0+4]=kb4.x; Ks[c][d0+5]=kb4.y; Ks[c][d0+6]=kb4.z; Ks[c][d0+7]=kb4.w;
            Vs[c][d0+0]=va.x; Vs[c][d0+1]=va.y; Vs[c][d0+2]=va.z; Vs[c][d0+3]=va.w;
            Vs[c][d0+4]=vb.x; Vs[c][d0+5]=vb.y; Vs[c][d0+6]=vb.z; Vs[c][d0+7]=vb.w;
        }
        __syncthreads();

        // S = Q K^T : rows r0, r0+1; cols oct*4 .. +3
        float s[2][4];
        #pragma unroll
        for (int c = 0; c < 4; c++) { s[0][c] = 0.f; s[1][c] = 0.f; }
        #pragma unroll 8
        for (int d = 0; d < 64; d++) {
            const float q0 = Qs[r0][d];
            const float q1 = Qs[r0+1][d];
            #pragma unroll
            for (int c = 0; c < 4; c++) {
                const float kv = Ks[oct*4+c][d];
                s[0][c] = fmaf(q0, kv, s[0][c]);
                s[1][c] = fmaf(q1, kv, s[1][c]);
            }
        }

        // scale + causal mask
        #pragma unroll
        for (int rr = 0; rr < 2; rr++) {
            const int rg = rg0 + rr;
            #pragma unroll
            for (int c = 0; c < 4; c++) {
                const int cg = kb*32 + oct*4 + c;
                s[rr][c] = (cg <= rg) ? s[rr][c] * 0.125f : -1e30f;
            }
        }

        // online softmax update
        #pragma unroll
        for (int rr = 0; rr < 2; rr++) {
            float mx = fmaxf(fmaxf(s[rr][0], s[rr][1]), fmaxf(s[rr][2], s[rr][3]));
            mx = fmaxf(mx, __shfl_xor_sync(0xffffffffu, mx, 1));
            mx = fmaxf(mx, __shfl_xor_sync(0xffffffffu, mx, 2));
            mx = fmaxf(mx, __shfl_xor_sync(0xffffffffu, mx, 4));
            const float mn = fmaxf(m[rr], mx);
            const float alpha = __expf(m[rr] - mn);
            m[rr] = mn;
            float ps = 0.f;
            #pragma unroll
            for (int c = 0; c < 4; c++) {
                s[rr][c] = __expf(s[rr][c] - mn);
                ps += s[rr][c];
            }
            l[rr] = l[rr]*alpha + ps;
            #pragma unroll
            for (int dd = 0; dd < 8; dd++) o[rr][dd] *= alpha;
        }

        __syncthreads();   // everyone done reading K
        // store P^T into Ks: Pt[c][row]
        #pragma unroll
        for (int rr = 0; rr < 2; rr++)
            #pragma unroll
            for (int c = 0; c < 4; c++)
                Ks[oct*4+c][r0+rr] = s[rr][c];
        __syncthreads();

        // O += P V  (thread: rows r0,r0+1; d = oct*8 .. +7)
        const int d0 = oct * 8;
        #pragma unroll 8
        for (int c = 0; c < 32; c++) {
            const float p0 = Ks[c][r0];
            const float p1 = Ks[c][r0+1];
            #pragma unroll
            for (int dd = 0; dd < 8; dd++) {
                const float vv = Vs[c][d0+dd];
                o[0][dd] = fmaf(p0, vv, o[0][dd]);
                o[1][dd] = fmaf(p1, vv, o[1][dd]);
            }
        }
    }

    // finalize: reduce l across the 8 threads sharing each row, normalize, store
    const int bbv = bh / NH;
    const int h   = bh % NH;
    #pragma unroll
    for (int rr = 0; rr < 2; rr++) {
        float lt = l[rr];
        lt += __shfl_xor_sync(0xffffffffu, lt, 1);
        lt += __shfl_xor_sync(0xffffffffu, lt, 2);
        lt += __shfl_xor_sync(0xffffffffu, lt, 4);
        const float inv = 1.f / lt;
        const int trow = qb*64 + r0 + rr;
        float* dst = y + (size_t)(bbv*TT + trow)*DM + h*DH + oct*8;
        float4 v0, v1;
        v0.x = o[rr][0]*inv; v0.y = o[rr][1]*inv; v0.z = o[rr][2]*inv; v0.w = o[rr][3]*inv;
        v1.x = o[rr][4]*inv; v1.y = o[rr][5]*inv; v1.z = o[rr][6]*inv; v1.w = o[rr][7]*inv;
        *reinterpret_cast<float4*>(dst)     = v0;
        *reinterpret_cast<float4*>(dst + 4) = v1;
    }
}

// ---------------------------------------------------------------------------
extern "C" void kernel_launch(void* const* d_in, const int* in_sizes, int n_in,
                              void* d_out, int out_size)
{
    const float* x  = (const float*)d_in[0];
    const float* Wq = (const float*)d_in[1];
    const float* bq = (const float*)d_in[2];
    const float* Wk = (const float*)d_in[3];
    const float* bk = (const float*)d_in[4];
    const float* Wv = (const float*)d_in[5];
    const float* bv = (const float*)d_in[6];
    const float* Wp = (const float*)d_in[7];
    const float* bp = (const float*)d_in[8];
    float* out = (float*)d_out;

    float *qp, *kp, *vp, *yp;
    cudaGetSymbolAddress((void**)&qp, g_q);
    cudaGetSymbolAddress((void**)&kp, g_k);
    cudaGetSymbolAddress((void**)&vp, g_v);
    cudaGetSymbolAddress((void**)&yp, g_y);

    dim3 gemm_grid(DM/128, MROWS/128);   // (6, 64)
    dim3 gemm_blk(256);

    sgemm_nt<1><<<gemm_grid, gemm_blk>>>(x, Wq, bq, qp);
    sgemm_nt<1><<<gemm_grid, gemm_blk>>>(x, Wk, bk, kp);
    sgemm_nt<1><<<gemm_grid, gemm_blk>>>(x, Wv, bv, vp);

    dim3 attn_grid(TT/64, BB*NH);        // (32, 48)
    attn_kernel<<<attn_grid, 256>>>(qp, kp, vp, yp);

    sgemm_nt<0><<<gemm_grid, gemm_blk>>>(yp, Wp, bp, out);
}

// round 3
// speedup vs baseline: 2.4222x; 2.4222x over previous
#include <cuda_runtime.h>
#include <math.h>

#define DM 768
#define NH 12
#define DH 64
#define BB 4
#define TT 2048
#define MROWS (BB*TT)   // 8192

// Scratch (device globals — no allocation allowed)
__device__ float g_q[BB*NH*TT*DH];
__device__ float g_k[BB*NH*TT*DH];
__device__ float g_v[BB*NH*TT*DH];
__device__ float g_y[BB*TT*DM];

// ---------------------------------------------------------------------------
// helpers
// ---------------------------------------------------------------------------
__device__ __forceinline__ float f2tf(float f) {
    unsigned u;
    asm("cvt.rna.tf32.f32 %0, %1;" : "=r"(u) : "f"(f));
    return __uint_as_float(u);
}
__device__ __forceinline__ float ex2(float x) {
    float r;
    asm("ex2.approx.f32 %0, %1;" : "=f"(r) : "f"(x));
    return r;
}
__device__ __forceinline__ void mma8(float d[4],
                                     float a0, float a1, float a2, float a3,
                                     float b0, float b1) {
    asm volatile(
        "mma.sync.aligned.m16n8k8.row.col.f32.tf32.tf32.f32 "
        "{%0,%1,%2,%3}, {%4,%5,%6,%7}, {%8,%9}, {%0,%1,%2,%3};\n"
        : "+f"(d[0]), "+f"(d[1]), "+f"(d[2]), "+f"(d[3])
        : "r"(__float_as_uint(a0)), "r"(__float_as_uint(a1)),
          "r"(__float_as_uint(a2)), "r"(__float_as_uint(a3)),
          "r"(__float_as_uint(b0)), "r"(__float_as_uint(b1)));
}

// ---------------------------------------------------------------------------
// TF32 GEMM (3x split): C[M,N] = A[M,768] @ W[N,768]^T + bias   (NT)
// BM=128 BN=128 BK=16. 256 threads = 8 warps (2m x 4n); warp tile 64x32.
// Plain row-major padded tiles, stride 20 floats:
//   - loader STS.128 conflict-free (20r mod 32 distinct over any 8 rows)
//   - fragment scalar LDS conflict-free (20*(lane>>2) + (lane&3) covers 32 banks)
// Fragment mapping = documented PTX m16n8k8 tf32 layout.
// ---------------------------------------------------------------------------
#define GST 20

template<int PERMUTE>
__global__ __launch_bounds__(256, 2)
void gemm_tf32(const float* __restrict__ A, const float* __restrict__ W,
               const float* __restrict__ bias, float* __restrict__ C)
{
    __shared__ float As[2][128][GST];
    __shared__ float Bs[2][128][GST];

    const int tid  = threadIdx.x;
    const int lane = tid & 31;
    const int wid  = tid >> 5;
    const int m0 = blockIdx.y * 128;
    const int n0 = blockIdx.x * 128;
    const int wm = wid >> 2;       // 0..1
    const int wn = wid & 3;        // 0..3
    const int g  = lane >> 2;      // group (row within 8)
    const int c  = lane & 3;       // k-lane

    // loader mapping: each thread loads 8 floats of A and 8 of W per BK=16
    const int lrow  = tid & 127;
    const int lhalf = tid >> 7;    // 0/1 selects k-subblock of 8
    const float* pa = A + (size_t)(m0 + lrow) * DM + lhalf * 8;
    const float* pw = W + (size_t)(n0 + lrow) * DM + lhalf * 8;

    float acc[4][4][4];
    #pragma unroll
    for (int i = 0; i < 4; i++)
        #pragma unroll
        for (int j = 0; j < 4; j++)
            #pragma unroll
            for (int r = 0; r < 4; r++) acc[i][j][r] = 0.f;

    float4 ar0, ar1, br0, br1;
    ar0 = *(const float4*)(pa);     ar1 = *(const float4*)(pa + 4);
    br0 = *(const float4*)(pw);     br1 = *(const float4*)(pw + 4);

    #pragma unroll 1
    for (int it = 0; it < 48; ++it) {
        const int buf = it & 1;
        {
            float* as = &As[buf][lrow][lhalf * 8];
            *(float4*)(as)     = ar0;  *(float4*)(as + 4) = ar1;
            float* bs = &Bs[buf][lrow][lhalf * 8];
            *(float4*)(bs)     = br0;  *(float4*)(bs + 4) = br1;
        }
        __syncthreads();

        if (it < 47) {
            const float* p = pa + (it + 1) * 16;
            ar0 = *(const float4*)(p);   ar1 = *(const float4*)(p + 4);
            const float* q = pw + (it + 1) * 16;
            br0 = *(const float4*)(q);   br1 = *(const float4*)(q + 4);
        }

        #pragma unroll
        for (int h = 0; h < 2; ++h) {
            // B fragments (n = wn*32+ni*8+g ; k = h*8 + c / c+4)
            float bh[4][2], bl[4][2];
            #pragma unroll
            for (int ni = 0; ni < 4; ++ni) {
                const int nrow = wn * 32 + ni * 8 + g;
                float x0 = Bs[buf][nrow][h * 8 + c];
                float x1 = Bs[buf][nrow][h * 8 + c + 4];
                bh[ni][0] = f2tf(x0);  bl[ni][0] = x0 - bh[ni][0];
                bh[ni][1] = f2tf(x1);  bl[ni][1] = x1 - bh[ni][1];
            }
            #pragma unroll
            for (int mi = 0; mi < 4; ++mi) {
                const int mrow = wm * 64 + mi * 16 + g;
                float y0 = As[buf][mrow][h * 8 + c];        // a0: (g,   c)
                float y1 = As[buf][mrow + 8][h * 8 + c];    // a1: (g+8, c)
                float y2 = As[buf][mrow][h * 8 + c + 4];    // a2: (g,   c+4)
                float y3 = As[buf][mrow + 8][h * 8 + c + 4];// a3: (g+8, c+4)
                float ah0 = f2tf(y0), al0 = y0 - ah0;
                float ah1 = f2tf(y1), al1 = y1 - ah1;
                float ah2 = f2tf(y2), al2 = y2 - ah2;
                float ah3 = f2tf(y3), al3 = y3 - ah3;
                #pragma unroll
                for (int ni = 0; ni < 4; ++ni) {
                    mma8(acc[mi][ni], ah0, ah1, ah2, ah3, bh[ni][0], bh[ni][1]);
                    mma8(acc[mi][ni], ah0, ah1, ah2, ah3, bl[ni][0], bl[ni][1]);
                    mma8(acc[mi][ni], al0, al1, al2, al3, bh[ni][0], bh[ni][1]);
                }
            }
        }
        __syncthreads();
    }

    // ---- epilogue: d0,d1 at (g, 2c..2c+1); d2,d3 at (g+8, same cols) ----
    #pragma unroll
    for (int mi = 0; mi < 4; ++mi) {
        const int row = m0 + wm * 64 + mi * 16 + g;
        #pragma unroll
        for (int ni = 0; ni < 4; ++ni) {
            const int col = n0 + wn * 32 + ni * 8 + c * 2;
            float2 bv = *(const float2*)(bias + col);
            float2 v0 = make_float2(acc[mi][ni][0] + bv.x, acc[mi][ni][1] + bv.y);
            float2 v1 = make_float2(acc[mi][ni][2] + bv.x, acc[mi][ni][3] + bv.y);
            if (PERMUTE) {
                const int bb = row >> 11;
                const int t  = row & 2047;
                const int hh = col >> 6;
                const int d  = col & 63;
                float* base = g_q /*unused*/, *dst;
                (void)base;
                dst = C + ((size_t)(bb * NH + hh) * TT + t) * DH + d;
                *(float2*)(dst)          = v0;
                *(float2*)(dst + 8 * DH) = v1;
            } else {
                *(float2*)(C + (size_t)row * DM + col)       = v0;
                *(float2*)(C + (size_t)(row + 8) * DM + col) = v1;
            }
        }
    }
}

// ---------------------------------------------------------------------------
// Flash attention. Br=64, Bc=64, 128 threads (4 warps), warp owns 16 q-rows.
// QK^T single tf32 (logit abs err ~1e-4); PV with 3x split.
// Smem: KP[64][68] (K tile, later reused for P), Vs[64][72].
// All fragments = documented PTX layouts over row-major padded tiles.
// ---------------------------------------------------------------------------
#define KST 68
#define VST 72

__global__ __launch_bounds__(128)
void attn_tf32(const float* __restrict__ q, const float* __restrict__ k,
               const float* __restrict__ v, float* __restrict__ y)
{
    __shared__ float KP[64 * KST];   // 17408 B
    __shared__ float Vs[64 * VST];   // 18432 B

    const int tid  = threadIdx.x;
    const int lane = tid & 31;
    const int wid  = tid >> 5;
    const int qb = blockIdx.x;       // 0..31
    const int bh = blockIdx.y;       // 0..47
    const int g  = lane >> 2;        // 0..7
    const int c  = lane & 3;         // 0..3

    // ---- Q fragments: A layout of m16n8k8; pre-scaled, tf32-rounded ----
    const float SC = 0.125f * 1.4426950408889634f;
    const float* qg = q + ((size_t)bh * TT + qb * 64 + wid * 16) * DH;
    float qf[8][4];
    #pragma unroll
    for (int h = 0; h < 8; ++h) {
        qf[h][0] = f2tf(qg[(size_t)g * DH + h * 8 + c] * SC);
        qf[h][1] = f2tf(qg[(size_t)(g + 8) * DH + h * 8 + c] * SC);
        qf[h][2] = f2tf(qg[(size_t)g * DH + h * 8 + c + 4] * SC);
        qf[h][3] = f2tf(qg[(size_t)(g + 8) * DH + h * 8 + c + 4] * SC);
    }

    float o[8][4];
    #pragma unroll
    for (int i = 0; i < 8; ++i)
        #pragma unroll
        for (int j = 0; j < 4; ++j) o[i][j] = 0.f;
    float m_lo = -1e30f, m_hi = -1e30f, l_lo = 0.f, l_hi = 0.f;

    const float* kg = k + (size_t)bh * TT * DH;
    const float* vg = v + (size_t)bh * TT * DH;

    // loader: warp w loads keys [w*16, w*16+16); coalesced 256B rows
    const int lkey0 = wid * 16 + (lane >> 4) * 8;   // +rr
    const int lcol  = (lane & 15) * 4;

    const int row_lo = qb * 64 + wid * 16 + g;
    const int row_hi = row_lo + 8;

    for (int kb = 0; kb <= qb; ++kb) {
        __syncthreads();   // prior iteration fully done with KP/Vs

        // ---- load K (tf32-rounded at store) and V (raw) ----
        const float* kbp = kg + (size_t)kb * 64 * DH;
        const float* vbp = vg + (size_t)kb * 64 * DH;
        #pragma unroll
        for (int rr = 0; rr < 8; ++rr) {
            const int key = lkey0 + rr;
            float4 t = *(const float4*)(kbp + (size_t)key * DH + lcol);
            t.x = f2tf(t.x); t.y = f2tf(t.y); t.z = f2tf(t.z); t.w = f2tf(t.w);
            *(float4*)(&KP[key * KST + lcol]) = t;
        }
        #pragma unroll
        for (int rr = 0; rr < 8; ++rr) {
            const int key = lkey0 + rr;
            float4 t = *(const float4*)(vbp + (size_t)key * DH + lcol);
            *(float4*)(&Vs[key * VST + lcol]) = t;
        }
        __syncthreads();

        // ---- S = Q K^T : B frag b0 = K[nt*8+g][h*8+c], b1 = col+4 ----
        float s[8][4];
        #pragma unroll
        for (int i = 0; i < 8; ++i)
            #pragma unroll
            for (int j = 0; j < 4; ++j) s[i][j] = 0.f;

        #pragma unroll
        for (int h = 0; h < 8; ++h) {
            #pragma unroll
            for (int nt = 0; nt < 8; ++nt) {
                const float b0 = KP[(nt * 8 + g) * KST + h * 8 + c];
                const float b1 = KP[(nt * 8 + g) * KST + h * 8 + c + 4];
                mma8(s[nt], qf[h][0], qf[h][1], qf[h][2], qf[h][3], b0, b1);
            }
        }

        // ---- causal mask (diagonal block only) ----
        if (kb == qb) {
            #pragma unroll
            for (int nt = 0; nt < 8; ++nt) {
                const int k0 = kb * 64 + nt * 8 + c * 2;
                if (k0 > row_lo)     s[nt][0] = -1e30f;
                if (k0 + 1 > row_lo) s[nt][1] = -1e30f;
                if (k0 > row_hi)     s[nt][2] = -1e30f;
                if (k0 + 1 > row_hi) s[nt][3] = -1e30f;
            }
        }

        // ---- online softmax (log2 domain) ----
        {
            float mx = -1e30f;
            #pragma unroll
            for (int nt = 0; nt < 8; ++nt) mx = fmaxf(mx, fmaxf(s[nt][0], s[nt][1]));
            mx = fmaxf(mx, __shfl_xor_sync(0xffffffffu, mx, 1));
            mx = fmaxf(mx, __shfl_xor_sync(0xffffffffu, mx, 2));
            const float mn = fmaxf(m_lo, mx);
            const float al = ex2(m_lo - mn);
            m_lo = mn;
            float ls = 0.f;
            #pragma unroll
            for (int nt = 0; nt < 8; ++nt) {
                s[nt][0] = ex2(s[nt][0] - mn); ls += s[nt][0];
                s[nt][1] = ex2(s[nt][1] - mn); ls += s[nt][1];
                o[nt][0] *= al; o[nt][1] *= al;
            }
            l_lo = l_lo * al + ls;
        }
        {
            float mx = -1e30f;
            #pragma unroll
            for (int nt = 0; nt < 8; ++nt) mx = fmaxf(mx, fmaxf(s[nt][2], s[nt][3]));
            mx = fmaxf(mx, __shfl_xor_sync(0xffffffffu, mx, 1));
            mx = fmaxf(mx, __shfl_xor_sync(0xffffffffu, mx, 2));
            const float mn = fmaxf(m_hi, mx);
            const float al = ex2(m_hi - mn);
            m_hi = mn;
            float ls = 0.f;
            #pragma unroll
            for (int nt = 0; nt < 8; ++nt) {
                s[nt][2] = ex2(s[nt][2] - mn); ls += s[nt][2];
                s[nt][3] = ex2(s[nt][3] - mn); ls += s[nt][3];
                o[nt][2] *= al; o[nt][3] *= al;
            }
            l_hi = l_hi * al + ls;
        }

        __syncthreads();  // all warps finished reading K region -> reuse as P

        // ---- store P (full fp32) to its own rows: warp-private region ----
        #pragma unroll
        for (int nt = 0; nt < 8; ++nt) {
            *(float2*)(&KP[(wid * 16 + g) * KST + nt * 8 + c * 2])     = make_float2(s[nt][0], s[nt][1]);
            *(float2*)(&KP[(wid * 16 + g + 8) * KST + nt * 8 + c * 2]) = make_float2(s[nt][2], s[nt][3]);
        }
        __syncwarp();

        // ---- O += P V  (3x split) ----
        #pragma unroll
        for (int kc = 0; kc < 8; ++kc) {
            const int pr = wid * 16 + g;
            float y0 = KP[pr * KST + kc * 8 + c];
            float y1 = KP[(pr + 8) * KST + kc * 8 + c];
            float y2 = KP[pr * KST + kc * 8 + c + 4];
            float y3 = KP[(pr + 8) * KST + kc * 8 + c + 4];
            float ah0 = f2tf(y0), al0 = y0 - ah0;
            float ah1 = f2tf(y1), al1 = y1 - ah1;
            float ah2 = f2tf(y2), al2 = y2 - ah2;
            float ah3 = f2tf(y3), al3 = y3 - ah3;
            #pragma unroll
            for (int nt = 0; nt < 8; ++nt) {
                float v0 = Vs[(kc * 8 + c) * VST + nt * 8 + g];
                float v1 = Vs[(kc * 8 + c + 4) * VST + nt * 8 + g];
                float vh0 = f2tf(v0), vl0 = v0 - vh0;
                float vh1 = f2tf(v1), vl1 = v1 - vh1;
                mma8(o[nt], ah0, ah1, ah2, ah3, vh0, vh1);
                mma8(o[nt], ah0, ah1, ah2, ah3, vl0, vl1);
                mma8(o[nt], al0, al1, al2, al3, vh0, vh1);
            }
        }
    }

    // ---- epilogue ----
    l_lo += __shfl_xor_sync(0xffffffffu, l_lo, 1);
    l_lo += __shfl_xor_sync(0xffffffffu, l_lo, 2);
    l_hi += __shfl_xor_sync(0xffffffffu, l_hi, 1);
    l_hi += __shfl_xor_sync(0xffffffffu, l_hi, 2);
    const float inv_lo = 1.f / l_lo;
    const float inv_hi = 1.f / l_hi;

    const int bbv = bh / NH;
    const int hh  = bh % NH;
    float* y_lo = y + ((size_t)bbv * TT + row_lo) * DM + hh * DH + c * 2;
    float* y_hi = y + ((size_t)bbv * TT + row_hi) * DM + hh * DH + c * 2;
    #pragma unroll
    for (int nt = 0; nt < 8; ++nt) {
        *(float2*)(y_lo + nt * 8) = make_float2(o[nt][0] * inv_lo, o[nt][1] * inv_lo);
        *(float2*)(y_hi + nt * 8) = make_float2(o[nt][2] * inv_hi, o[nt][3] * inv_hi);
    }
}

// ---------------------------------------------------------------------------
extern "C" void kernel_launch(void* const* d_in, const int* in_sizes, int n_in,
                              void* d_out, int out_size)
{
    const float* x  = (const float*)d_in[0];
    const float* Wq = (const float*)d_in[1];
    const float* bq = (const float*)d_in[2];
    const float* Wk = (const float*)d_in[3];
    const float* bk = (const float*)d_in[4];
    const float* Wv = (const float*)d_in[5];
    const float* bv = (const float*)d_in[6];
    const float* Wp = (const float*)d_in[7];
    const float* bp = (const float*)d_in[8];
    float* out = (float*)d_out;

    float *qp, *kp, *vp, *yp;
    cudaGetSymbolAddress((void**)&qp, g_q);
    cudaGetSymbolAddress((void**)&kp, g_k);
    cudaGetSymbolAddress((void**)&vp, g_v);
    cudaGetSymbolAddress((void**)&yp, g_y);

    dim3 gemm_grid(DM / 128, MROWS / 128);   // (6, 64)

    gemm_tf32<1><<<gemm_grid, 256>>>(x, Wq, bq, qp);
    gemm_tf32<1><<<gemm_grid, 256>>>(x, Wk, bk, kp);
    gemm_tf32<1><<<gemm_grid, 256>>>(x, Wv, bv, vp);

    dim3 attn_grid(TT / 64, BB * NH);        // (32, 48)
    attn_tf32<<<attn_grid, 128>>>(qp, kp, vp, yp);

    gemm_tf32<0><<<gemm_grid, 256>>>(yp, Wp, bp, out);
}

// round 4
// speedup vs baseline: 2.9515x; 1.2185x over previous
#include <cuda_runtime.h>
#include <cuda_bf16.h>
#include <math.h>

#define DM 768
#define NH 12
#define DH 64
#define BB 4
#define TT 2048
#define MROWS (BB*TT)   // 8192

// Scratch (device globals — no allocation allowed)
__device__ float g_q[BB*NH*TT*DH];
__device__ float g_k[BB*NH*TT*DH];
__device__ float g_v[BB*NH*TT*DH];
__device__ float g_y[BB*TT*DM];

// ---------------------------------------------------------------------------
// helpers
// ---------------------------------------------------------------------------
__device__ __forceinline__ float f2tf(float f) {
    unsigned u;
    asm("cvt.rna.tf32.f32 %0, %1;" : "=r"(u) : "f"(f));
    return __uint_as_float(u);
}
__device__ __forceinline__ float ex2(float x) {
    float r;
    asm("ex2.approx.f32 %0, %1;" : "=f"(r) : "f"(x));
    return r;
}
// tf32 m16n8k8
__device__ __forceinline__ void mma8(float d[4],
                                     float a0, float a1, float a2, float a3,
                                     float b0, float b1) {
    asm volatile(
        "mma.sync.aligned.m16n8k8.row.col.f32.tf32.tf32.f32 "
        "{%0,%1,%2,%3}, {%4,%5,%6,%7}, {%8,%9}, {%0,%1,%2,%3};\n"
        : "+f"(d[0]), "+f"(d[1]), "+f"(d[2]), "+f"(d[3])
        : "r"(__float_as_uint(a0)), "r"(__float_as_uint(a1)),
          "r"(__float_as_uint(a2)), "r"(__float_as_uint(a3)),
          "r"(__float_as_uint(b0)), "r"(__float_as_uint(b1)));
}
// bf16 m16n8k16
__device__ __forceinline__ void mma16(float d[4],
                                      unsigned a0, unsigned a1, unsigned a2, unsigned a3,
                                      unsigned b0, unsigned b1) {
    asm volatile(
        "mma.sync.aligned.m16n8k16.row.col.f32.bf16.bf16.f32 "
        "{%0,%1,%2,%3}, {%4,%5,%6,%7}, {%8,%9}, {%0,%1,%2,%3};\n"
        : "+f"(d[0]), "+f"(d[1]), "+f"(d[2]), "+f"(d[3])
        : "r"(a0), "r"(a1), "r"(a2), "r"(a3), "r"(b0), "r"(b1));
}
__device__ __forceinline__ unsigned pack_bf(__nv_bfloat16 a, __nv_bfloat16 b) {
    __nv_bfloat162 t = __halves2bfloat162(a, b);
    return *reinterpret_cast<unsigned*>(&t);
}
__device__ __forceinline__ unsigned pack_f(float a, float b) {
    __nv_bfloat162 t = __floats2bfloat162_rn(a, b);
    return *reinterpret_cast<unsigned*>(&t);
}
// split x = hi(bf16) + lo(float, to be bf16-rounded at pack)
__device__ __forceinline__ void bsplit(float x, __nv_bfloat16& h, float& l) {
    h = __float2bfloat16(x);
    l = x - __bfloat162float(h);
}

// ---------------------------------------------------------------------------
// bf16x3 GEMM: C[M,N] = A[M,768] @ W[N,768]^T + bias   (NT)
// BM=128 BN=128 BK=16. 256 threads = 8 warps (2m x 4n); warp tile 64x32.
// smem: hi/lo bf16 tiles, stride 24 halves (frag LDS banks 12g+c: conflict-free)
// QKV merged via blockIdx.z (kills wave quantization).
// ---------------------------------------------------------------------------
#define HST 24

template<int PERMUTE>
__global__ __launch_bounds__(256, 2)
void gemm_bf16x3(const float* __restrict__ A,
                 const float* __restrict__ W0, const float* __restrict__ W1,
                 const float* __restrict__ W2,
                 const float* __restrict__ b0_, const float* __restrict__ b1_,
                 const float* __restrict__ b2_,
                 float* __restrict__ C0, float* __restrict__ C1,
                 float* __restrict__ C2)
{
    // [buf][tile: 0=AH 1=AL 2=BH 3=BL][row][k]
    __shared__ __align__(16) unsigned short sh[2][4][128][HST];

    const int z = blockIdx.z;
    const float* W    = (z == 0) ? W0 : ((z == 1) ? W1 : W2);
    const float* bias = (z == 0) ? b0_ : ((z == 1) ? b1_ : b2_);
    float*       C    = (z == 0) ? C0 : ((z == 1) ? C1 : C2);

    const int tid  = threadIdx.x;
    const int lane = tid & 31;
    const int wid  = tid >> 5;
    const int m0 = blockIdx.y * 128;
    const int n0 = blockIdx.x * 128;
    const int wm = wid >> 2;       // 0..1
    const int wn = wid & 3;        // 0..3
    const int g  = lane >> 2;      // 0..7
    const int c  = lane & 3;       // 0..3

    const int lrow  = tid & 127;
    const int lhalf = tid >> 7;    // k-offset 0 / 8
    const float* pa = A + (size_t)(m0 + lrow) * DM + lhalf * 8;
    const float* pw = W + (size_t)(n0 + lrow) * DM + lhalf * 8;

    float acc[4][4][4];
    #pragma unroll
    for (int i = 0; i < 4; i++)
        #pragma unroll
        for (int j = 0; j < 4; j++)
            #pragma unroll
            for (int r = 0; r < 4; r++) acc[i][j][r] = 0.f;

    float4 ar0, ar1, wr0, wr1;
    ar0 = *(const float4*)(pa);     ar1 = *(const float4*)(pa + 4);
    wr0 = *(const float4*)(pw);     wr1 = *(const float4*)(pw + 4);

    #pragma unroll 1
    for (int it = 0; it < 48; ++it) {
        const int buf = it & 1;
        {
            float av[8] = {ar0.x, ar0.y, ar0.z, ar0.w, ar1.x, ar1.y, ar1.z, ar1.w};
            float wv[8] = {wr0.x, wr0.y, wr0.z, wr0.w, wr1.x, wr1.y, wr1.z, wr1.w};
            unsigned* pAH = (unsigned*)&sh[buf][0][lrow][lhalf * 8];
            unsigned* pAL = (unsigned*)&sh[buf][1][lrow][lhalf * 8];
            unsigned* pBH = (unsigned*)&sh[buf][2][lrow][lhalf * 8];
            unsigned* pBL = (unsigned*)&sh[buf][3][lrow][lhalf * 8];
            #pragma unroll
            for (int j = 0; j < 4; ++j) {
                __nv_bfloat16 h0, h1; float l0, l1;
                bsplit(av[2*j],   h0, l0);
                bsplit(av[2*j+1], h1, l1);
                pAH[j] = pack_bf(h0, h1);
                pAL[j] = pack_f(l0, l1);
                bsplit(wv[2*j],   h0, l0);
                bsplit(wv[2*j+1], h1, l1);
                pBH[j] = pack_bf(h0, h1);
                pBL[j] = pack_f(l0, l1);
            }
        }
        __syncthreads();

        if (it < 47) {
            const float* p = pa + (it + 1) * 16;
            ar0 = *(const float4*)(p);   ar1 = *(const float4*)(p + 4);
            const float* q = pw + (it + 1) * 16;
            wr0 = *(const float4*)(q);   wr1 = *(const float4*)(q + 4);
        }

        // ---- compute: frags straight from documented m16n8k16 layout ----
        {
            unsigned bh[4][2], bl[4][2];
            #pragma unroll
            for (int ni = 0; ni < 4; ++ni) {
                const int nr = wn * 32 + ni * 8 + g;
                bh[ni][0] = *(const unsigned*)&sh[buf][2][nr][2 * c];
                bh[ni][1] = *(const unsigned*)&sh[buf][2][nr][2 * c + 8];
                bl[ni][0] = *(const unsigned*)&sh[buf][3][nr][2 * c];
                bl[ni][1] = *(const unsigned*)&sh[buf][3][nr][2 * c + 8];
            }
            #pragma unroll
            for (int mi = 0; mi < 4; ++mi) {
                const int mr = wm * 64 + mi * 16 + g;
                unsigned ah0 = *(const unsigned*)&sh[buf][0][mr][2 * c];
                unsigned ah1 = *(const unsigned*)&sh[buf][0][mr + 8][2 * c];
                unsigned ah2 = *(const unsigned*)&sh[buf][0][mr][2 * c + 8];
                unsigned ah3 = *(const unsigned*)&sh[buf][0][mr + 8][2 * c + 8];
                unsigned al0 = *(const unsigned*)&sh[buf][1][mr][2 * c];
                unsigned al1 = *(const unsigned*)&sh[buf][1][mr + 8][2 * c];
                unsigned al2 = *(const unsigned*)&sh[buf][1][mr][2 * c + 8];
                unsigned al3 = *(const unsigned*)&sh[buf][1][mr + 8][2 * c + 8];
                #pragma unroll
                for (int ni = 0; ni < 4; ++ni) {
                    mma16(acc[mi][ni], ah0, ah1, ah2, ah3, bh[ni][0], bh[ni][1]);
                    mma16(acc[mi][ni], ah0, ah1, ah2, ah3, bl[ni][0], bl[ni][1]);
                    mma16(acc[mi][ni], al0, al1, al2, al3, bh[ni][0], bh[ni][1]);
                }
            }
        }
        __syncthreads();
    }

    // ---- epilogue: d0,d1 at (g, 2c..2c+1); d2,d3 at (g+8, same cols) ----
    #pragma unroll
    for (int mi = 0; mi < 4; ++mi) {
        const int row = m0 + wm * 64 + mi * 16 + g;
        #pragma unroll
        for (int ni = 0; ni < 4; ++ni) {
            const int col = n0 + wn * 32 + ni * 8 + c * 2;
            float2 bv = *(const float2*)(bias + col);
            float2 v0 = make_float2(acc[mi][ni][0] + bv.x, acc[mi][ni][1] + bv.y);
            float2 v1 = make_float2(acc[mi][ni][2] + bv.x, acc[mi][ni][3] + bv.y);
            if (PERMUTE) {
                const int bb = row >> 11;
                const int t  = row & 2047;
                const int hh = col >> 6;
                const int d  = col & 63;
                float* dst = C + ((size_t)(bb * NH + hh) * TT + t) * DH + d;
                *(float2*)(dst)          = v0;
                *(float2*)(dst + 8 * DH) = v1;
            } else {
                *(float2*)(C + (size_t)row * DM + col)       = v0;
                *(float2*)(C + (size_t)(row + 8) * DM + col) = v1;
            }
        }
    }
}

// ---------------------------------------------------------------------------
// Flash attention. Br=64, Bc=64, 128 threads (4 warps), warp owns 16 q-rows.
// QK^T: single tf32 (sets the accuracy floor ~1e-4, measured OK).
// PV:   bf16x3 m16n8k16; P fragments are THREAD-LOCAL from the S accumulator
//       (documented layout identity) — no smem round-trip for P.
// V staged transposed as bf16 hi/lo, stride 72 halves (frag banks 4g+c: clean).
// ---------------------------------------------------------------------------
#define KST 68
#define VSTR 72

__global__ __launch_bounds__(128)
void attn_tf32(const float* __restrict__ q, const float* __restrict__ k,
               const float* __restrict__ v, float* __restrict__ y)
{
    __shared__ __align__(16) float KP[64 * KST];             // 17408 B
    __shared__ __align__(16) unsigned short VT[2][64 * VSTR];// 18432 B (hi, lo)

    const int tid  = threadIdx.x;
    const int lane = tid & 31;
    const int wid  = tid >> 5;
    const int qb = blockIdx.x;       // 0..31
    const int bh = blockIdx.y;       // 0..47
    const int g  = lane >> 2;        // 0..7
    const int c  = lane & 3;         // 0..3

    // ---- Q fragments (pre-scaled by 1/8*log2e, tf32-rounded) ----
    const float SC = 0.125f * 1.4426950408889634f;
    const float* qg = q + ((size_t)bh * TT + qb * 64 + wid * 16) * DH;
    float qf[8][4];
    #pragma unroll
    for (int h = 0; h < 8; ++h) {
        qf[h][0] = f2tf(qg[(size_t)g * DH + h * 8 + c] * SC);
        qf[h][1] = f2tf(qg[(size_t)(g + 8) * DH + h * 8 + c] * SC);
        qf[h][2] = f2tf(qg[(size_t)g * DH + h * 8 + c + 4] * SC);
        qf[h][3] = f2tf(qg[(size_t)(g + 8) * DH + h * 8 + c + 4] * SC);
    }

    float o[8][4];
    #pragma unroll
    for (int i = 0; i < 8; ++i)
        #pragma unroll
        for (int j = 0; j < 4; ++j) o[i][j] = 0.f;
    float m_lo = -1e30f, m_hi = -1e30f, l_lo = 0.f, l_hi = 0.f;

    const float* kg = k + (size_t)bh * TT * DH;
    const float* vg = v + (size_t)bh * TT * DH;

    // K loader: warp w stages keys [w*16, w*16+16)
    const int lkey0 = wid * 16 + (lane >> 4) * 8;   // + rr
    const int lcol  = (lane & 15) * 4;
    // V loader: key pair + d-group
    const int vkp = lane & 7;              // key pair index
    const int vdg = lane >> 3;             // 0..3
    const int vlk = wid * 16 + 2 * vkp;    // local even key

    const int row_lo = qb * 64 + wid * 16 + g;
    const int row_hi = row_lo + 8;

    for (int kb = 0; kb <= qb; ++kb) {
        __syncthreads();   // prior iteration done with KP/VT

        // ---- stage K (tf32-rounded fp32) ----
        const float* kbp = kg + (size_t)kb * 64 * DH;
        #pragma unroll
        for (int rr = 0; rr < 8; ++rr) {
            const int key = lkey0 + rr;
            float4 t = *(const float4*)(kbp + (size_t)key * DH + lcol);
            t.x = f2tf(t.x); t.y = f2tf(t.y); t.z = f2tf(t.z); t.w = f2tf(t.w);
            *(float4*)(&KP[key * KST + lcol]) = t;
        }
        // ---- stage V transposed as bf16 hi/lo ----
        const float* vbp = vg + (size_t)kb * 64 * DH;
        #pragma unroll
        for (int rr = 0; rr < 4; ++rr) {
            const int d0 = rr * 16 + vdg * 4;
            float4 v0 = *(const float4*)(vbp + (size_t)vlk * DH + d0);
            float4 v1 = *(const float4*)(vbp + (size_t)(vlk + 1) * DH + d0);
            float a0[4] = {v0.x, v0.y, v0.z, v0.w};
            float a1[4] = {v1.x, v1.y, v1.z, v1.w};
            #pragma unroll
            for (int i = 0; i < 4; ++i) {
                __nv_bfloat16 h0, h1; float l0, l1;
                bsplit(a0[i], h0, l0);
                bsplit(a1[i], h1, l1);
                *(unsigned*)&VT[0][(d0 + i) * VSTR + vlk] = pack_bf(h0, h1);
                *(unsigned*)&VT[1][(d0 + i) * VSTR + vlk] = pack_f(l0, l1);
            }
        }
        __syncthreads();

        // ---- S = Q K^T (single tf32) ----
        float s[8][4];
        #pragma unroll
        for (int i = 0; i < 8; ++i)
            #pragma unroll
            for (int j = 0; j < 4; ++j) s[i][j] = 0.f;

        #pragma unroll
        for (int h = 0; h < 8; ++h) {
            #pragma unroll
            for (int nt = 0; nt < 8; ++nt) {
                const float b0 = KP[(nt * 8 + g) * KST + h * 8 + c];
                const float b1 = KP[(nt * 8 + g) * KST + h * 8 + c + 4];
                mma8(s[nt], qf[h][0], qf[h][1], qf[h][2], qf[h][3], b0, b1);
            }
        }

        // ---- causal mask (diagonal block only) ----
        if (kb == qb) {
            #pragma unroll
            for (int nt = 0; nt < 8; ++nt) {
                const int k0 = kb * 64 + nt * 8 + c * 2;
                if (k0 > row_lo)     s[nt][0] = -1e30f;
                if (k0 + 1 > row_lo) s[nt][1] = -1e30f;
                if (k0 > row_hi)     s[nt][2] = -1e30f;
                if (k0 + 1 > row_hi) s[nt][3] = -1e30f;
            }
        }

        // ---- online softmax (log2 domain) ----
        {
            float mx = -1e30f;
            #pragma unroll
            for (int nt = 0; nt < 8; ++nt) mx = fmaxf(mx, fmaxf(s[nt][0], s[nt][1]));
            mx = fmaxf(mx, __shfl_xor_sync(0xffffffffu, mx, 1));
            mx = fmaxf(mx, __shfl_xor_sync(0xffffffffu, mx, 2));
            const float mn = fmaxf(m_lo, mx);
            const float al = ex2(m_lo - mn);
            m_lo = mn;
            float ls = 0.f;
            #pragma unroll
            for (int nt = 0; nt < 8; ++nt) {
                s[nt][0] = ex2(s[nt][0] - mn); ls += s[nt][0];
                s[nt][1] = ex2(s[nt][1] - mn); ls += s[nt][1];
                o[nt][0] *= al; o[nt][1] *= al;
            }
            l_lo = l_lo * al + ls;
        }
        {
            float mx = -1e30f;
            #pragma unroll
            for (int nt = 0; nt < 8; ++nt) mx = fmaxf(mx, fmaxf(s[nt][2], s[nt][3]));
            mx = fmaxf(mx, __shfl_xor_sync(0xffffffffu, mx, 1));
            mx = fmaxf(mx, __shfl_xor_sync(0xffffffffu, mx, 2));
            const float mn = fmaxf(m_hi, mx);
            const float al = ex2(m_hi - mn);
            m_hi = mn;
            float ls = 0.f;
            #pragma unroll
            for (int nt = 0; nt < 8; ++nt) {
                s[nt][2] = ex2(s[nt][2] - mn); ls += s[nt][2];
                s[nt][3] = ex2(s[nt][3] - mn); ls += s[nt][3];
                o[nt][2] *= al; o[nt][3] *= al;
            }
            l_hi = l_hi * al + ls;
        }

        // ---- O += P V  (bf16x3; P frags thread-local from S) ----
        #pragma unroll
        for (int kc = 0; kc < 4; ++kc) {
            __nv_bfloat16 h00, h01, h02, h03, h10, h11, h12, h13;
            float l00, l01, l02, l03, l10, l11, l12, l13;
            bsplit(s[2*kc][0],   h00, l00);  bsplit(s[2*kc][1],   h01, l01);
            bsplit(s[2*kc][2],   h02, l02);  bsplit(s[2*kc][3],   h03, l03);
            bsplit(s[2*kc+1][0], h10, l10);  bsplit(s[2*kc+1][1], h11, l11);
            bsplit(s[2*kc+1][2], h12, l12);  bsplit(s[2*kc+1][3], h13, l13);
            const unsigned ah0 = pack_bf(h00, h01);   // (row g,   k 2c..2c+1)
            const unsigned ah1 = pack_bf(h02, h03);   // (row g+8, k 2c..2c+1)
            const unsigned ah2 = pack_bf(h10, h11);   // (row g,   k 2c+8..9)
            const unsigned ah3 = pack_bf(h12, h13);   // (row g+8, k 2c+8..9)
            const unsigned al0 = pack_f(l00, l01);
            const unsigned al1 = pack_f(l02, l03);
            const unsigned al2 = pack_f(l10, l11);
            const unsigned al3 = pack_f(l12, l13);
            #pragma unroll
            for (int nt = 0; nt < 8; ++nt) {
                const int base = (nt * 8 + g) * VSTR + kc * 16 + 2 * c;
                const unsigned vh0 = *(const unsigned*)&VT[0][base];
                const unsigned vh1 = *(const unsigned*)&VT[0][base + 8];
                const unsigned vl0 = *(const unsigned*)&VT[1][base];
                const unsigned vl1 = *(const unsigned*)&VT[1][base + 8];
                mma16(o[nt], ah0, ah1, ah2, ah3, vh0, vh1);
                mma16(o[nt], ah0, ah1, ah2, ah3, vl0, vl1);
                mma16(o[nt], al0, al1, al2, al3, vh0, vh1);
            }
        }
    }

    // ---- epilogue ----
    l_lo += __shfl_xor_sync(0xffffffffu, l_lo, 1);
    l_lo += __shfl_xor_sync(0xffffffffu, l_lo, 2);
    l_hi += __shfl_xor_sync(0xffffffffu, l_hi, 1);
    l_hi += __shfl_xor_sync(0xffffffffu, l_hi, 2);
    const float inv_lo = 1.f / l_lo;
    const float inv_hi = 1.f / l_hi;

    const int bbv = bh / NH;
    const int hh  = bh % NH;
    float* y_lo = y + ((size_t)bbv * TT + row_lo) * DM + hh * DH + c * 2;
    float* y_hi = y + ((size_t)bbv * TT + row_hi) * DM + hh * DH + c * 2;
    #pragma unroll
    for (int nt = 0; nt < 8; ++nt) {
        *(float2*)(y_lo + nt * 8) = make_float2(o[nt][0] * inv_lo, o[nt][1] * inv_lo);
        *(float2*)(y_hi + nt * 8) = make_float2(o[nt][2] * inv_hi, o[nt][3] * inv_hi);
    }
}

// ---------------------------------------------------------------------------
extern "C" void kernel_launch(void* const* d_in, const int* in_sizes, int n_in,
                              void* d_out, int out_size)
{
    const float* x  = (const float*)d_in[0];
    const float* Wq = (const float*)d_in[1];
    const float* bq = (const float*)d_in[2];
    const float* Wk = (const float*)d_in[3];
    const float* bk = (const float*)d_in[4];
    const float* Wv = (const float*)d_in[5];
    const float* bv = (const float*)d_in[6];
    const float* Wp = (const float*)d_in[7];
    const float* bp = (const float*)d_in[8];
    float* out = (float*)d_out;

    float *qp, *kp, *vp, *yp;
    cudaGetSymbolAddress((void**)&qp, g_q);
    cudaGetSymbolAddress((void**)&kp, g_k);
    cudaGetSymbolAddress((void**)&vp, g_v);
    cudaGetSymbolAddress((void**)&yp, g_y);

    // merged QKV: z selects projection (fills 4 waves instead of 3 x 1.3)
    dim3 qkv_grid(DM / 128, MROWS / 128, 3);   // (6, 64, 3)
    gemm_bf16x3<1><<<qkv_grid, 256>>>(x, Wq, Wk, Wv, bq, bk, bv, qp, kp, vp);

    dim3 attn_grid(TT / 64, BB * NH);          // (32, 48)
    attn_tf32<<<attn_grid, 128>>>(qp, kp, vp, yp);

    dim3 proj_grid(DM / 128, MROWS / 128, 1);
    gemm_bf16x3<0><<<proj_grid, 256>>>(yp, Wp, Wp, Wp, bp, bp, bp, out, out, out);
}

// round 6
// speedup vs baseline: 3.4389x; 1.1651x over previous
#include <cuda_runtime.h>
#include <cuda_bf16.h>
#include <math.h>

#define DM 768
#define NH 12
#define DH 64
#define BB 4
#define TT 2048
#define MROWS (BB*TT)   // 8192
#define ZSZ ((size_t)BB*NH*TT*DH)   // per-tensor q/k/v elems

// ---------------- scratch (device globals; no allocation allowed) ----------
__device__ __nv_bfloat16 g_xh[(size_t)MROWS*DM], g_xl[(size_t)MROWS*DM];
__device__ __nv_bfloat16 g_wh[4*(size_t)DM*DM], g_wl[4*(size_t)DM*DM];
__device__ __nv_bfloat16 g_h3[3*ZSZ], g_l3[3*ZSZ];      // q,k,v hi / lo
__device__ __nv_bfloat16 g_yh[(size_t)MROWS*DM], g_yl[(size_t)MROWS*DM];

// ---------------- helpers --------------------------------------------------
__device__ __forceinline__ float ex2(float x) {
    float r; asm("ex2.approx.f32 %0, %1;" : "=f"(r) : "f"(x)); return r;
}
__device__ __forceinline__ void mma16(float d[4],
                                      unsigned a0, unsigned a1, unsigned a2, unsigned a3,
                                      unsigned b0, unsigned b1) {
    asm volatile(
        "mma.sync.aligned.m16n8k16.row.col.f32.bf16.bf16.f32 "
        "{%0,%1,%2,%3}, {%4,%5,%6,%7}, {%8,%9}, {%0,%1,%2,%3};\n"
        : "+f"(d[0]), "+f"(d[1]), "+f"(d[2]), "+f"(d[3])
        : "r"(a0), "r"(a1), "r"(a2), "r"(a3), "r"(b0), "r"(b1));
}
__device__ __forceinline__ void ldm4(unsigned r[4], unsigned addr) {
    asm volatile("ldmatrix.sync.aligned.m8n8.x4.shared.b16 {%0,%1,%2,%3}, [%4];"
                 : "=r"(r[0]), "=r"(r[1]), "=r"(r[2]), "=r"(r[3]) : "r"(addr));
}
__device__ __forceinline__ unsigned s2u(const void* p) {
    return (unsigned)__cvta_generic_to_shared(p);
}
__device__ __forceinline__ unsigned pack_bf(__nv_bfloat16 a, __nv_bfloat16 b) {
    __nv_bfloat162 t = __halves2bfloat162(a, b);
    return *reinterpret_cast<unsigned*>(&t);
}
__device__ __forceinline__ unsigned pack_f(float a, float b) {
    __nv_bfloat162 t = __floats2bfloat162_rn(a, b);
    return *reinterpret_cast<unsigned*>(&t);
}
__device__ __forceinline__ void bsplit(float x, __nv_bfloat16& h, float& l) {
    h = __float2bfloat16(x);
    l = x - __bfloat162float(h);
}

// ---------------- pre-pass: fp32 -> bf16 hi/lo -----------------------------
__global__ void convert_split(const float* __restrict__ src,
                              __nv_bfloat16* __restrict__ h,
                              __nv_bfloat16* __restrict__ l, int n4)
{
    int i = blockIdx.x * blockDim.x + threadIdx.x;
    if (i >= n4) return;
    float4 v = reinterpret_cast<const float4*>(src)[i];
    __nv_bfloat16 h0, h1, h2, h3; float l0, l1, l2, l3;
    bsplit(v.x, h0, l0); bsplit(v.y, h1, l1);
    bsplit(v.z, h2, l2); bsplit(v.w, h3, l3);
    reinterpret_cast<__nv_bfloat162*>(h)[2*i]   = __halves2bfloat162(h0, h1);
    reinterpret_cast<__nv_bfloat162*>(h)[2*i+1] = __halves2bfloat162(h2, h3);
    reinterpret_cast<__nv_bfloat162*>(l)[2*i]   = __floats2bfloat162_rn(l0, l1);
    reinterpret_cast<__nv_bfloat162*>(l)[2*i+1] = __floats2bfloat162_rn(l2, l3);
}

// ---------------------------------------------------------------------------
// bf16x3 GEMM, operands pre-split in gmem. BM=BN=128, BK=16, 8 warps (2m x 4n).
// smem tiles stride 24 halves (ldmatrix + STS.128 conflict-free).
// MODE 0: QKV (z in 0..2; permuted bf16 hi/lo out). MODE 1: proj (fp32 out).
// ---------------------------------------------------------------------------
#define HST 24
#define ABYTES (128*HST*2)   // 6144 per array

template<int MODE>
__global__ __launch_bounds__(256, 2)
void gemm_bf(const __nv_bfloat16* __restrict__ Ah, const __nv_bfloat16* __restrict__ Al,
             const __nv_bfloat16* __restrict__ Whb, const __nv_bfloat16* __restrict__ Wlb,
             const float* __restrict__ b0p, const float* __restrict__ b1p,
             const float* __restrict__ b2p,
             __nv_bfloat16* __restrict__ ChB, __nv_bfloat16* __restrict__ ClB,
             float* __restrict__ outF)
{
    // [buf][arr: 0=Ah 1=Al 2=Bh 3=Bl][row][k]  = 49152 B
    __shared__ __align__(16) __nv_bfloat16 sh[2][4][128][HST];

    const int z = blockIdx.z;
    const size_t woff = (size_t)((MODE == 0) ? z : 3) * DM * DM;
    const float* bias = (z == 0) ? b0p : ((z == 1) ? b1p : b2p);

    const int tid  = threadIdx.x;
    const int lane = tid & 31;
    const int wid  = tid >> 5;
    const int m0 = blockIdx.y * 128;
    const int n0 = blockIdx.x * 128;
    const int wm = wid >> 2;
    const int wn = wid & 3;
    const int g  = lane >> 2;
    const int c  = lane & 3;

    // ldmatrix per-lane offsets (halves)
    const int rowA_ = (lane & 7) + ((lane >> 3) & 1) * 8;
    const int colA_ = (lane >> 4) * 8;
    const int rowB_ = (lane & 7) + ((lane >> 4) & 1) * 8;
    const int colB_ = ((lane >> 3) & 1) * 8;

    const bool isA = tid < 128;
    const int lrow = tid & 127;
    const __nv_bfloat16* ph = (isA ? Ah + (size_t)(m0 + lrow) * DM
                                   : Whb + woff + (size_t)(n0 + lrow) * DM);
    const __nv_bfloat16* pl = (isA ? Al + (size_t)(m0 + lrow) * DM
                                   : Wlb + woff + (size_t)(n0 + lrow) * DM);

    float acc[4][4][4];
    #pragma unroll
    for (int i = 0; i < 4; i++)
        #pragma unroll
        for (int j = 0; j < 4; j++)
            #pragma unroll
            for (int r = 0; r < 4; r++) acc[i][j][r] = 0.f;

    const unsigned sbase = s2u(&sh[0][0][0][0]);
    const int arrH = isA ? 0 : 2;

    uint4 rh0 = *(const uint4*)(ph);     uint4 rh1 = *(const uint4*)(ph + 8);
    uint4 rl0 = *(const uint4*)(pl);     uint4 rl1 = *(const uint4*)(pl + 8);

    #pragma unroll 1
    for (int it = 0; it < 48; ++it) {
        const int buf = it & 1;
        {
            uint4* dh = (uint4*)&sh[buf][arrH][lrow][0];
            dh[0] = rh0; dh[1] = rh1;
            uint4* dl = (uint4*)&sh[buf][arrH + 1][lrow][0];
            dl[0] = rl0; dl[1] = rl1;
        }
        __syncthreads();

        if (it < 47) {
            const int k0 = (it + 1) * 16;
            rh0 = *(const uint4*)(ph + k0);  rh1 = *(const uint4*)(ph + k0 + 8);
            rl0 = *(const uint4*)(pl + k0);  rl1 = *(const uint4*)(pl + k0 + 8);
        }

        // ---- fragments via ldmatrix ----
        const unsigned bufo = sbase + (unsigned)(buf * 4) * ABYTES;
        unsigned bh[4][2], bl[4][2];
        #pragma unroll
        for (int ntp = 0; ntp < 2; ++ntp) {
            unsigned r[4];
            const int rb = wn * 32 + ntp * 16 + rowB_;
            ldm4(r, bufo + 2u * ABYTES + (unsigned)((rb * HST + colB_) * 2));
            bh[ntp*2][0] = r[0]; bh[ntp*2][1] = r[1];
            bh[ntp*2+1][0] = r[2]; bh[ntp*2+1][1] = r[3];
            ldm4(r, bufo + 3u * ABYTES + (unsigned)((rb * HST + colB_) * 2));
            bl[ntp*2][0] = r[0]; bl[ntp*2][1] = r[1];
            bl[ntp*2+1][0] = r[2]; bl[ntp*2+1][1] = r[3];
        }
        #pragma unroll
        for (int mi = 0; mi < 4; ++mi) {
            const int ra = wm * 64 + mi * 16 + rowA_;
            unsigned ah[4], al[4];
            ldm4(ah, bufo + (unsigned)((ra * HST + colA_) * 2));
            ldm4(al, bufo + 1u * ABYTES + (unsigned)((ra * HST + colA_) * 2));
            #pragma unroll
            for (int ni = 0; ni < 4; ++ni) {
                mma16(acc[mi][ni], ah[0], ah[1], ah[2], ah[3], bh[ni][0], bh[ni][1]);
                mma16(acc[mi][ni], ah[0], ah[1], ah[2], ah[3], bl[ni][0], bl[ni][1]);
                mma16(acc[mi][ni], al[0], al[1], al[2], al[3], bh[ni][0], bh[ni][1]);
            }
        }
    }

    // ---- epilogue ----
    __nv_bfloat16* Ch = (MODE == 0) ? (ChB + (size_t)z * ZSZ) : nullptr;
    __nv_bfloat16* Cl = (MODE == 0) ? (ClB + (size_t)z * ZSZ) : nullptr;
    #pragma unroll
    for (int mi = 0; mi < 4; ++mi) {
        const int row = m0 + wm * 64 + mi * 16 + g;
        #pragma unroll
        for (int ni = 0; ni < 4; ++ni) {
            const int col = n0 + wn * 32 + ni * 8 + c * 2;
            float2 bv = *(const float2*)(bias + col);
            float v0 = acc[mi][ni][0] + bv.x;
            float v1 = acc[mi][ni][1] + bv.y;
            float v2 = acc[mi][ni][2] + bv.x;
            float v3 = acc[mi][ni][3] + bv.y;
            if (MODE == 0) {
                const int bb = row >> 11;
                const int t  = row & 2047;
                const int hd = col >> 6;
                const int d  = col & 63;
                const size_t a0 = ((size_t)(bb * NH + hd) * TT + t) * DH + d;
                __nv_bfloat16 h0, h1; float l0, l1;
                bsplit(v0, h0, l0); bsplit(v1, h1, l1);
                *(__nv_bfloat162*)(Ch + a0) = __halves2bfloat162(h0, h1);
                *(__nv_bfloat162*)(Cl + a0) = __floats2bfloat162_rn(l0, l1);
                bsplit(v2, h0, l0); bsplit(v3, h1, l1);
                *(__nv_bfloat162*)(Ch + a0 + 8 * DH) = __halves2bfloat162(h0, h1);
                *(__nv_bfloat162*)(Cl + a0 + 8 * DH) = __floats2bfloat162_rn(l0, l1);
            } else {
                *(float2*)(outF + (size_t)row * DM + col)       = make_float2(v0, v1);
                *(float2*)(outF + (size_t)(row + 8) * DM + col) = make_float2(v2, v3);
            }
        }
    }
}

// ---------------------------------------------------------------------------
// Flash attention, bf16x3 for both QK^T and PV. Br=64, Bc=64, 4 warps.
// K tiles: row-major [key][dh] stride 72 halves (ldmatrix-friendly).
// V tiles: transposed [dh][key] stride 72. All frag loads via ldmatrix.x4.
// ---------------------------------------------------------------------------
#define KVS 72

__global__ __launch_bounds__(128)
void attn_bf(float* __restrict__ dummy)
{
    __shared__ __align__(16) __nv_bfloat16 Kh[64 * KVS], Kl[64 * KVS];
    __shared__ __align__(16) unsigned short VTh[64 * KVS], VTl[64 * KVS];

    const int tid  = threadIdx.x;
    const int lane = tid & 31;
    const int wid  = tid >> 5;
    const int qb = blockIdx.x;       // 0..31
    const int bh = blockIdx.y;       // 0..47
    const int g  = lane >> 2;
    const int c  = lane & 3;

    // ldmatrix per-lane offsets (B-type pattern used for both K and V^T)
    const int rowB_ = (lane & 7) + ((lane >> 4) & 1) * 8;
    const int colB_ = ((lane >> 3) & 1) * 8;

    // ---- Q fragments: combine hi+lo, scale, re-split ----
    const float SC = 0.125f * 1.4426950408889634f;
    const __nv_bfloat16* qhp = g_h3 + ((size_t)bh * TT + qb * 64 + wid * 16) * DH;
    const __nv_bfloat16* qlp = g_l3 + ((size_t)bh * TT + qb * 64 + wid * 16) * DH;
    unsigned qfh[4][4], qfl[4][4];
    #pragma unroll
    for (int kc = 0; kc < 4; ++kc) {
        #pragma unroll
        for (int j = 0; j < 4; ++j) {
            const int row = g + (j & 1) * 8;
            const int col = kc * 16 + 2 * c + (j >> 1) * 8;
            __nv_bfloat162 hh = *(const __nv_bfloat162*)(qhp + (size_t)row * DH + col);
            __nv_bfloat162 ll = *(const __nv_bfloat162*)(qlp + (size_t)row * DH + col);
            float x0 = (__bfloat162float(hh.x) + __bfloat162float(ll.x)) * SC;
            float x1 = (__bfloat162float(hh.y) + __bfloat162float(ll.y)) * SC;
            __nv_bfloat16 h0, h1; float l0, l1;
            bsplit(x0, h0, l0); bsplit(x1, h1, l1);
            qfh[kc][j] = pack_bf(h0, h1);
            qfl[kc][j] = pack_f(l0, l1);
        }
    }

    float o[8][4];
    #pragma unroll
    for (int i = 0; i < 8; ++i)
        #pragma unroll
        for (int j = 0; j < 4; ++j) o[i][j] = 0.f;
    float m_lo = -1e30f, m_hi = -1e30f, l_lo = 0.f, l_hi = 0.f;

    // V loader mapping: kp = key pair, dhalf selects d range
    const int vkp   = tid & 31;
    const int vdh   = (tid >> 5) & 1;
    const int vsel  = tid >> 6;     // 0: hi, 1: lo
    const __nv_bfloat16* vsrc_base =
        (vsel ? g_l3 : g_h3) + 2 * ZSZ + ((size_t)bh * TT + 2 * vkp) * DH + vdh * 32;
    unsigned short* VTd = vsel ? VTl : VTh;

    const unsigned uKh = s2u(Kh), uKl = s2u(Kl);
    const unsigned uVh = s2u(VTh), uVl = s2u(VTl);

    const int row_lo = qb * 64 + wid * 16 + g;
    const int row_hi = row_lo + 8;

    const __nv_bfloat16* khs_base = g_h3 + ZSZ + (size_t)bh * TT * DH;
    const __nv_bfloat16* kls_base = g_l3 + ZSZ + (size_t)bh * TT * DH;

    for (int kb = 0; kb <= qb; ++kb) {
        __syncthreads();

        // ---- stage K: linear LDG.128 copy into stride-72 rows ----
        {
            const __nv_bfloat16* kh = khs_base + (size_t)kb * 64 * DH;
            const __nv_bfloat16* kl = kls_base + (size_t)kb * 64 * DH;
            #pragma unroll
            for (int i = 0; i < 4; ++i) {
                const int idx = tid + i * 128;
                const int key = idx >> 3;
                const int cc  = idx & 7;
                *(uint4*)(&Kh[key * KVS + cc * 8]) = *(const uint4*)(kh + idx * 8);
                *(uint4*)(&Kl[key * KVS + cc * 8]) = *(const uint4*)(kl + idx * 8);
            }
        }
        // ---- stage V transposed ----
        {
            const __nv_bfloat16* ve = vsrc_base + (size_t)kb * 64 * DH;
            const __nv_bfloat16* vo = ve + DH;
            #pragma unroll
            for (int q = 0; q < 4; ++q) {
                uint4 e = *(const uint4*)(ve + q * 8);
                uint4 od = *(const uint4*)(vo + q * 8);
                unsigned ue[4] = {e.x, e.y, e.z, e.w};
                unsigned uo[4] = {od.x, od.y, od.z, od.w};
                #pragma unroll
                for (int j = 0; j < 4; ++j) {
                    const int d = vdh * 32 + q * 8 + 2 * j;
                    *(unsigned*)(&VTd[d * KVS + 2 * vkp])       = __byte_perm(ue[j], uo[j], 0x5410);
                    *(unsigned*)(&VTd[(d + 1) * KVS + 2 * vkp]) = __byte_perm(ue[j], uo[j], 0x7632);
                }
            }
        }
        __syncthreads();

        // ---- S = Q K^T (bf16x3) ----
        float s[8][4];
        #pragma unroll
        for (int i = 0; i < 8; ++i)
            #pragma unroll
            for (int j = 0; j < 4; ++j) s[i][j] = 0.f;

        #pragma unroll
        for (int kc = 0; kc < 4; ++kc) {
            #pragma unroll
            for (int ntp = 0; ntp < 4; ++ntp) {
                const unsigned off = (unsigned)(((ntp * 16 + rowB_) * KVS + kc * 16 + colB_) * 2);
                unsigned rh[4], rl[4];
                ldm4(rh, uKh + off);
                ldm4(rl, uKl + off);
                float* s0 = s[ntp * 2];
                float* s1 = s[ntp * 2 + 1];
                mma16(s0, qfh[kc][0], qfh[kc][1], qfh[kc][2], qfh[kc][3], rh[0], rh[1]);
                mma16(s0, qfh[kc][0], qfh[kc][1], qfh[kc][2], qfh[kc][3], rl[0], rl[1]);
                mma16(s0, qfl[kc][0], qfl[kc][1], qfl[kc][2], qfl[kc][3], rh[0], rh[1]);
                mma16(s1, qfh[kc][0], qfh[kc][1], qfh[kc][2], qfh[kc][3], rh[2], rh[3]);
                mma16(s1, qfh[kc][0], qfh[kc][1], qfh[kc][2], qfh[kc][3], rl[2], rl[3]);
                mma16(s1, qfl[kc][0], qfl[kc][1], qfl[kc][2], qfl[kc][3], rh[2], rh[3]);
            }
        }

        // ---- causal mask (diagonal block only) ----
        if (kb == qb) {
            #pragma unroll
            for (int nt = 0; nt < 8; ++nt) {
                const int k0 = kb * 64 + nt * 8 + c * 2;
                if (k0 > row_lo)     s[nt][0] = -1e30f;
                if (k0 + 1 > row_lo) s[nt][1] = -1e30f;
                if (k0 > row_hi)     s[nt][2] = -1e30f;
                if (k0 + 1 > row_hi) s[nt][3] = -1e30f;
            }
        }

        // ---- online softmax (log2 domain) ----
        {
            float mx = -1e30f;
            #pragma unroll
            for (int nt = 0; nt < 8; ++nt) mx = fmaxf(mx, fmaxf(s[nt][0], s[nt][1]));
            mx = fmaxf(mx, __shfl_xor_sync(0xffffffffu, mx, 1));
            mx = fmaxf(mx, __shfl_xor_sync(0xffffffffu, mx, 2));
            const float mn = fmaxf(m_lo, mx);
            const float al = ex2(m_lo - mn);
            m_lo = mn;
            float ls = 0.f;
            #pragma unroll
            for (int nt = 0; nt < 8; ++nt) {
                s[nt][0] = ex2(s[nt][0] - mn); ls += s[nt][0];
                s[nt][1] = ex2(s[nt][1] - mn); ls += s[nt][1];
                o[nt][0] *= al; o[nt][1] *= al;
            }
            l_lo = l_lo * al + ls;
        }
        {
            float mx = -1e30f;
            #pragma unroll
            for (int nt = 0; nt < 8; ++nt) mx = fmaxf(mx, fmaxf(s[nt][2], s[nt][3]));
            mx = fmaxf(mx, __shfl_xor_sync(0xffffffffu, mx, 1));
            mx = fmaxf(mx, __shfl_xor_sync(0xffffffffu, mx, 2));
            const float mn = fmaxf(m_hi, mx);
            const float al = ex2(m_hi - mn);
            m_hi = mn;
            float ls = 0.f;
            #pragma unroll
            for (int nt = 0; nt < 8; ++nt) {
                s[nt][2] = ex2(s[nt][2] - mn); ls += s[nt][2];
                s[nt][3] = ex2(s[nt][3] - mn); ls += s[nt][3];
                o[nt][2] *= al; o[nt][3] *= al;
            }
            l_hi = l_hi * al + ls;
        }

        // ---- O += P V  (bf16x3; P frags thread-local, V via ldmatrix) ----
        #pragma unroll
        for (int kc = 0; kc < 4; ++kc) {
            __nv_bfloat16 h00, h01, h02, h03, h10, h11, h12, h13;
            float l00, l01, l02, l03, l10, l11, l12, l13;
            bsplit(s[2*kc][0],   h00, l00);  bsplit(s[2*kc][1],   h01, l01);
            bsplit(s[2*kc][2],   h02, l02);  bsplit(s[2*kc][3],   h03, l03);
            bsplit(s[2*kc+1][0], h10, l10);  bsplit(s[2*kc+1][1], h11, l11);
            bsplit(s[2*kc+1][2], h12, l12);  bsplit(s[2*kc+1][3], h13, l13);
            const unsigned ah0 = pack_bf(h00, h01);
            const unsigned ah1 = pack_bf(h02, h03);
            const unsigned ah2 = pack_bf(h10, h11);
            const unsigned ah3 = pack_bf(h12, h13);
            const unsigned al0 = pack_f(l00, l01);
            const unsigned al1 = pack_f(l02, l03);
            const unsigned al2 = pack_f(l10, l11);
            const unsigned al3 = pack_f(l12, l13);
            #pragma unroll
            for (int ntp = 0; ntp < 4; ++ntp) {
                const unsigned off = (unsigned)(((ntp * 16 + rowB_) * KVS + kc * 16 + colB_) * 2);
                unsigned vh[4], vl[4];
                ldm4(vh, uVh + off);
                ldm4(vl, uVl + off);
                float* o0 = o[ntp * 2];
                float* o1 = o[ntp * 2 + 1];
                mma16(o0, ah0, ah1, ah2, ah3, vh[0], vh[1]);
                mma16(o0, ah0, ah1, ah2, ah3, vl[0], vl[1]);
                mma16(o0, al0, al1, al2, al3, vh[0], vh[1]);
                mma16(o1, ah0, ah1, ah2, ah3, vh[2], vh[3]);
                mma16(o1, ah0, ah1, ah2, ah3, vl[2], vl[3]);
                mma16(o1, al0, al1, al2, al3, vh[2], vh[3]);
            }
        }
    }

    // ---- epilogue: normalize, split, write y hi/lo ----
    l_lo += __shfl_xor_sync(0xffffffffu, l_lo, 1);
    l_lo += __shfl_xor_sync(0xffffffffu, l_lo, 2);
    l_hi += __shfl_xor_sync(0xffffffffu, l_hi, 1);
    l_hi += __shfl_xor_sync(0xffffffffu, l_hi, 2);
    const float inv_lo = 1.f / l_lo;
    const float inv_hi = 1.f / l_hi;

    const int bbv = bh / NH;
    const int hd  = bh % NH;
    const size_t alo = ((size_t)bbv * TT + row_lo) * DM + hd * DH + 2 * c;
    const size_t ahi = ((size_t)bbv * TT + row_hi) * DM + hd * DH + 2 * c;
    #pragma unroll
    for (int nt = 0; nt < 8; ++nt) {
        __nv_bfloat16 h0, h1; float l0, l1;
        bsplit(o[nt][0] * inv_lo, h0, l0);
        bsplit(o[nt][1] * inv_lo, h1, l1);
        *(__nv_bfloat162*)(g_yh + alo + nt * 8) = __halves2bfloat162(h0, h1);
        *(__nv_bfloat162*)(g_yl + alo + nt * 8) = __floats2bfloat162_rn(l0, l1);
        bsplit(o[nt][2] * inv_hi, h0, l0);
        bsplit(o[nt][3] * inv_hi, h1, l1);
        *(__nv_bfloat162*)(g_yh + ahi + nt * 8) = __halves2bfloat162(h0, h1);
        *(__nv_bfloat162*)(g_yl + ahi + nt * 8) = __floats2bfloat162_rn(l0, l1);
    }
    (void)dummy;
}

// ---------------------------------------------------------------------------
extern "C" void kernel_launch(void* const* d_in, const int* in_sizes, int n_in,
                              void* d_out, int out_size)
{
    const float* x  = (const float*)d_in[0];
    const float* Wq = (const float*)d_in[1];
    const float* bq = (const float*)d_in[2];
    const float* Wk = (const float*)d_in[3];
    const float* bk = (const float*)d_in[4];
    const float* Wv = (const float*)d_in[5];
    const float* bv = (const float*)d_in[6];
    const float* Wp = (const float*)d_in[7];
    const float* bp = (const float*)d_in[8];
    float* out = (float*)d_out;

    __nv_bfloat16 *xh, *xl, *wh, *wl, *h3, *l3, *yh, *yl;
    cudaGetSymbolAddress((void**)&xh, g_xh);
    cudaGetSymbolAddress((void**)&xl, g_xl);
    cudaGetSymbolAddress((void**)&wh, g_wh);
    cudaGetSymbolAddress((void**)&wl, g_wl);
    cudaGetSymbolAddress((void**)&h3, g_h3);
    cudaGetSymbolAddress((void**)&l3, g_l3);
    cudaGetSymbolAddress((void**)&yh, g_yh);
    cudaGetSymbolAddress((void**)&yl, g_yl);

    // pre-pass conversions
    const int n4x = MROWS * DM / 4;          // 1572864
    const int n4w = DM * DM / 4;             // 147456
    convert_split<<<(n4x + 255) / 256, 256>>>(x, xh, xl, n4x);
    convert_split<<<(n4w + 255) / 256, 256>>>(Wq, wh + 0 * (size_t)DM * DM, wl + 0 * (size_t)DM * DM, n4w);
    convert_split<<<(n4w + 255) / 256, 256>>>(Wk, wh + 1 * (size_t)DM * DM, wl + 1 * (size_t)DM * DM, n4w);
    convert_split<<<(n4w + 255) / 256, 256>>>(Wv, wh + 2 * (size_t)DM * DM, wl + 2 * (size_t)DM * DM, n4w);
    convert_split<<<(n4w + 255) / 256, 256>>>(Wp, wh + 3 * (size_t)DM * DM, wl + 3 * (size_t)DM * DM, n4w);

    // QKV (merged, permuted bf16 hi/lo out)
    dim3 qkv_grid(DM / 128, MROWS / 128, 3);
    gemm_bf<0><<<qkv_grid, 256>>>(xh, xl, wh, wl, bq, bk, bv, h3, l3, nullptr);

    // attention (reads g_h3/g_l3, writes g_yh/g_yl)
    dim3 attn_grid(TT / 64, BB * NH);
    attn_bf<<<attn_grid, 128>>>(nullptr);

    // out-proj (fp32 out)
    dim3 proj_grid(DM / 128, MROWS / 128, 1);
    gemm_bf<1><<<proj_grid, 256>>>(yh, yl, wh, wl, bp, bp, bp, nullptr, nullptr, out);
}

// round 8
// speedup vs baseline: 3.6971x; 1.0751x over previous
#include <cuda_runtime.h>
#include <cuda_bf16.h>
#include <math.h>

#define DM 768
#define NH 12
#define DH 64
#define BB 4
#define TT 2048
#define MROWS (BB*TT)   // 8192
#define ZSZ ((size_t)BB*NH*TT*DH)   // per-tensor q/k/v elems

// ---------------- scratch (device globals; no allocation allowed) ----------
__device__ __nv_bfloat16 g_xh[(size_t)MROWS*DM], g_xl[(size_t)MROWS*DM];
__device__ __nv_bfloat16 g_wh[4*(size_t)DM*DM], g_wl[4*(size_t)DM*DM];
__device__ __nv_bfloat16 g_h3[3*ZSZ], g_l3[3*ZSZ];      // q,k,v hi / lo
__device__ __nv_bfloat16 g_yh[(size_t)MROWS*DM], g_yl[(size_t)MROWS*DM];

// ---------------- helpers --------------------------------------------------
__device__ __forceinline__ float ex2(float x) {
    float r; asm("ex2.approx.f32 %0, %1;" : "=f"(r) : "f"(x)); return r;
}
__device__ __forceinline__ void mma16(float d[4],
                                      unsigned a0, unsigned a1, unsigned a2, unsigned a3,
                                      unsigned b0, unsigned b1) {
    asm volatile(
        "mma.sync.aligned.m16n8k16.row.col.f32.bf16.bf16.f32 "
        "{%0,%1,%2,%3}, {%4,%5,%6,%7}, {%8,%9}, {%0,%1,%2,%3};\n"
        : "+f"(d[0]), "+f"(d[1]), "+f"(d[2]), "+f"(d[3])
        : "r"(a0), "r"(a1), "r"(a2), "r"(a3), "r"(b0), "r"(b1));
}
__device__ __forceinline__ void ldm4(unsigned r[4], unsigned addr) {
    asm volatile("ldmatrix.sync.aligned.m8n8.x4.shared.b16 {%0,%1,%2,%3}, [%4];"
                 : "=r"(r[0]), "=r"(r[1]), "=r"(r[2]), "=r"(r[3]) : "r"(addr));
}
__device__ __forceinline__ void ldm4t(unsigned r[4], unsigned addr) {
    asm volatile("ldmatrix.sync.aligned.m8n8.x4.trans.shared.b16 {%0,%1,%2,%3}, [%4];"
                 : "=r"(r[0]), "=r"(r[1]), "=r"(r[2]), "=r"(r[3]) : "r"(addr));
}
__device__ __forceinline__ unsigned s2u(const void* p) {
    return (unsigned)__cvta_generic_to_shared(p);
}
__device__ __forceinline__ void cp16(unsigned saddr, const void* gptr) {
    asm volatile("cp.async.cg.shared.global [%0], [%1], 16;"
                 :: "r"(saddr), "l"(gptr) : "memory");
}
__device__ __forceinline__ void cp_commit() {
    asm volatile("cp.async.commit_group;" ::: "memory");
}
template<int N>
__device__ __forceinline__ void cp_wait() {
    asm volatile("cp.async.wait_group %0;" :: "n"(N) : "memory");
}
__device__ __forceinline__ unsigned pack_bf(__nv_bfloat16 a, __nv_bfloat16 b) {
    __nv_bfloat162 t = __halves2bfloat162(a, b);
    return *reinterpret_cast<unsigned*>(&t);
}
__device__ __forceinline__ unsigned pack_f(float a, float b) {
    __nv_bfloat162 t = __floats2bfloat162_rn(a, b);
    return *reinterpret_cast<unsigned*>(&t);
}
__device__ __forceinline__ void bsplit(float x, __nv_bfloat16& h, float& l) {
    h = __float2bfloat16(x);
    l = x - __bfloat162float(h);
}

// ---------------- pre-pass: fp32 -> bf16 hi/lo -----------------------------
__global__ void convert_split(const float* __restrict__ src,
                              __nv_bfloat16* __restrict__ h,
                              __nv_bfloat16* __restrict__ l, int n4)
{
    int i = blockIdx.x * blockDim.x + threadIdx.x;
    if (i >= n4) return;
    float4 v = reinterpret_cast<const float4*>(src)[i];
    __nv_bfloat16 h0, h1, h2, h3; float l0, l1, l2, l3;
    bsplit(v.x, h0, l0); bsplit(v.y, h1, l1);
    bsplit(v.z, h2, l2); bsplit(v.w, h3, l3);
    reinterpret_cast<__nv_bfloat162*>(h)[2*i]   = __halves2bfloat162(h0, h1);
    reinterpret_cast<__nv_bfloat162*>(h)[2*i+1] = __halves2bfloat162(h2, h3);
    reinterpret_cast<__nv_bfloat162*>(l)[2*i]   = __floats2bfloat162_rn(l0, l1);
    reinterpret_cast<__nv_bfloat162*>(l)[2*i+1] = __floats2bfloat162_rn(l2, l3);
}
// all 4 weight matrices in one launch (blockIdx.y selects matrix)
__global__ void convert_w4(const float* __restrict__ s0, const float* __restrict__ s1,
                           const float* __restrict__ s2, const float* __restrict__ s3,
                           __nv_bfloat16* __restrict__ h, __nv_bfloat16* __restrict__ l,
                           int n4)
{
    int i = blockIdx.x * blockDim.x + threadIdx.x;
    if (i >= n4) return;
    const int z = blockIdx.y;
    const float* src = (z == 0) ? s0 : ((z == 1) ? s1 : ((z == 2) ? s2 : s3));
    const size_t off2 = (size_t)z * (DM * DM / 2);   // in bf16x2 units
    float4 v = reinterpret_cast<const float4*>(src)[i];
    __nv_bfloat16 h0, h1, h2, h3; float l0, l1, l2, l3;
    bsplit(v.x, h0, l0); bsplit(v.y, h1, l1);
    bsplit(v.z, h2, l2); bsplit(v.w, h3, l3);
    reinterpret_cast<__nv_bfloat162*>(h)[off2 + 2*i]   = __halves2bfloat162(h0, h1);
    reinterpret_cast<__nv_bfloat162*>(h)[off2 + 2*i+1] = __halves2bfloat162(h2, h3);
    reinterpret_cast<__nv_bfloat162*>(l)[off2 + 2*i]   = __floats2bfloat162_rn(l0, l1);
    reinterpret_cast<__nv_bfloat162*>(l)[off2 + 2*i+1] = __floats2bfloat162_rn(l2, l3);
}

// ---------------------------------------------------------------------------
// bf16x3 GEMM (mma.sync), cp.async 2-stage pipeline. BM=BN=128, BK=16,
// 8 warps (2m x 4n). smem tiles stride 24 halves. Same math as R6 (validated).
// MODE 0: QKV (z in 0..2; permuted bf16 hi/lo out). MODE 1: proj (fp32 out).
// ---------------------------------------------------------------------------
#define HST 24
#define ABYTES (128*HST*2)   // 6144 per array

template<int MODE>
__global__ __launch_bounds__(256, 2)
void gemm_bf(const __nv_bfloat16* __restrict__ Ah, const __nv_bfloat16* __restrict__ Al,
             const __nv_bfloat16* __restrict__ Whb, const __nv_bfloat16* __restrict__ Wlb,
             const float* __restrict__ b0p, const float* __restrict__ b1p,
             const float* __restrict__ b2p,
             __nv_bfloat16* __restrict__ ChB, __nv_bfloat16* __restrict__ ClB,
             float* __restrict__ outF)
{
    // [buf][arr: 0=Ah 1=Al 2=Bh 3=Bl][row][k]  = 49152 B
    __shared__ __align__(16) __nv_bfloat16 sh[2][4][128][HST];

    const int z = blockIdx.z;
    const size_t woff = (size_t)((MODE == 0) ? z : 3) * DM * DM;
    const float* bias = (z == 0) ? b0p : ((z == 1) ? b1p : b2p);

    const int tid  = threadIdx.x;
    const int lane = tid & 31;
    const int wid  = tid >> 5;
    const int m0 = blockIdx.y * 128;
    const int n0 = blockIdx.x * 128;
    const int wm = wid >> 2;
    const int wn = wid & 3;
    const int g  = lane >> 2;
    const int c  = lane & 3;

    const int rowA_ = (lane & 7) + ((lane >> 3) & 1) * 8;
    const int colA_ = (lane >> 4) * 8;
    const int rowB_ = (lane & 7) + ((lane >> 4) & 1) * 8;
    const int colB_ = ((lane >> 3) & 1) * 8;

    const bool isA = tid < 128;
    const int lrow = tid & 127;
    const __nv_bfloat16* ph = (isA ? Ah + (size_t)(m0 + lrow) * DM
                                   : Whb + woff + (size_t)(n0 + lrow) * DM);
    const __nv_bfloat16* pl = (isA ? Al + (size_t)(m0 + lrow) * DM
                                   : Wlb + woff + (size_t)(n0 + lrow) * DM);

    const unsigned sbase = s2u(&sh[0][0][0][0]);
    const int arrH = isA ? 0 : 2;
    // smem byte offsets of this thread's staging rows
    const unsigned sH = (unsigned)(arrH * ABYTES + lrow * (HST * 2));
    const unsigned sL = sH + ABYTES;

    float acc[4][4][4];
    #pragma unroll
    for (int i = 0; i < 4; i++)
        #pragma unroll
        for (int j = 0; j < 4; j++)
            #pragma unroll
            for (int r = 0; r < 4; r++) acc[i][j][r] = 0.f;

    // prologue: stage 0
    {
        cp16(sbase + sH,      ph);      cp16(sbase + sH + 16, ph + 8);
        cp16(sbase + sL,      pl);      cp16(sbase + sL + 16, pl + 8);
        cp_commit();
    }

    #pragma unroll 1
    for (int it = 0; it < 48; ++it) {
        const int buf = it & 1;
        if (it < 47) {
            const int k0 = (it + 1) * 16;
            const unsigned nb = (unsigned)((buf ^ 1) * 4 * ABYTES);
            cp16(sbase + nb + sH,      ph + k0);  cp16(sbase + nb + sH + 16, ph + k0 + 8);
            cp16(sbase + nb + sL,      pl + k0);  cp16(sbase + nb + sL + 16, pl + k0 + 8);
            cp_commit();
            cp_wait<1>();
        } else {
            cp_wait<0>();
        }
        __syncthreads();

        // ---- fragments via ldmatrix (same math as R6) ----
        const unsigned bufo = sbase + (unsigned)(buf * 4) * ABYTES;
        unsigned bh[4][2], bl[4][2];
        #pragma unroll
        for (int ntp = 0; ntp < 2; ++ntp) {
            unsigned r[4];
            const int rb = wn * 32 + ntp * 16 + rowB_;
            ldm4(r, bufo + 2u * ABYTES + (unsigned)((rb * HST + colB_) * 2));
            bh[ntp*2][0] = r[0]; bh[ntp*2][1] = r[1];
            bh[ntp*2+1][0] = r[2]; bh[ntp*2+1][1] = r[3];
            ldm4(r, bufo + 3u * ABYTES + (unsigned)((rb * HST + colB_) * 2));
            bl[ntp*2][0] = r[0]; bl[ntp*2][1] = r[1];
            bl[ntp*2+1][0] = r[2]; bl[ntp*2+1][1] = r[3];
        }
        #pragma unroll
        for (int mi = 0; mi < 4; ++mi) {
            const int ra = wm * 64 + mi * 16 + rowA_;
            unsigned ah[4], al[4];
            ldm4(ah, bufo + (unsigned)((ra * HST + colA_) * 2));
            ldm4(al, bufo + 1u * ABYTES + (unsigned)((ra * HST + colA_) * 2));
            #pragma unroll
            for (int ni = 0; ni < 4; ++ni) {
                mma16(acc[mi][ni], ah[0], ah[1], ah[2], ah[3], bh[ni][0], bh[ni][1]);
                mma16(acc[mi][ni], ah[0], ah[1], ah[2], ah[3], bl[ni][0], bl[ni][1]);
                mma16(acc[mi][ni], al[0], al[1], al[2], al[3], bh[ni][0], bh[ni][1]);
            }
        }
        __syncthreads();
    }

    // ---- epilogue (unchanged from R6) ----
    __nv_bfloat16* Ch = (MODE == 0) ? (ChB + (size_t)z * ZSZ) : nullptr;
    __nv_bfloat16* Cl = (MODE == 0) ? (ClB + (size_t)z * ZSZ) : nullptr;
    #pragma unroll
    for (int mi = 0; mi < 4; ++mi) {
        const int row = m0 + wm * 64 + mi * 16 + g;
        #pragma unroll
        for (int ni = 0; ni < 4; ++ni) {
            const int col = n0 + wn * 32 + ni * 8 + c * 2;
            float2 bv = *(const float2*)(bias + col);
            float v0 = acc[mi][ni][0] + bv.x;
            float v1 = acc[mi][ni][1] + bv.y;
            float v2 = acc[mi][ni][2] + bv.x;
            float v3 = acc[mi][ni][3] + bv.y;
            if (MODE == 0) {
                const int bb = row >> 11;
                const int t  = row & 2047;
                const int hd = col >> 6;
                const int d  = col & 63;
                const size_t a0 = ((size_t)(bb * NH + hd) * TT + t) * DH + d;
                __nv_bfloat16 h0, h1; float l0, l1;
                bsplit(v0, h0, l0); bsplit(v1, h1, l1);
                *(__nv_bfloat162*)(Ch + a0) = __halves2bfloat162(h0, h1);
                *(__nv_bfloat162*)(Cl + a0) = __floats2bfloat162_rn(l0, l1);
                bsplit(v2, h0, l0); bsplit(v3, h1, l1);
                *(__nv_bfloat162*)(Ch + a0 + 8 * DH) = __halves2bfloat162(h0, h1);
                *(__nv_bfloat162*)(Cl + a0 + 8 * DH) = __floats2bfloat162_rn(l0, l1);
            } else {
                *(float2*)(outF + (size_t)row * DM + col)       = make_float2(v0, v1);
                *(float2*)(outF + (size_t)(row + 8) * DM + col) = make_float2(v2, v3);
            }
        }
    }
}

// ---------------------------------------------------------------------------
// Flash attention, bf16x3 (same math as R6). Br=128, Bc=64, 8 warps.
// cp.async double-buffered K/V staging (V stored raw row-major; PV B-frags
// via ldmatrix.trans — register contents identical to R6's VT+ldmatrix).
// ---------------------------------------------------------------------------
#define AKVS 72
#define AARR 9216                  // 64 * 72 * 2 bytes
#define ASTG (4*AARR)              // Kh,Kl,Vh,Vl
#define A_KH 0
#define A_KL AARR
#define A_VH (2*AARR)
#define A_VL (3*AARR)
#define ASMEM (2*ASTG)             // 73728

__global__ __launch_bounds__(256, 2)
void attn_bf(float* __restrict__ dummy)
{
    extern __shared__ __align__(16) char asmz[];
    const unsigned uS = s2u(asmz);

    const int tid  = threadIdx.x;
    const int lane = tid & 31;
    const int wid  = tid >> 5;       // 0..7
    const int qb = blockIdx.x;       // 0..15 (128-row q tiles)
    const int bh = blockIdx.y;       // 0..47
    const int g  = lane >> 2;
    const int c  = lane & 3;

    const int rowB_ = (lane & 7) + ((lane >> 4) & 1) * 8;
    const int colB_ = ((lane >> 3) & 1) * 8;
    // trans-ldmatrix lane address components (verified ≡ R6 VT mapping)
    const int vkey_ = lane & 15;
    const int vd_   = (lane >> 4) * 8;

    // ---- Q fragments: combine hi+lo, scale, re-split (same as R6) ----
    const float SC = 0.125f * 1.4426950408889634f;
    const __nv_bfloat16* qhp = g_h3 + ((size_t)bh * TT + qb * 128 + wid * 16) * DH;
    const __nv_bfloat16* qlp = g_l3 + ((size_t)bh * TT + qb * 128 + wid * 16) * DH;
    unsigned qfh[4][4], qfl[4][4];
    #pragma unroll
    for (int kc = 0; kc < 4; ++kc) {
        #pragma unroll
        for (int j = 0; j < 4; ++j) {
            const int row = g + (j & 1) * 8;
            const int col = kc * 16 + 2 * c + (j >> 1) * 8;
            __nv_bfloat162 hh = *(const __nv_bfloat162*)(qhp + (size_t)row * DH + col);
            __nv_bfloat162 ll = *(const __nv_bfloat162*)(qlp + (size_t)row * DH + col);
            float x0 = (__bfloat162float(hh.x) + __bfloat162float(ll.x)) * SC;
            float x1 = (__bfloat162float(hh.y) + __bfloat162float(ll.y)) * SC;
            __nv_bfloat16 h0, h1; float l0, l1;
            bsplit(x0, h0, l0); bsplit(x1, h1, l1);
            qfh[kc][j] = pack_bf(h0, h1);
            qfl[kc][j] = pack_f(l0, l1);
        }
    }

    float o[8][4];
    #pragma unroll
    for (int i = 0; i < 8; ++i)
        #pragma unroll
        for (int j = 0; j < 4; ++j) o[i][j] = 0.f;
    float m_lo = -1e30f, m_hi = -1e30f, l_lo = 0.f, l_hi = 0.f;

    const __nv_bfloat16* kh_b = g_h3 + ZSZ     + (size_t)bh * TT * DH;
    const __nv_bfloat16* kl_b = g_l3 + ZSZ     + (size_t)bh * TT * DH;
    const __nv_bfloat16* vh_b = g_h3 + 2 * ZSZ + (size_t)bh * TT * DH;
    const __nv_bfloat16* vl_b = g_l3 + 2 * ZSZ + (size_t)bh * TT * DH;

    const int row_lo = qb * 128 + wid * 16 + g;
    const int row_hi = row_lo + 8;
    const int nkb = 2 * qb + 2;

    // stage loader: 512 16B-chunks per array; 2 per thread per array
    auto issue = [&](int kb, int s) {
        const unsigned sb = uS + (unsigned)s * ASTG;
        const size_t t0 = (size_t)kb * 64 * DH;  // halves
        #pragma unroll
        for (int i = 0; i < 2; ++i) {
            const int ch  = tid + i * 256;          // 0..511
            const int row = ch >> 3;
            const int seg = ch & 7;
            const unsigned ro = (unsigned)(row * (AKVS * 2) + seg * 16);
            const size_t go = t0 + (size_t)ch * 8;  // halves
            cp16(sb + A_KH + ro, kh_b + go);
            cp16(sb + A_KL + ro, kl_b + go);
            cp16(sb + A_VH + ro, vh_b + go);
            cp16(sb + A_VL + ro, vl_b + go);
        }
    };

    issue(0, 0);
    cp_commit();

    #pragma unroll 1
    for (int kb = 0; kb < nkb; ++kb) {
        const int s = kb & 1;
        if (kb + 1 < nkb) {
            issue(kb + 1, s ^ 1);
            cp_commit();
            cp_wait<1>();
        } else {
            cp_wait<0>();
        }
        __syncthreads();

        const unsigned sk = uS + (unsigned)s * ASTG;

        // ---- S = Q K^T (bf16x3, same as R6) ----
        float sx[8][4];
        #pragma unroll
        for (int i = 0; i < 8; ++i)
            #pragma unroll
            for (int j = 0; j < 4; ++j) sx[i][j] = 0.f;

        #pragma unroll
        for (int kc = 0; kc < 4; ++kc) {
            #pragma unroll
            for (int ntp = 0; ntp < 4; ++ntp) {
                const unsigned off = (unsigned)(((ntp * 16 + rowB_) * AKVS + kc * 16 + colB_) * 2);
                unsigned rh[4], rl[4];
                ldm4(rh, sk + A_KH + off);
                ldm4(rl, sk + A_KL + off);
                float* s0 = sx[ntp * 2];
                float* s1 = sx[ntp * 2 + 1];
                mma16(s0, qfh[kc][0], qfh[kc][1], qfh[kc][2], qfh[kc][3], rh[0], rh[1]);
                mma16(s0, qfh[kc][0], qfh[kc][1], qfh[kc][2], qfh[kc][3], rl[0], rl[1]);
                mma16(s0, qfl[kc][0], qfl[kc][1], qfl[kc][2], qfl[kc][3], rh[0], rh[1]);
                mma16(s1, qfh[kc][0], qfh[kc][1], qfh[kc][2], qfh[kc][3], rh[2], rh[3]);
                mma16(s1, qfh[kc][0], qfh[kc][1], qfh[kc][2], qfh[kc][3], rl[2], rl[3]);
                mma16(s1, qfl[kc][0], qfl[kc][1], qfl[kc][2], qfl[kc][3], rh[2], rh[3]);
            }
        }

        // ---- causal mask (only where this warp's rows touch the diagonal) ----
        if (kb * 64 + 63 > qb * 128 + wid * 16) {
            #pragma unroll
            for (int nt = 0; nt < 8; ++nt) {
                const int k0 = kb * 64 + nt * 8 + c * 2;
                if (k0 > row_lo)     sx[nt][0] = -1e30f;
                if (k0 + 1 > row_lo) sx[nt][1] = -1e30f;
                if (k0 > row_hi)     sx[nt][2] = -1e30f;
                if (k0 + 1 > row_hi) sx[nt][3] = -1e30f;
            }
        }

        // ---- online softmax (log2 domain, same as R6) ----
        {
            float mx = -1e30f;
            #pragma unroll
            for (int nt = 0; nt < 8; ++nt) mx = fmaxf(mx, fmaxf(sx[nt][0], sx[nt][1]));
            mx = fmaxf(mx, __shfl_xor_sync(0xffffffffu, mx, 1));
            mx = fmaxf(mx, __shfl_xor_sync(0xffffffffu, mx, 2));
            const float mn = fmaxf(m_lo, mx);
            const float al = ex2(m_lo - mn);
            m_lo = mn;
            float ls = 0.f;
            #pragma unroll
            for (int nt = 0; nt < 8; ++nt) {
                sx[nt][0] = ex2(sx[nt][0] - mn); ls += sx[nt][0];
                sx[nt][1] = ex2(sx[nt][1] - mn); ls += sx[nt][1];
                o[nt][0] *= al; o[nt][1] *= al;
            }
            l_lo = l_lo * al + ls;
        }
        {
            float mx = -1e30f;
            #pragma unroll
            for (int nt = 0; nt < 8; ++nt) mx = fmaxf(mx, fmaxf(sx[nt][2], sx[nt][3]));
            mx = fmaxf(mx, __shfl_xor_sync(0xffffffffu, mx, 1));
            mx = fmaxf(mx, __shfl_xor_sync(0xffffffffu, mx, 2));
            const float mn = fmaxf(m_hi, mx);
            const float al = ex2(m_hi - mn);
            m_hi = mn;
            float ls = 0.f;
            #pragma unroll
            for (int nt = 0; nt < 8; ++nt) {
                sx[nt][2] = ex2(sx[nt][2] - mn); ls += sx[nt][2];
                sx[nt][3] = ex2(sx[nt][3] - mn); ls += sx[nt][3];
                o[nt][2] *= al; o[nt][3] *= al;
            }
            l_hi = l_hi * al + ls;
        }

        // ---- O += P V (bf16x3; P thread-local; V frags via ldmatrix.trans) ----
        #pragma unroll
        for (int kc = 0; kc < 4; ++kc) {
            __nv_bfloat16 h00, h01, h02, h03, h10, h11, h12, h13;
            float l00, l01, l02, l03, l10, l11, l12, l13;
            bsplit(sx[2*kc][0],   h00, l00);  bsplit(sx[2*kc][1],   h01, l01);
            bsplit(sx[2*kc][2],   h02, l02);  bsplit(sx[2*kc][3],   h03, l03);
            bsplit(sx[2*kc+1][0], h10, l10);  bsplit(sx[2*kc+1][1], h11, l11);
            bsplit(sx[2*kc+1][2], h12, l12);  bsplit(sx[2*kc+1][3], h13, l13);
            const unsigned ah0 = pack_bf(h00, h01);
            const unsigned ah1 = pack_bf(h02, h03);
            const unsigned ah2 = pack_bf(h10, h11);
            const unsigned ah3 = pack_bf(h12, h13);
            const unsigned al0 = pack_f(l00, l01);
            const unsigned al1 = pack_f(l02, l03);
            const unsigned al2 = pack_f(l10, l11);
            const unsigned al3 = pack_f(l12, l13);
            #pragma unroll
            for (int ntp = 0; ntp < 4; ++ntp) {
                const unsigned off =
                    (unsigned)(((kc * 16 + vkey_) * AKVS + ntp * 16 + vd_) * 2);
                unsigned vh[4], vl[4];
                ldm4t(vh, sk + A_VH + off);
                ldm4t(vl, sk + A_VL + off);
                float* o0 = o[ntp * 2];
                float* o1 = o[ntp * 2 + 1];
                mma16(o0, ah0, ah1, ah2, ah3, vh[0], vh[1]);
                mma16(o0, ah0, ah1, ah2, ah3, vl[0], vl[1]);
                mma16(o0, al0, al1, al2, al3, vh[0], vh[1]);
                mma16(o1, ah0, ah1, ah2, ah3, vh[2], vh[3]);
                mma16(o1, ah0, ah1, ah2, ah3, vl[2], vl[3]);
                mma16(o1, al0, al1, al2, al3, vh[2], vh[3]);
            }
        }
        __syncthreads();
    }

    // ---- epilogue: normalize, split, write y hi/lo (same as R6) ----
    l_lo += __shfl_xor_sync(0xffffffffu, l_lo, 1);
    l_lo += __shfl_xor_sync(0xffffffffu, l_lo, 2);
    l_hi += __shfl_xor_sync(0xffffffffu, l_hi, 1);
    l_hi += __shfl_xor_sync(0xffffffffu, l_hi, 2);
    const float inv_lo = 1.f / l_lo;
    const float inv_hi = 1.f / l_hi;

    const int bbv = bh / NH;
    const int hd  = bh % NH;
    const size_t alo = ((size_t)bbv * TT + row_lo) * DM + hd * DH + 2 * c;
    const size_t ahi = ((size_t)bbv * TT + row_hi) * DM + hd * DH + 2 * c;
    #pragma unroll
    for (int nt = 0; nt < 8; ++nt) {
        __nv_bfloat16 h0, h1; float l0, l1;
        bsplit(o[nt][0] * inv_lo, h0, l0);
        bsplit(o[nt][1] * inv_lo, h1, l1);
        *(__nv_bfloat162*)(g_yh + alo + nt * 8) = __halves2bfloat162(h0, h1);
        *(__nv_bfloat162*)(g_yl + alo + nt * 8) = __floats2bfloat162_rn(l0, l1);
        bsplit(o[nt][2] * inv_hi, h0, l0);
        bsplit(o[nt][3] * inv_hi, h1, l1);
        *(__nv_bfloat162*)(g_yh + ahi + nt * 8) = __halves2bfloat162(h0, h1);
        *(__nv_bfloat162*)(g_yl + ahi + nt * 8) = __floats2bfloat162_rn(l0, l1);
    }
    (void)dummy;
}

// ---------------------------------------------------------------------------
extern "C" void kernel_launch(void* const* d_in, const int* in_sizes, int n_in,
                              void* d_out, int out_size)
{
    const float* x  = (const float*)d_in[0];
    const float* Wq = (const float*)d_in[1];
    const float* bq = (const float*)d_in[2];
    const float* Wk = (const float*)d_in[3];
    const float* bk = (const float*)d_in[4];
    const float* Wv = (const float*)d_in[5];
    const float* bv = (const float*)d_in[6];
    const float* Wp = (const float*)d_in[7];
    const float* bp = (const float*)d_in[8];
    float* out = (float*)d_out;

    __nv_bfloat16 *xh, *xl, *wh, *wl, *h3, *l3, *yh, *yl;
    cudaGetSymbolAddress((void**)&xh, g_xh);
    cudaGetSymbolAddress((void**)&xl, g_xl);
    cudaGetSymbolAddress((void**)&wh, g_wh);
    cudaGetSymbolAddress((void**)&wl, g_wl);
    cudaGetSymbolAddress((void**)&h3, g_h3);
    cudaGetSymbolAddress((void**)&l3, g_l3);
    cudaGetSymbolAddress((void**)&yh, g_yh);
    cudaGetSymbolAddress((void**)&yl, g_yl);

    cudaFuncSetAttribute(attn_bf, cudaFuncAttributeMaxDynamicSharedMemorySize, ASMEM);

    // pre-pass conversions (x + all 4 weights in 2 launches)
    const int n4x = MROWS * DM / 4;
    const int n4w = DM * DM / 4;
    convert_split<<<(n4x + 255) / 256, 256>>>(x, xh, xl, n4x);
    dim3 wgrid((n4w + 255) / 256, 4);
    convert_w4<<<wgrid, 256>>>(Wq, Wk, Wv, Wp, wh, wl, n4w);

    // QKV (merged, permuted bf16 hi/lo out)
    dim3 qkv_grid(DM / 128, MROWS / 128, 3);
    gemm_bf<0><<<qkv_grid, 256>>>(xh, xl, wh, wl, bq, bk, bv, h3, l3, nullptr);

    // attention (Br=128)
    dim3 attn_grid(TT / 128, BB * NH);
    attn_bf<<<attn_grid, 256, ASMEM>>>(nullptr);

    // out-proj (fp32 out)
    dim3 proj_grid(DM / 128, MROWS / 128, 1);
    gemm_bf<1><<<proj_grid, 256>>>(yh, yl, wh, wl, bp, bp, bp, nullptr, nullptr, out);
}

// round 9
// speedup vs baseline: 3.8340x; 1.0370x over previous
#include <cuda_runtime.h>
#include <cuda_bf16.h>
#include <math.h>

#define DM 768
#define NH 12
#define DH 64
#define BB 4
#define TT 2048
#define MROWS (BB*TT)   // 8192
#define ZSZ ((size_t)BB*NH*TT*DH)   // per-tensor q/k/v elems

// ---------------- scratch (device globals; no allocation allowed) ----------
__device__ __nv_bfloat16 g_xh[(size_t)MROWS*DM], g_xl[(size_t)MROWS*DM];
__device__ __nv_bfloat16 g_wh[4*(size_t)DM*DM], g_wl[4*(size_t)DM*DM];
__device__ __nv_bfloat16 g_h3[3*ZSZ], g_l3[3*ZSZ];      // q,k,v hi / lo
__device__ __nv_bfloat16 g_yh[(size_t)MROWS*DM], g_yl[(size_t)MROWS*DM];

// ---------------- helpers --------------------------------------------------
__device__ __forceinline__ float ex2(float x) {
    float r; asm("ex2.approx.f32 %0, %1;" : "=f"(r) : "f"(x)); return r;
}
__device__ __forceinline__ void mma16(float d[4],
                                      unsigned a0, unsigned a1, unsigned a2, unsigned a3,
                                      unsigned b0, unsigned b1) {
    asm volatile(
        "mma.sync.aligned.m16n8k16.row.col.f32.bf16.bf16.f32 "
        "{%0,%1,%2,%3}, {%4,%5,%6,%7}, {%8,%9}, {%0,%1,%2,%3};\n"
        : "+f"(d[0]), "+f"(d[1]), "+f"(d[2]), "+f"(d[3])
        : "r"(a0), "r"(a1), "r"(a2), "r"(a3), "r"(b0), "r"(b1));
}
__device__ __forceinline__ void ldm4(unsigned r[4], unsigned addr) {
    asm volatile("ldmatrix.sync.aligned.m8n8.x4.shared.b16 {%0,%1,%2,%3}, [%4];"
                 : "=r"(r[0]), "=r"(r[1]), "=r"(r[2]), "=r"(r[3]) : "r"(addr));
}
__device__ __forceinline__ void ldm4t(unsigned r[4], unsigned addr) {
    asm volatile("ldmatrix.sync.aligned.m8n8.x4.trans.shared.b16 {%0,%1,%2,%3}, [%4];"
                 : "=r"(r[0]), "=r"(r[1]), "=r"(r[2]), "=r"(r[3]) : "r"(addr));
}
__device__ __forceinline__ unsigned s2u(const void* p) {
    return (unsigned)__cvta_generic_to_shared(p);
}
__device__ __forceinline__ void cp16(unsigned saddr, const void* gptr) {
    asm volatile("cp.async.cg.shared.global [%0], [%1], 16;"
                 :: "r"(saddr), "l"(gptr) : "memory");
}
__device__ __forceinline__ void cp_commit() {
    asm volatile("cp.async.commit_group;" ::: "memory");
}
template<int N>
__device__ __forceinline__ void cp_wait() {
    asm volatile("cp.async.wait_group %0;" :: "n"(N) : "memory");
}
__device__ __forceinline__ unsigned pack_bf(__nv_bfloat16 a, __nv_bfloat16 b) {
    __nv_bfloat162 t = __halves2bfloat162(a, b);
    return *reinterpret_cast<unsigned*>(&t);
}
__device__ __forceinline__ unsigned pack_f(float a, float b) {
    __nv_bfloat162 t = __floats2bfloat162_rn(a, b);
    return *reinterpret_cast<unsigned*>(&t);
}
__device__ __forceinline__ void bsplit(float x, __nv_bfloat16& h, float& l) {
    h = __float2bfloat16(x);
    l = x - __bfloat162float(h);
}

// ---------------- pre-pass: fp32 -> bf16 hi/lo -----------------------------
__global__ void convert_split(const float* __restrict__ src,
                              __nv_bfloat16* __restrict__ h,
                              __nv_bfloat16* __restrict__ l, int n4)
{
    int i = blockIdx.x * blockDim.x + threadIdx.x;
    if (i >= n4) return;
    float4 v = reinterpret_cast<const float4*>(src)[i];
    __nv_bfloat16 h0, h1, h2, h3; float l0, l1, l2, l3;
    bsplit(v.x, h0, l0); bsplit(v.y, h1, l1);
    bsplit(v.z, h2, l2); bsplit(v.w, h3, l3);
    reinterpret_cast<__nv_bfloat162*>(h)[2*i]   = __halves2bfloat162(h0, h1);
    reinterpret_cast<__nv_bfloat162*>(h)[2*i+1] = __halves2bfloat162(h2, h3);
    reinterpret_cast<__nv_bfloat162*>(l)[2*i]   = __floats2bfloat162_rn(l0, l1);
    reinterpret_cast<__nv_bfloat162*>(l)[2*i+1] = __floats2bfloat162_rn(l2, l3);
}
// all 4 weight matrices in one launch (blockIdx.y selects matrix)
__global__ void convert_w4(const float* __restrict__ s0, const float* __restrict__ s1,
                           const float* __restrict__ s2, const float* __restrict__ s3,
                           __nv_bfloat16* __restrict__ h, __nv_bfloat16* __restrict__ l,
                           int n4)
{
    int i = blockIdx.x * blockDim.x + threadIdx.x;
    if (i >= n4) return;
    const int z = blockIdx.y;
    const float* src = (z == 0) ? s0 : ((z == 1) ? s1 : ((z == 2) ? s2 : s3));
    const size_t off2 = (size_t)z * (DM * DM / 2);   // in bf16x2 units
    float4 v = reinterpret_cast<const float4*>(src)[i];
    __nv_bfloat16 h0, h1, h2, h3; float l0, l1, l2, l3;
    bsplit(v.x, h0, l0); bsplit(v.y, h1, l1);
    bsplit(v.z, h2, l2); bsplit(v.w, h3, l3);
    reinterpret_cast<__nv_bfloat162*>(h)[off2 + 2*i]   = __halves2bfloat162(h0, h1);
    reinterpret_cast<__nv_bfloat162*>(h)[off2 + 2*i+1] = __halves2bfloat162(h2, h3);
    reinterpret_cast<__nv_bfloat162*>(l)[off2 + 2*i]   = __floats2bfloat162_rn(l0, l1);
    reinterpret_cast<__nv_bfloat162*>(l)[off2 + 2*i+1] = __floats2bfloat162_rn(l2, l3);
}

// ---------------------------------------------------------------------------
// bf16x3 GEMM (mma.sync), 3-stage cp.async pipeline, ONE barrier per iter.
// BM=BN=128, BK=16, 8 warps (2m x 4n). smem stride 24 halves. Same math as R6.
// MODE 0: QKV (z in 0..2; permuted bf16 hi/lo out). MODE 1: proj (fp32 out).
// ---------------------------------------------------------------------------
#define HST 24
#define ABYTES (128*HST*2)     // 6144 per array
#define GSTG  (4*ABYTES)       // 24576 per stage
#define GSMEM (3*GSTG)         // 73728

template<int MODE>
__global__ __launch_bounds__(256, 2)
void gemm_bf(const __nv_bfloat16* __restrict__ Ah, const __nv_bfloat16* __restrict__ Al,
             const __nv_bfloat16* __restrict__ Whb, const __nv_bfloat16* __restrict__ Wlb,
             const float* __restrict__ b0p, const float* __restrict__ b1p,
             const float* __restrict__ b2p,
             __nv_bfloat16* __restrict__ ChB, __nv_bfloat16* __restrict__ ClB,
             float* __restrict__ outF)
{
    extern __shared__ __align__(16) char gsm[];
    const unsigned sbase = s2u(gsm);

    const int z = blockIdx.z;
    const size_t woff = (size_t)((MODE == 0) ? z : 3) * DM * DM;
    const float* bias = (z == 0) ? b0p : ((z == 1) ? b1p : b2p);

    const int tid  = threadIdx.x;
    const int lane = tid & 31;
    const int wid  = tid >> 5;
    const int m0 = blockIdx.y * 128;
    const int n0 = blockIdx.x * 128;
    const int wm = wid >> 2;
    const int wn = wid & 3;
    const int g  = lane >> 2;
    const int c  = lane & 3;

    const int rowA_ = (lane & 7) + ((lane >> 3) & 1) * 8;
    const int colA_ = (lane >> 4) * 8;
    const int rowB_ = (lane & 7) + ((lane >> 4) & 1) * 8;
    const int colB_ = ((lane >> 3) & 1) * 8;

    const bool isA = tid < 128;
    const int lrow = tid & 127;
    const __nv_bfloat16* ph = (isA ? Ah + (size_t)(m0 + lrow) * DM
                                   : Whb + woff + (size_t)(n0 + lrow) * DM);
    const __nv_bfloat16* pl = (isA ? Al + (size_t)(m0 + lrow) * DM
                                   : Wlb + woff + (size_t)(n0 + lrow) * DM);

    const int arrH = isA ? 0 : 2;
    const unsigned sH = (unsigned)(arrH * ABYTES + lrow * (HST * 2));
    const unsigned sL = sH + ABYTES;

    float acc[4][4][4];
    #pragma unroll
    for (int i = 0; i < 4; i++)
        #pragma unroll
        for (int j = 0; j < 4; j++)
            #pragma unroll
            for (int r = 0; r < 4; r++) acc[i][j][r] = 0.f;

    auto issueG = [&](int itx, int st) {
        const int k0 = itx * 16;
        const unsigned sb = sbase + (unsigned)st * GSTG;
        cp16(sb + sH,      ph + k0);  cp16(sb + sH + 16, ph + k0 + 8);
        cp16(sb + sL,      pl + k0);  cp16(sb + sL + 16, pl + k0 + 8);
    };

    // prologue: stages 0 and 1 in flight
    issueG(0, 0); cp_commit();
    issueG(1, 1); cp_commit();

    #pragma unroll 1
    for (int it = 0; it < 48; ++it) {
        const int s = it % 3;
        if (it == 47) { cp_wait<0>(); } else { cp_wait<1>(); }
        __syncthreads();   // stage s visible to all; all warps done with stage (it+2)%3
        if (it + 2 < 48) { issueG(it + 2, (it + 2) % 3); cp_commit(); }

        // ---- fragments via ldmatrix (same math as R6) ----
        const unsigned bufo = sbase + (unsigned)s * GSTG;
        unsigned bh[4][2], bl[4][2];
        #pragma unroll
        for (int ntp = 0; ntp < 2; ++ntp) {
            unsigned r[4];
            const int rb = wn * 32 + ntp * 16 + rowB_;
            ldm4(r, bufo + 2u * ABYTES + (unsigned)((rb * HST + colB_) * 2));
            bh[ntp*2][0] = r[0]; bh[ntp*2][1] = r[1];
            bh[ntp*2+1][0] = r[2]; bh[ntp*2+1][1] = r[3];
            ldm4(r, bufo + 3u * ABYTES + (unsigned)((rb * HST + colB_) * 2));
            bl[ntp*2][0] = r[0]; bl[ntp*2][1] = r[1];
            bl[ntp*2+1][0] = r[2]; bl[ntp*2+1][1] = r[3];
        }
        #pragma unroll
        for (int mi = 0; mi < 4; ++mi) {
            const int ra = wm * 64 + mi * 16 + rowA_;
            unsigned ah[4], al[4];
            ldm4(ah, bufo + (unsigned)((ra * HST + colA_) * 2));
            ldm4(al, bufo + 1u * ABYTES + (unsigned)((ra * HST + colA_) * 2));
            #pragma unroll
            for (int ni = 0; ni < 4; ++ni) {
                mma16(acc[mi][ni], ah[0], ah[1], ah[2], ah[3], bh[ni][0], bh[ni][1]);
                mma16(acc[mi][ni], ah[0], ah[1], ah[2], ah[3], bl[ni][0], bl[ni][1]);
                mma16(acc[mi][ni], al[0], al[1], al[2], al[3], bh[ni][0], bh[ni][1]);
            }
        }
    }

    // ---- epilogue (unchanged) ----
    __nv_bfloat16* Ch = (MODE == 0) ? (ChB + (size_t)z * ZSZ) : nullptr;
    __nv_bfloat16* Cl = (MODE == 0) ? (ClB + (size_t)z * ZSZ) : nullptr;
    #pragma unroll
    for (int mi = 0; mi < 4; ++mi) {
        const int row = m0 + wm * 64 + mi * 16 + g;
        #pragma unroll
        for (int ni = 0; ni < 4; ++ni) {
            const int col = n0 + wn * 32 + ni * 8 + c * 2;
            float2 bv = *(const float2*)(bias + col);
            float v0 = acc[mi][ni][0] + bv.x;
            float v1 = acc[mi][ni][1] + bv.y;
            float v2 = acc[mi][ni][2] + bv.x;
            float v3 = acc[mi][ni][3] + bv.y;
            if (MODE == 0) {
                const int bb = row >> 11;
                const int t  = row & 2047;
                const int hd = col >> 6;
                const int d  = col & 63;
                const size_t a0 = ((size_t)(bb * NH + hd) * TT + t) * DH + d;
                __nv_bfloat16 h0, h1; float l0, l1;
                bsplit(v0, h0, l0); bsplit(v1, h1, l1);
                *(__nv_bfloat162*)(Ch + a0) = __halves2bfloat162(h0, h1);
                *(__nv_bfloat162*)(Cl + a0) = __floats2bfloat162_rn(l0, l1);
                bsplit(v2, h0, l0); bsplit(v3, h1, l1);
                *(__nv_bfloat162*)(Ch + a0 + 8 * DH) = __halves2bfloat162(h0, h1);
                *(__nv_bfloat162*)(Cl + a0 + 8 * DH) = __floats2bfloat162_rn(l0, l1);
            } else {
                *(float2*)(outF + (size_t)row * DM + col)       = make_float2(v0, v1);
                *(float2*)(outF + (size_t)(row + 8) * DM + col) = make_float2(v2, v3);
            }
        }
    }
}

// ---------------------------------------------------------------------------
// Flash attention, bf16x3 (same math as R6/R8). Br=128, Bc=64, 8 warps.
// 3-stage cp.async K/V staging, ONE barrier per iteration.
// ---------------------------------------------------------------------------
#define AKVS 72
#define AARR 9216                  // 64 * 72 * 2 bytes
#define ASTG (4*AARR)              // Kh,Kl,Vh,Vl = 36864
#define A_KH 0
#define A_KL AARR
#define A_VH (2*AARR)
#define A_VL (3*AARR)
#define ASMEM (3*ASTG)             // 110592

__global__ __launch_bounds__(256, 2)
void attn_bf(float* __restrict__ dummy)
{
    extern __shared__ __align__(16) char asmz[];
    const unsigned uS = s2u(asmz);

    const int tid  = threadIdx.x;
    const int lane = tid & 31;
    const int wid  = tid >> 5;       // 0..7
    const int qb = blockIdx.x;       // 0..15 (128-row q tiles)
    const int bh = blockIdx.y;       // 0..47
    const int g  = lane >> 2;
    const int c  = lane & 3;

    const int rowB_ = (lane & 7) + ((lane >> 4) & 1) * 8;
    const int colB_ = ((lane >> 3) & 1) * 8;
    const int vkey_ = lane & 15;
    const int vd_   = (lane >> 4) * 8;

    // ---- Q fragments (same as R6/R8) ----
    const float SC = 0.125f * 1.4426950408889634f;
    const __nv_bfloat16* qhp = g_h3 + ((size_t)bh * TT + qb * 128 + wid * 16) * DH;
    const __nv_bfloat16* qlp = g_l3 + ((size_t)bh * TT + qb * 128 + wid * 16) * DH;
    unsigned qfh[4][4], qfl[4][4];
    #pragma unroll
    for (int kc = 0; kc < 4; ++kc) {
        #pragma unroll
        for (int j = 0; j < 4; ++j) {
            const int row = g + (j & 1) * 8;
            const int col = kc * 16 + 2 * c + (j >> 1) * 8;
            __nv_bfloat162 hh = *(const __nv_bfloat162*)(qhp + (size_t)row * DH + col);
            __nv_bfloat162 ll = *(const __nv_bfloat162*)(qlp + (size_t)row * DH + col);
            float x0 = (__bfloat162float(hh.x) + __bfloat162float(ll.x)) * SC;
            float x1 = (__bfloat162float(hh.y) + __bfloat162float(ll.y)) * SC;
            __nv_bfloat16 h0, h1; float l0, l1;
            bsplit(x0, h0, l0); bsplit(x1, h1, l1);
            qfh[kc][j] = pack_bf(h0, h1);
            qfl[kc][j] = pack_f(l0, l1);
        }
    }

    float o[8][4];
    #pragma unroll
    for (int i = 0; i < 8; ++i)
        #pragma unroll
        for (int j = 0; j < 4; ++j) o[i][j] = 0.f;
    float m_lo = -1e30f, m_hi = -1e30f, l_lo = 0.f, l_hi = 0.f;

    const __nv_bfloat16* kh_b = g_h3 + ZSZ     + (size_t)bh * TT * DH;
    const __nv_bfloat16* kl_b = g_l3 + ZSZ     + (size_t)bh * TT * DH;
    const __nv_bfloat16* vh_b = g_h3 + 2 * ZSZ + (size_t)bh * TT * DH;
    const __nv_bfloat16* vl_b = g_l3 + 2 * ZSZ + (size_t)bh * TT * DH;

    const int row_lo = qb * 128 + wid * 16 + g;
    const int row_hi = row_lo + 8;
    const int nkb = 2 * qb + 2;

    auto issue = [&](int kb, int st) {
        const unsigned sb = uS + (unsigned)st * ASTG;
        const size_t t0 = (size_t)kb * 64 * DH;  // halves
        #pragma unroll
        for (int i = 0; i < 2; ++i) {
            const int ch  = tid + i * 256;          // 0..511
            const int row = ch >> 3;
            const int seg = ch & 7;
            const unsigned ro = (unsigned)(row * (AKVS * 2) + seg * 16);
            const size_t go = t0 + (size_t)ch * 8;  // halves
            cp16(sb + A_KH + ro, kh_b + go);
            cp16(sb + A_KL + ro, kl_b + go);
            cp16(sb + A_VH + ro, vh_b + go);
            cp16(sb + A_VL + ro, vl_b + go);
        }
    };

    // prologue: stages 0 and 1 in flight (nkb >= 2 always)
    issue(0, 0); cp_commit();
    issue(1, 1); cp_commit();

    #pragma unroll 1
    for (int kb = 0; kb < nkb; ++kb) {
        const int s = kb % 3;
        if (kb == nkb - 1) { cp_wait<0>(); } else { cp_wait<1>(); }
        __syncthreads();   // stage s visible; all warps done with stage (kb+2)%3
        if (kb + 2 < nkb) { issue(kb + 2, (kb + 2) % 3); cp_commit(); }

        const unsigned sk = uS + (unsigned)s * ASTG;

        // ---- S = Q K^T (bf16x3) ----
        float sx[8][4];
        #pragma unroll
        for (int i = 0; i < 8; ++i)
            #pragma unroll
            for (int j = 0; j < 4; ++j) sx[i][j] = 0.f;

        #pragma unroll
        for (int kc = 0; kc < 4; ++kc) {
            #pragma unroll
            for (int ntp = 0; ntp < 4; ++ntp) {
                const unsigned off = (unsigned)(((ntp * 16 + rowB_) * AKVS + kc * 16 + colB_) * 2);
                unsigned rh[4], rl[4];
                ldm4(rh, sk + A_KH + off);
                ldm4(rl, sk + A_KL + off);
                float* s0 = sx[ntp * 2];
                float* s1 = sx[ntp * 2 + 1];
                mma16(s0, qfh[kc][0], qfh[kc][1], qfh[kc][2], qfh[kc][3], rh[0], rh[1]);
                mma16(s0, qfh[kc][0], qfh[kc][1], qfh[kc][2], qfh[kc][3], rl[0], rl[1]);
                mma16(s0, qfl[kc][0], qfl[kc][1], qfl[kc][2], qfl[kc][3], rh[0], rh[1]);
                mma16(s1, qfh[kc][0], qfh[kc][1], qfh[kc][2], qfh[kc][3], rh[2], rh[3]);
                mma16(s1, qfh[kc][0], qfh[kc][1], qfh[kc][2], qfh[kc][3], rl[2], rl[3]);
                mma16(s1, qfl[kc][0], qfl[kc][1], qfl[kc][2], qfl[kc][3], rh[2], rh[3]);
            }
        }

        // ---- causal mask ----
        if (kb * 64 + 63 > qb * 128 + wid * 16) {
            #pragma unroll
            for (int nt = 0; nt < 8; ++nt) {
                const int k0 = kb * 64 + nt * 8 + c * 2;
                if (k0 > row_lo)     sx[nt][0] = -1e30f;
                if (k0 + 1 > row_lo) sx[nt][1] = -1e30f;
                if (k0 > row_hi)     sx[nt][2] = -1e30f;
                if (k0 + 1 > row_hi) sx[nt][3] = -1e30f;
            }
        }

        // ---- online softmax (log2 domain) ----
        {
            float mx = -1e30f;
            #pragma unroll
            for (int nt = 0; nt < 8; ++nt) mx = fmaxf(mx, fmaxf(sx[nt][0], sx[nt][1]));
            mx = fmaxf(mx, __shfl_xor_sync(0xffffffffu, mx, 1));
            mx = fmaxf(mx, __shfl_xor_sync(0xffffffffu, mx, 2));
            const float mn = fmaxf(m_lo, mx);
            const float al = ex2(m_lo - mn);
            m_lo = mn;
            float ls = 0.f;
            #pragma unroll
            for (int nt = 0; nt < 8; ++nt) {
                sx[nt][0] = ex2(sx[nt][0] - mn); ls += sx[nt][0];
                sx[nt][1] = ex2(sx[nt][1] - mn); ls += sx[nt][1];
                o[nt][0] *= al; o[nt][1] *= al;
            }
            l_lo = l_lo * al + ls;
        }
        {
            float mx = -1e30f;
            #pragma unroll
            for (int nt = 0; nt < 8; ++nt) mx = fmaxf(mx, fmaxf(sx[nt][2], sx[nt][3]));
            mx = fmaxf(mx, __shfl_xor_sync(0xffffffffu, mx, 1));
            mx = fmaxf(mx, __shfl_xor_sync(0xffffffffu, mx, 2));
            const float mn = fmaxf(m_hi, mx);
            const float al = ex2(m_hi - mn);
            m_hi = mn;
            float ls = 0.f;
            #pragma unroll
            for (int nt = 0; nt < 8; ++nt) {
                sx[nt][2] = ex2(sx[nt][2] - mn); ls += sx[nt][2];
                sx[nt][3] = ex2(sx[nt][3] - mn); ls += sx[nt][3];
                o[nt][2] *= al; o[nt][3] *= al;
            }
            l_hi = l_hi * al + ls;
        }

        // ---- O += P V (bf16x3; P thread-local; V frags via ldmatrix.trans) ----
        #pragma unroll
        for (int kc = 0; kc < 4; ++kc) {
            __nv_bfloat16 h00, h01, h02, h03, h10, h11, h12, h13;
            float l00, l01, l02, l03, l10, l11, l12, l13;
            bsplit(sx[2*kc][0],   h00, l00);  bsplit(sx[2*kc][1],   h01, l01);
            bsplit(sx[2*kc][2],   h02, l02);  bsplit(sx[2*kc][3],   h03, l03);
            bsplit(sx[2*kc+1][0], h10, l10);  bsplit(sx[2*kc+1][1], h11, l11);
            bsplit(sx[2*kc+1][2], h12, l12);  bsplit(sx[2*kc+1][3], h13, l13);
            const unsigned ah0 = pack_bf(h00, h01);
            const unsigned ah1 = pack_bf(h02, h03);
            const unsigned ah2 = pack_bf(h10, h11);
            const unsigned ah3 = pack_bf(h12, h13);
            const unsigned al0 = pack_f(l00, l01);
            const unsigned al1 = pack_f(l02, l03);
            const unsigned al2 = pack_f(l10, l11);
            const unsigned al3 = pack_f(l12, l13);
            #pragma unroll
            for (int ntp = 0; ntp < 4; ++ntp) {
                const unsigned off =
                    (unsigned)(((kc * 16 + vkey_) * AKVS + ntp * 16 + vd_) * 2);
                unsigned vh[4], vl[4];
                ldm4t(vh, sk + A_VH + off);
                ldm4t(vl, sk + A_VL + off);
                float* o0 = o[ntp * 2];
                float* o1 = o[ntp * 2 + 1];
                mma16(o0, ah0, ah1, ah2, ah3, vh[0], vh[1]);
                mma16(o0, ah0, ah1, ah2, ah3, vl[0], vl[1]);
                mma16(o0, al0, al1, al2, al3, vh[0], vh[1]);
                mma16(o1, ah0, ah1, ah2, ah3, vh[2], vh[3]);
                mma16(o1, ah0, ah1, ah2, ah3, vl[2], vl[3]);
                mma16(o1, al0, al1, al2, al3, vh[2], vh[3]);
            }
        }
    }

    // ---- epilogue (same as R6/R8) ----
    l_lo += __shfl_xor_sync(0xffffffffu, l_lo, 1);
    l_lo += __shfl_xor_sync(0xffffffffu, l_lo, 2);
    l_hi += __shfl_xor_sync(0xffffffffu, l_hi, 1);
    l_hi += __shfl_xor_sync(0xffffffffu, l_hi, 2);
    const float inv_lo = 1.f / l_lo;
    const float inv_hi = 1.f / l_hi;

    const int bbv = bh / NH;
    const int hd  = bh % NH;
    const size_t alo = ((size_t)bbv * TT + row_lo) * DM + hd * DH + 2 * c;
    const size_t ahi = ((size_t)bbv * TT + row_hi) * DM + hd * DH + 2 * c;
    #pragma unroll
    for (int nt = 0; nt < 8; ++nt) {
        __nv_bfloat16 h0, h1; float l0, l1;
        bsplit(o[nt][0] * inv_lo, h0, l0);
        bsplit(o[nt][1] * inv_lo, h1, l1);
        *(__nv_bfloat162*)(g_yh + alo + nt * 8) = __halves2bfloat162(h0, h1);
        *(__nv_bfloat162*)(g_yl + alo + nt * 8) = __floats2bfloat162_rn(l0, l1);
        bsplit(o[nt][2] * inv_hi, h0, l0);
        bsplit(o[nt][3] * inv_hi, h1, l1);
        *(__nv_bfloat162*)(g_yh + ahi + nt * 8) = __halves2bfloat162(h0, h1);
        *(__nv_bfloat162*)(g_yl + ahi + nt * 8) = __floats2bfloat162_rn(l0, l1);
    }
    (void)dummy;
}

// ---------------------------------------------------------------------------
extern "C" void kernel_launch(void* const* d_in, const int* in_sizes, int n_in,
                              void* d_out, int out_size)
{
    const float* x  = (const float*)d_in[0];
    const float* Wq = (const float*)d_in[1];
    const float* bq = (const float*)d_in[2];
    const float* Wk = (const float*)d_in[3];
    const float* bk = (const float*)d_in[4];
    const float* Wv = (const float*)d_in[5];
    const float* bv = (const float*)d_in[6];
    const float* Wp = (const float*)d_in[7];
    const float* bp = (const float*)d_in[8];
    float* out = (float*)d_out;

    __nv_bfloat16 *xh, *xl, *wh, *wl, *h3, *l3, *yh, *yl;
    cudaGetSymbolAddress((void**)&xh, g_xh);
    cudaGetSymbolAddress((void**)&xl, g_xl);
    cudaGetSymbolAddress((void**)&wh, g_wh);
    cudaGetSymbolAddress((void**)&wl, g_wl);
    cudaGetSymbolAddress((void**)&h3, g_h3);
    cudaGetSymbolAddress((void**)&l3, g_l3);
    cudaGetSymbolAddress((void**)&yh, g_yh);
    cudaGetSymbolAddress((void**)&yl, g_yl);

    cudaFuncSetAttribute(gemm_bf<0>, cudaFuncAttributeMaxDynamicSharedMemorySize, GSMEM);
    cudaFuncSetAttribute(gemm_bf<1>, cudaFuncAttributeMaxDynamicSharedMemorySize, GSMEM);
    cudaFuncSetAttribute(attn_bf, cudaFuncAttributeMaxDynamicSharedMemorySize, ASMEM);

    // pre-pass conversions (x + all 4 weights in 2 launches)
    const int n4x = MROWS * DM / 4;
    const int n4w = DM * DM / 4;
    convert_split<<<(n4x + 255) / 256, 256>>>(x, xh, xl, n4x);
    dim3 wgrid((n4w + 255) / 256, 4);
    convert_w4<<<wgrid, 256>>>(Wq, Wk, Wv, Wp, wh, wl, n4w);

    // QKV (merged, permuted bf16 hi/lo out)
    dim3 qkv_grid(DM / 128, MROWS / 128, 3);
    gemm_bf<0><<<qkv_grid, 256, GSMEM>>>(xh, xl, wh, wl, bq, bk, bv, h3, l3, nullptr);

    // attention (Br=128, 3-stage)
    dim3 attn_grid(TT / 128, BB * NH);
    attn_bf<<<attn_grid, 256, ASMEM>>>(nullptr);

    // out-proj (fp32 out)
    dim3 proj_grid(DM / 128, MROWS / 128, 1);
    gemm_bf<1><<<proj_grid, 256, GSMEM>>>(yh, yl, wh, wl, bp, bp, bp, nullptr, nullptr, out);
}

// round 10
// speedup vs baseline: 4.1616x; 1.0855x over previous
#include <cuda_runtime.h>
#include <cuda_bf16.h>
#include <math.h>

#define DM 768
#define NH 12
#define DH 64
#define BB 4
#define TT 2048
#define MROWS (BB*TT)   // 8192
#define ZSZ ((size_t)BB*NH*TT*DH)   // per-tensor q/k/v elems

// ---------------- scratch (device globals; no allocation allowed) ----------
__device__ __nv_bfloat16 g_xh[(size_t)MROWS*DM], g_xl[(size_t)MROWS*DM];
__device__ __nv_bfloat16 g_wh[4*(size_t)DM*DM], g_wl[4*(size_t)DM*DM];
__device__ __nv_bfloat16 g_h3[3*ZSZ], g_l3[3*ZSZ];      // q,k,v hi / lo
__device__ __nv_bfloat16 g_yh[(size_t)MROWS*DM], g_yl[(size_t)MROWS*DM];

// ---------------- helpers --------------------------------------------------
__device__ __forceinline__ float ex2(float x) {
    float r; asm("ex2.approx.f32 %0, %1;" : "=f"(r) : "f"(x)); return r;
}
__device__ __forceinline__ void mma16(float d[4],
                                      unsigned a0, unsigned a1, unsigned a2, unsigned a3,
                                      unsigned b0, unsigned b1) {
    asm volatile(
        "mma.sync.aligned.m16n8k16.row.col.f32.bf16.bf16.f32 "
        "{%0,%1,%2,%3}, {%4,%5,%6,%7}, {%8,%9}, {%0,%1,%2,%3};\n"
        : "+f"(d[0]), "+f"(d[1]), "+f"(d[2]), "+f"(d[3])
        : "r"(a0), "r"(a1), "r"(a2), "r"(a3), "r"(b0), "r"(b1));
}
__device__ __forceinline__ void ldm4(unsigned r[4], unsigned addr) {
    asm volatile("ldmatrix.sync.aligned.m8n8.x4.shared.b16 {%0,%1,%2,%3}, [%4];"
                 : "=r"(r[0]), "=r"(r[1]), "=r"(r[2]), "=r"(r[3]) : "r"(addr));
}
__device__ __forceinline__ void ldm4t(unsigned r[4], unsigned addr) {
    asm volatile("ldmatrix.sync.aligned.m8n8.x4.trans.shared.b16 {%0,%1,%2,%3}, [%4];"
                 : "=r"(r[0]), "=r"(r[1]), "=r"(r[2]), "=r"(r[3]) : "r"(addr));
}
__device__ __forceinline__ unsigned s2u(const void* p) {
    return (unsigned)__cvta_generic_to_shared(p);
}
__device__ __forceinline__ void cp16(unsigned saddr, const void* gptr) {
    asm volatile("cp.async.cg.shared.global [%0], [%1], 16;"
                 :: "r"(saddr), "l"(gptr) : "memory");
}
__device__ __forceinline__ void cp_commit() {
    asm volatile("cp.async.commit_group;" ::: "memory");
}
template<int N>
__device__ __forceinline__ void cp_wait() {
    asm volatile("cp.async.wait_group %0;" :: "n"(N) : "memory");
}
__device__ __forceinline__ unsigned pack_bf(__nv_bfloat16 a, __nv_bfloat16 b) {
    __nv_bfloat162 t = __halves2bfloat162(a, b);
    return *reinterpret_cast<unsigned*>(&t);
}
__device__ __forceinline__ unsigned pack_f(float a, float b) {
    __nv_bfloat162 t = __floats2bfloat162_rn(a, b);
    return *reinterpret_cast<unsigned*>(&t);
}
__device__ __forceinline__ void bsplit(float x, __nv_bfloat16& h, float& l) {
    h = __float2bfloat16(x);
    l = x - __bfloat162float(h);
}
// split a PAIR: h2 = {bf(x0), bf(x1)} packed, l2 = {bf(x0-hi0), bf(x1-hi1)}.
// Bit-identical to bsplit+pack (same .rn rounding; bf16->f32 via shifts is exact).
__device__ __forceinline__ void split2(float x0, float x1, unsigned& h2, unsigned& l2) {
    __nv_bfloat162 t = __floats2bfloat162_rn(x0, x1);
    h2 = *reinterpret_cast<unsigned*>(&t);
    const float f0 = __uint_as_float(h2 << 16);
    const float f1 = __uint_as_float(h2 & 0xFFFF0000u);
    __nv_bfloat162 tl = __floats2bfloat162_rn(x0 - f0, x1 - f1);
    l2 = *reinterpret_cast<unsigned*>(&tl);
}

// ---------------- pre-pass: fp32 -> bf16 hi/lo -----------------------------
__global__ void convert_split(const float* __restrict__ src,
                              __nv_bfloat16* __restrict__ h,
                              __nv_bfloat16* __restrict__ l, int n4)
{
    int i = blockIdx.x * blockDim.x + threadIdx.x;
    if (i >= n4) return;
    float4 v = reinterpret_cast<const float4*>(src)[i];
    __nv_bfloat16 h0, h1, h2, h3; float l0, l1, l2, l3;
    bsplit(v.x, h0, l0); bsplit(v.y, h1, l1);
    bsplit(v.z, h2, l2); bsplit(v.w, h3, l3);
    reinterpret_cast<__nv_bfloat162*>(h)[2*i]   = __halves2bfloat162(h0, h1);
    reinterpret_cast<__nv_bfloat162*>(h)[2*i+1] = __halves2bfloat162(h2, h3);
    reinterpret_cast<__nv_bfloat162*>(l)[2*i]   = __floats2bfloat162_rn(l0, l1);
    reinterpret_cast<__nv_bfloat162*>(l)[2*i+1] = __floats2bfloat162_rn(l2, l3);
}
// all 4 weight matrices in one launch (blockIdx.y selects matrix)
__global__ void convert_w4(const float* __restrict__ s0, const float* __restrict__ s1,
                           const float* __restrict__ s2, const float* __restrict__ s3,
                           __nv_bfloat16* __restrict__ h, __nv_bfloat16* __restrict__ l,
                           int n4)
{
    int i = blockIdx.x * blockDim.x + threadIdx.x;
    if (i >= n4) return;
    const int z = blockIdx.y;
    const float* src = (z == 0) ? s0 : ((z == 1) ? s1 : ((z == 2) ? s2 : s3));
    const size_t off2 = (size_t)z * (DM * DM / 2);   // in bf16x2 units
    float4 v = reinterpret_cast<const float4*>(src)[i];
    __nv_bfloat16 h0, h1, h2, h3; float l0, l1, l2, l3;
    bsplit(v.x, h0, l0); bsplit(v.y, h1, l1);
    bsplit(v.z, h2, l2); bsplit(v.w, h3, l3);
    reinterpret_cast<__nv_bfloat162*>(h)[off2 + 2*i]   = __halves2bfloat162(h0, h1);
    reinterpret_cast<__nv_bfloat162*>(h)[off2 + 2*i+1] = __halves2bfloat162(h2, h3);
    reinterpret_cast<__nv_bfloat162*>(l)[off2 + 2*i]   = __floats2bfloat162_rn(l0, l1);
    reinterpret_cast<__nv_bfloat162*>(l)[off2 + 2*i+1] = __floats2bfloat162_rn(l2, l3);
}

// ---------------------------------------------------------------------------
// bf16x3 GEMM (mma.sync), 3-stage cp.async pipeline, ONE barrier per iter.
// (unchanged from R9 — validated)
// ---------------------------------------------------------------------------
#define HST 24
#define ABYTES (128*HST*2)     // 6144 per array
#define GSTG  (4*ABYTES)       // 24576 per stage
#define GSMEM (3*GSTG)         // 73728

template<int MODE>
__global__ __launch_bounds__(256, 2)
void gemm_bf(const __nv_bfloat16* __restrict__ Ah, const __nv_bfloat16* __restrict__ Al,
             const __nv_bfloat16* __restrict__ Whb, const __nv_bfloat16* __restrict__ Wlb,
             const float* __restrict__ b0p, const float* __restrict__ b1p,
             const float* __restrict__ b2p,
             __nv_bfloat16* __restrict__ ChB, __nv_bfloat16* __restrict__ ClB,
             float* __restrict__ outF)
{
    extern __shared__ __align__(16) char gsm[];
    const unsigned sbase = s2u(gsm);

    const int z = blockIdx.z;
    const size_t woff = (size_t)((MODE == 0) ? z : 3) * DM * DM;
    const float* bias = (z == 0) ? b0p : ((z == 1) ? b1p : b2p);

    const int tid  = threadIdx.x;
    const int lane = tid & 31;
    const int wid  = tid >> 5;
    const int m0 = blockIdx.y * 128;
    const int n0 = blockIdx.x * 128;
    const int wm = wid >> 2;
    const int wn = wid & 3;
    const int g  = lane >> 2;
    const int c  = lane & 3;

    const int rowA_ = (lane & 7) + ((lane >> 3) & 1) * 8;
    const int colA_ = (lane >> 4) * 8;
    const int rowB_ = (lane & 7) + ((lane >> 4) & 1) * 8;
    const int colB_ = ((lane >> 3) & 1) * 8;

    const bool isA = tid < 128;
    const int lrow = tid & 127;
    const __nv_bfloat16* ph = (isA ? Ah + (size_t)(m0 + lrow) * DM
                                   : Whb + woff + (size_t)(n0 + lrow) * DM);
    const __nv_bfloat16* pl = (isA ? Al + (size_t)(m0 + lrow) * DM
                                   : Wlb + woff + (size_t)(n0 + lrow) * DM);

    const int arrH = isA ? 0 : 2;
    const unsigned sH = (unsigned)(arrH * ABYTES + lrow * (HST * 2));
    const unsigned sL = sH + ABYTES;

    float acc[4][4][4];
    #pragma unroll
    for (int i = 0; i < 4; i++)
        #pragma unroll
        for (int j = 0; j < 4; j++)
            #pragma unroll
            for (int r = 0; r < 4; r++) acc[i][j][r] = 0.f;

    auto issueG = [&](int itx, int st) {
        const int k0 = itx * 16;
        const unsigned sb = sbase + (unsigned)st * GSTG;
        cp16(sb + sH,      ph + k0);  cp16(sb + sH + 16, ph + k0 + 8);
        cp16(sb + sL,      pl + k0);  cp16(sb + sL + 16, pl + k0 + 8);
    };

    issueG(0, 0); cp_commit();
    issueG(1, 1); cp_commit();

    #pragma unroll 1
    for (int it = 0; it < 48; ++it) {
        const int s = it % 3;
        if (it == 47) { cp_wait<0>(); } else { cp_wait<1>(); }
        __syncthreads();
        if (it + 2 < 48) { issueG(it + 2, (it + 2) % 3); cp_commit(); }

        const unsigned bufo = sbase + (unsigned)s * GSTG;
        unsigned bh[4][2], bl[4][2];
        #pragma unroll
        for (int ntp = 0; ntp < 2; ++ntp) {
            unsigned r[4];
            const int rb = wn * 32 + ntp * 16 + rowB_;
            ldm4(r, bufo + 2u * ABYTES + (unsigned)((rb * HST + colB_) * 2));
            bh[ntp*2][0] = r[0]; bh[ntp*2][1] = r[1];
            bh[ntp*2+1][0] = r[2]; bh[ntp*2+1][1] = r[3];
            ldm4(r, bufo + 3u * ABYTES + (unsigned)((rb * HST + colB_) * 2));
            bl[ntp*2][0] = r[0]; bl[ntp*2][1] = r[1];
            bl[ntp*2+1][0] = r[2]; bl[ntp*2+1][1] = r[3];
        }
        #pragma unroll
        for (int mi = 0; mi < 4; ++mi) {
            const int ra = wm * 64 + mi * 16 + rowA_;
            unsigned ah[4], al[4];
            ldm4(ah, bufo + (unsigned)((ra * HST + colA_) * 2));
            ldm4(al, bufo + 1u * ABYTES + (unsigned)((ra * HST + colA_) * 2));
            #pragma unroll
            for (int ni = 0; ni < 4; ++ni) {
                mma16(acc[mi][ni], ah[0], ah[1], ah[2], ah[3], bh[ni][0], bh[ni][1]);
                mma16(acc[mi][ni], ah[0], ah[1], ah[2], ah[3], bl[ni][0], bl[ni][1]);
                mma16(acc[mi][ni], al[0], al[1], al[2], al[3], bh[ni][0], bh[ni][1]);
            }
        }
    }

    __nv_bfloat16* Ch = (MODE == 0) ? (ChB + (size_t)z * ZSZ) : nullptr;
    __nv_bfloat16* Cl = (MODE == 0) ? (ClB + (size_t)z * ZSZ) : nullptr;
    #pragma unroll
    for (int mi = 0; mi < 4; ++mi) {
        const int row = m0 + wm * 64 + mi * 16 + g;
        #pragma unroll
        for (int ni = 0; ni < 4; ++ni) {
            const int col = n0 + wn * 32 + ni * 8 + c * 2;
            float2 bv = *(const float2*)(bias + col);
            float v0 = acc[mi][ni][0] + bv.x;
            float v1 = acc[mi][ni][1] + bv.y;
            float v2 = acc[mi][ni][2] + bv.x;
            float v3 = acc[mi][ni][3] + bv.y;
            if (MODE == 0) {
                const int bb = row >> 11;
                const int t  = row & 2047;
                const int hd = col >> 6;
                const int d  = col & 63;
                const size_t a0 = ((size_t)(bb * NH + hd) * TT + t) * DH + d;
                __nv_bfloat16 h0, h1; float l0, l1;
                bsplit(v0, h0, l0); bsplit(v1, h1, l1);
                *(__nv_bfloat162*)(Ch + a0) = __halves2bfloat162(h0, h1);
                *(__nv_bfloat162*)(Cl + a0) = __floats2bfloat162_rn(l0, l1);
                bsplit(v2, h0, l0); bsplit(v3, h1, l1);
                *(__nv_bfloat162*)(Ch + a0 + 8 * DH) = __halves2bfloat162(h0, h1);
                *(__nv_bfloat162*)(Cl + a0 + 8 * DH) = __floats2bfloat162_rn(l0, l1);
            } else {
                *(float2*)(outF + (size_t)row * DM + col)       = make_float2(v0, v1);
                *(float2*)(outF + (size_t)(row + 8) * DM + col) = make_float2(v2, v3);
            }
        }
    }
}

// ---------------------------------------------------------------------------
// Flash attention, bf16x3 (math identical to R9). Br=128, Bc=64, 8 warps.
// PERSISTENT: grid=296 (2 CTAs/SM), snake-balanced items sorted by cost.
// 3-stage cp.async staging, one barrier per iteration. split2 packing.
// ---------------------------------------------------------------------------
#define AKVS 72
#define AARR 9216                  // 64 * 72 * 2 bytes
#define ASTG (4*AARR)              // Kh,Kl,Vh,Vl = 36864
#define A_KH 0
#define A_KL AARR
#define A_VH (2*AARR)
#define A_VL (3*AARR)
#define ASMEM (3*ASTG)             // 110592
#define APERS 296
#define AITEMS 768                 // 16 q-blocks * 48 bh

__global__ __launch_bounds__(256, 2)
void attn_bf(float* __restrict__ dummy)
{
    extern __shared__ __align__(16) char asmz[];
    const unsigned uS = s2u(asmz);

    const int tid  = threadIdx.x;
    const int lane = tid & 31;
    const int wid  = tid >> 5;       // 0..7
    const int g  = lane >> 2;
    const int c  = lane & 3;
    const int kblk = blockIdx.x;     // 0..295

    const int rowB_ = (lane & 7) + ((lane >> 4) & 1) * 8;
    const int colB_ = ((lane >> 3) & 1) * 8;
    const int vkey_ = lane & 15;
    const int vd_   = (lane >> 4) * 8;

    const float SC = 0.125f * 1.4426950408889634f;

    #pragma unroll 1
    for (int p = 0; p < 3; ++p) {
        const int j = p * APERS + ((p & 1) ? (APERS - 1 - kblk) : kblk);
        if (j >= AITEMS) continue;
        const int qb = 15 - (j / 48);    // descending cost order
        const int bh = j % 48;

        // ---- Q fragments ----
        const __nv_bfloat16* qhp = g_h3 + ((size_t)bh * TT + qb * 128 + wid * 16) * DH;
        const __nv_bfloat16* qlp = g_l3 + ((size_t)bh * TT + qb * 128 + wid * 16) * DH;
        unsigned qfh[4][4], qfl[4][4];
        #pragma unroll
        for (int kc = 0; kc < 4; ++kc) {
            #pragma unroll
            for (int jj = 0; jj < 4; ++jj) {
                const int row = g + (jj & 1) * 8;
                const int col = kc * 16 + 2 * c + (jj >> 1) * 8;
                __nv_bfloat162 hh = *(const __nv_bfloat162*)(qhp + (size_t)row * DH + col);
                __nv_bfloat162 ll = *(const __nv_bfloat162*)(qlp + (size_t)row * DH + col);
                float x0 = (__bfloat162float(hh.x) + __bfloat162float(ll.x)) * SC;
                float x1 = (__bfloat162float(hh.y) + __bfloat162float(ll.y)) * SC;
                split2(x0, x1, qfh[kc][jj], qfl[kc][jj]);
            }
        }

        float o[8][4];
        #pragma unroll
        for (int i = 0; i < 8; ++i)
            #pragma unroll
            for (int jj = 0; jj < 4; ++jj) o[i][jj] = 0.f;
        float m_lo = -1e30f, m_hi = -1e30f, l_lo = 0.f, l_hi = 0.f;

        const __nv_bfloat16* kh_b = g_h3 + ZSZ     + (size_t)bh * TT * DH;
        const __nv_bfloat16* kl_b = g_l3 + ZSZ     + (size_t)bh * TT * DH;
        const __nv_bfloat16* vh_b = g_h3 + 2 * ZSZ + (size_t)bh * TT * DH;
        const __nv_bfloat16* vl_b = g_l3 + 2 * ZSZ + (size_t)bh * TT * DH;

        const int row_lo = qb * 128 + wid * 16 + g;
        const int row_hi = row_lo + 8;
        const int nkb = 2 * qb + 2;

        auto issue = [&](int kb, int st) {
            const unsigned sb = uS + (unsigned)st * ASTG;
            const size_t t0 = (size_t)kb * 64 * DH;
            #pragma unroll
            for (int i = 0; i < 2; ++i) {
                const int ch  = tid + i * 256;
                const int row = ch >> 3;
                const int seg = ch & 7;
                const unsigned ro = (unsigned)(row * (AKVS * 2) + seg * 16);
                const size_t go = t0 + (size_t)ch * 8;
                cp16(sb + A_KH + ro, kh_b + go);
                cp16(sb + A_KL + ro, kl_b + go);
                cp16(sb + A_VH + ro, vh_b + go);
                cp16(sb + A_VL + ro, vl_b + go);
            }
        };

        issue(0, 0); cp_commit();
        issue(1, 1); cp_commit();

        #pragma unroll 1
        for (int kb = 0; kb < nkb; ++kb) {
            const int s = kb % 3;
            if (kb == nkb - 1) { cp_wait<0>(); } else { cp_wait<1>(); }
            __syncthreads();
            if (kb + 2 < nkb) { issue(kb + 2, (kb + 2) % 3); cp_commit(); }

            const unsigned sk = uS + (unsigned)s * ASTG;

            // ---- S = Q K^T (bf16x3) ----
            float sx[8][4];
            #pragma unroll
            for (int i = 0; i < 8; ++i)
                #pragma unroll
                for (int jj = 0; jj < 4; ++jj) sx[i][jj] = 0.f;

            #pragma unroll
            for (int kc = 0; kc < 4; ++kc) {
                #pragma unroll
                for (int ntp = 0; ntp < 4; ++ntp) {
                    const unsigned off = (unsigned)(((ntp * 16 + rowB_) * AKVS + kc * 16 + colB_) * 2);
                    unsigned rh[4], rl[4];
                    ldm4(rh, sk + A_KH + off);
                    ldm4(rl, sk + A_KL + off);
                    float* s0 = sx[ntp * 2];
                    float* s1 = sx[ntp * 2 + 1];
                    mma16(s0, qfh[kc][0], qfh[kc][1], qfh[kc][2], qfh[kc][3], rh[0], rh[1]);
                    mma16(s0, qfh[kc][0], qfh[kc][1], qfh[kc][2], qfh[kc][3], rl[0], rl[1]);
                    mma16(s0, qfl[kc][0], qfl[kc][1], qfl[kc][2], qfl[kc][3], rh[0], rh[1]);
                    mma16(s1, qfh[kc][0], qfh[kc][1], qfh[kc][2], qfh[kc][3], rh[2], rh[3]);
                    mma16(s1, qfh[kc][0], qfh[kc][1], qfh[kc][2], qfh[kc][3], rl[2], rl[3]);
                    mma16(s1, qfl[kc][0], qfl[kc][1], qfl[kc][2], qfl[kc][3], rh[2], rh[3]);
                }
            }

            // ---- causal mask ----
            if (kb * 64 + 63 > qb * 128 + wid * 16) {
                #pragma unroll
                for (int nt = 0; nt < 8; ++nt) {
                    const int k0 = kb * 64 + nt * 8 + c * 2;
                    if (k0 > row_lo)     sx[nt][0] = -1e30f;
                    if (k0 + 1 > row_lo) sx[nt][1] = -1e30f;
                    if (k0 > row_hi)     sx[nt][2] = -1e30f;
                    if (k0 + 1 > row_hi) sx[nt][3] = -1e30f;
                }
            }

            // ---- online softmax (log2 domain) ----
            {
                float mx = -1e30f;
                #pragma unroll
                for (int nt = 0; nt < 8; ++nt) mx = fmaxf(mx, fmaxf(sx[nt][0], sx[nt][1]));
                mx = fmaxf(mx, __shfl_xor_sync(0xffffffffu, mx, 1));
                mx = fmaxf(mx, __shfl_xor_sync(0xffffffffu, mx, 2));
                const float mn = fmaxf(m_lo, mx);
                const float al = ex2(m_lo - mn);
                m_lo = mn;
                float ls = 0.f;
                #pragma unroll
                for (int nt = 0; nt < 8; ++nt) {
                    sx[nt][0] = ex2(sx[nt][0] - mn); ls += sx[nt][0];
                    sx[nt][1] = ex2(sx[nt][1] - mn); ls += sx[nt][1];
                    o[nt][0] *= al; o[nt][1] *= al;
                }
                l_lo = l_lo * al + ls;
            }
            {
                float mx = -1e30f;
                #pragma unroll
                for (int nt = 0; nt < 8; ++nt) mx = fmaxf(mx, fmaxf(sx[nt][2], sx[nt][3]));
                mx = fmaxf(mx, __shfl_xor_sync(0xffffffffu, mx, 1));
                mx = fmaxf(mx, __shfl_xor_sync(0xffffffffu, mx, 2));
                const float mn = fmaxf(m_hi, mx);
                const float al = ex2(m_hi - mn);
                m_hi = mn;
                float ls = 0.f;
                #pragma unroll
                for (int nt = 0; nt < 8; ++nt) {
                    sx[nt][2] = ex2(sx[nt][2] - mn); ls += sx[nt][2];
                    sx[nt][3] = ex2(sx[nt][3] - mn); ls += sx[nt][3];
                    o[nt][2] *= al; o[nt][3] *= al;
                }
                l_hi = l_hi * al + ls;
            }

            // ---- O += P V (bf16x3; split2 pack; V frags via ldmatrix.trans) ----
            #pragma unroll
            for (int kc = 0; kc < 4; ++kc) {
                unsigned ah0, ah1, ah2, ah3, al0, al1, al2, al3;
                split2(sx[2*kc][0],   sx[2*kc][1],   ah0, al0);
                split2(sx[2*kc][2],   sx[2*kc][3],   ah1, al1);
                split2(sx[2*kc+1][0], sx[2*kc+1][1], ah2, al2);
                split2(sx[2*kc+1][2], sx[2*kc+1][3], ah3, al3);
                #pragma unroll
                for (int ntp = 0; ntp < 4; ++ntp) {
                    const unsigned off =
                        (unsigned)(((kc * 16 + vkey_) * AKVS + ntp * 16 + vd_) * 2);
                    unsigned vh[4], vl[4];
                    ldm4t(vh, sk + A_VH + off);
                    ldm4t(vl, sk + A_VL + off);
                    float* o0 = o[ntp * 2];
                    float* o1 = o[ntp * 2 + 1];
                    mma16(o0, ah0, ah1, ah2, ah3, vh[0], vh[1]);
                    mma16(o0, ah0, ah1, ah2, ah3, vl[0], vl[1]);
                    mma16(o0, al0, al1, al2, al3, vh[0], vh[1]);
                    mma16(o1, ah0, ah1, ah2, ah3, vh[2], vh[3]);
                    mma16(o1, ah0, ah1, ah2, ah3, vl[2], vl[3]);
                    mma16(o1, al0, al1, al2, al3, vh[2], vh[3]);
                }
            }
        }

        // ---- epilogue ----
        l_lo += __shfl_xor_sync(0xffffffffu, l_lo, 1);
        l_lo += __shfl_xor_sync(0xffffffffu, l_lo, 2);
        l_hi += __shfl_xor_sync(0xffffffffu, l_hi, 1);
        l_hi += __shfl_xor_sync(0xffffffffu, l_hi, 2);
        const float inv_lo = 1.f / l_lo;
        const float inv_hi = 1.f / l_hi;

        const int bbv = bh / NH;
        const int hd  = bh % NH;
        const size_t alo = ((size_t)bbv * TT + row_lo) * DM + hd * DH + 2 * c;
        const size_t ahi = ((size_t)bbv * TT + row_hi) * DM + hd * DH + 2 * c;
        #pragma unroll
        for (int nt = 0; nt < 8; ++nt) {
            unsigned h2, l2;
            split2(o[nt][0] * inv_lo, o[nt][1] * inv_lo, h2, l2);
            *(unsigned*)(g_yh + alo + nt * 8) = h2;
            *(unsigned*)(g_yl + alo + nt * 8) = l2;
            split2(o[nt][2] * inv_hi, o[nt][3] * inv_hi, h2, l2);
            *(unsigned*)(g_yh + ahi + nt * 8) = h2;
            *(unsigned*)(g_yl + ahi + nt * 8) = l2;
        }

        __syncthreads();   // protect smem stages before next item's prologue
    }
    (void)dummy;
}

// ---------------------------------------------------------------------------
extern "C" void kernel_launch(void* const* d_in, const int* in_sizes, int n_in,
                              void* d_out, int out_size)
{
    const float* x  = (const float*)d_in[0];
    const float* Wq = (const float*)d_in[1];
    const float* bq = (const float*)d_in[2];
    const float* Wk = (const float*)d_in[3];
    const float* bk = (const float*)d_in[4];
    const float* Wv = (const float*)d_in[5];
    const float* bv = (const float*)d_in[6];
    const float* Wp = (const float*)d_in[7];
    const float* bp = (const float*)d_in[8];
    float* out = (float*)d_out;

    __nv_bfloat16 *xh, *xl, *wh, *wl, *h3, *l3, *yh, *yl;
    cudaGetSymbolAddress((void**)&xh, g_xh);
    cudaGetSymbolAddress((void**)&xl, g_xl);
    cudaGetSymbolAddress((void**)&wh, g_wh);
    cudaGetSymbolAddress((void**)&wl, g_wl);
    cudaGetSymbolAddress((void**)&h3, g_h3);
    cudaGetSymbolAddress((void**)&l3, g_l3);
    cudaGetSymbolAddress((void**)&yh, g_yh);
    cudaGetSymbolAddress((void**)&yl, g_yl);

    cudaFuncSetAttribute(gemm_bf<0>, cudaFuncAttributeMaxDynamicSharedMemorySize, GSMEM);
    cudaFuncSetAttribute(gemm_bf<1>, cudaFuncAttributeMaxDynamicSharedMemorySize, GSMEM);
    cudaFuncSetAttribute(attn_bf, cudaFuncAttributeMaxDynamicSharedMemorySize, ASMEM);

    // pre-pass conversions
    const int n4x = MROWS * DM / 4;
    const int n4w = DM * DM / 4;
    convert_split<<<(n4x + 255) / 256, 256>>>(x, xh, xl, n4x);
    dim3 wgrid((n4w + 255) / 256, 4);
    convert_w4<<<wgrid, 256>>>(Wq, Wk, Wv, Wp, wh, wl, n4w);

    // QKV (merged, permuted bf16 hi/lo out)
    dim3 qkv_grid(DM / 128, MROWS / 128, 3);
    gemm_bf<0><<<qkv_grid, 256, GSMEM>>>(xh, xl, wh, wl, bq, bk, bv, h3, l3, nullptr);

    // attention (persistent, load-balanced)
    attn_bf<<<APERS, 256, ASMEM>>>(nullptr);

    // out-proj (fp32 out)
    dim3 proj_grid(DM / 128, MROWS / 128, 1);
    gemm_bf<1><<<proj_grid, 256, GSMEM>>>(yh, yl, wh, wl, bp, bp, bp, nullptr, nullptr, out);
}

// round 11
// speedup vs baseline: 4.3472x; 1.0446x over previous
#include <cuda_runtime.h>
#include <cuda_bf16.h>
#include <cuda_fp16.h>
#include <math.h>

#define DM 768
#define NH 12
#define DH 64
#define BB 4
#define TT 2048
#define MROWS (BB*TT)   // 8192
#define ZSZ ((size_t)BB*NH*TT*DH)   // per-tensor q/k/v elems

// ---------------- scratch (device globals; no allocation allowed) ----------
__device__ __nv_bfloat16 g_xh[(size_t)MROWS*DM], g_xl[(size_t)MROWS*DM];
__device__ __nv_bfloat16 g_wh[4*(size_t)DM*DM], g_wl[4*(size_t)DM*DM];
__device__ __nv_bfloat16 g_h3[3*ZSZ], g_l3[3*ZSZ];      // q,k bf16 hi/lo; v fp16 hi/lo (raw 16-bit)
__device__ __nv_bfloat16 g_yh[(size_t)MROWS*DM], g_yl[(size_t)MROWS*DM];

// ---------------- helpers --------------------------------------------------
__device__ __forceinline__ float ex2(float x) {
    float r; asm("ex2.approx.f32 %0, %1;" : "=f"(r) : "f"(x)); return r;
}
__device__ __forceinline__ unsigned ex2h2(unsigned x) {
    unsigned r; asm("ex2.approx.f16x2 %0, %1;" : "=r"(r) : "r"(x)); return r;
}
// bf16 m16n8k16
__device__ __forceinline__ void mma16(float d[4],
                                      unsigned a0, unsigned a1, unsigned a2, unsigned a3,
                                      unsigned b0, unsigned b1) {
    asm volatile(
        "mma.sync.aligned.m16n8k16.row.col.f32.bf16.bf16.f32 "
        "{%0,%1,%2,%3}, {%4,%5,%6,%7}, {%8,%9}, {%0,%1,%2,%3};\n"
        : "+f"(d[0]), "+f"(d[1]), "+f"(d[2]), "+f"(d[3])
        : "r"(a0), "r"(a1), "r"(a2), "r"(a3), "r"(b0), "r"(b1));
}
// fp16 m16n8k16
__device__ __forceinline__ void mma16h(float d[4],
                                       unsigned a0, unsigned a1, unsigned a2, unsigned a3,
                                       unsigned b0, unsigned b1) {
    asm volatile(
        "mma.sync.aligned.m16n8k16.row.col.f32.f16.f16.f32 "
        "{%0,%1,%2,%3}, {%4,%5,%6,%7}, {%8,%9}, {%0,%1,%2,%3};\n"
        : "+f"(d[0]), "+f"(d[1]), "+f"(d[2]), "+f"(d[3])
        : "r"(a0), "r"(a1), "r"(a2), "r"(a3), "r"(b0), "r"(b1));
}
__device__ __forceinline__ void ldm4(unsigned r[4], unsigned addr) {
    asm volatile("ldmatrix.sync.aligned.m8n8.x4.shared.b16 {%0,%1,%2,%3}, [%4];"
                 : "=r"(r[0]), "=r"(r[1]), "=r"(r[2]), "=r"(r[3]) : "r"(addr));
}
__device__ __forceinline__ void ldm4t(unsigned r[4], unsigned addr) {
    asm volatile("ldmatrix.sync.aligned.m8n8.x4.trans.shared.b16 {%0,%1,%2,%3}, [%4];"
                 : "=r"(r[0]), "=r"(r[1]), "=r"(r[2]), "=r"(r[3]) : "r"(addr));
}
__device__ __forceinline__ unsigned s2u(const void* p) {
    return (unsigned)__cvta_generic_to_shared(p);
}
__device__ __forceinline__ void cp16(unsigned saddr, const void* gptr) {
    asm volatile("cp.async.cg.shared.global [%0], [%1], 16;"
                 :: "r"(saddr), "l"(gptr) : "memory");
}
__device__ __forceinline__ void cp_commit() {
    asm volatile("cp.async.commit_group;" ::: "memory");
}
template<int N>
__device__ __forceinline__ void cp_wait() {
    asm volatile("cp.async.wait_group %0;" :: "n"(N) : "memory");
}
__device__ __forceinline__ void bsplit(float x, __nv_bfloat16& h, float& l) {
    h = __float2bfloat16(x);
    l = x - __bfloat162float(h);
}
// bf16 pair split (bit-identical to bsplit+pack)
__device__ __forceinline__ void split2(float x0, float x1, unsigned& h2, unsigned& l2) {
    __nv_bfloat162 t = __floats2bfloat162_rn(x0, x1);
    h2 = *reinterpret_cast<unsigned*>(&t);
    const float f0 = __uint_as_float(h2 << 16);
    const float f1 = __uint_as_float(h2 & 0xFFFF0000u);
    __nv_bfloat162 tl = __floats2bfloat162_rn(x0 - f0, x1 - f1);
    l2 = *reinterpret_cast<unsigned*>(&tl);
}
// fp16 pair split
__device__ __forceinline__ void split2h(float x0, float x1, unsigned& h2, unsigned& l2) {
    __half2 t = __floats2half2_rn(x0, x1);
    h2 = *reinterpret_cast<unsigned*>(&t);
    const float f0 = __half2float(__low2half(t));
    const float f1 = __half2float(__high2half(t));
    __half2 tl = __floats2half2_rn(x0 - f0, x1 - f1);
    l2 = *reinterpret_cast<unsigned*>(&tl);
}

// ---------------- pre-pass: fp32 -> bf16 hi/lo -----------------------------
__global__ void convert_split(const float* __restrict__ src,
                              __nv_bfloat16* __restrict__ h,
                              __nv_bfloat16* __restrict__ l, int n4)
{
    int i = blockIdx.x * blockDim.x + threadIdx.x;
    if (i >= n4) return;
    float4 v = reinterpret_cast<const float4*>(src)[i];
    __nv_bfloat16 h0, h1, h2, h3; float l0, l1, l2, l3;
    bsplit(v.x, h0, l0); bsplit(v.y, h1, l1);
    bsplit(v.z, h2, l2); bsplit(v.w, h3, l3);
    reinterpret_cast<__nv_bfloat162*>(h)[2*i]   = __halves2bfloat162(h0, h1);
    reinterpret_cast<__nv_bfloat162*>(h)[2*i+1] = __halves2bfloat162(h2, h3);
    reinterpret_cast<__nv_bfloat162*>(l)[2*i]   = __floats2bfloat162_rn(l0, l1);
    reinterpret_cast<__nv_bfloat162*>(l)[2*i+1] = __floats2bfloat162_rn(l2, l3);
}
// all 4 weight matrices in one launch (blockIdx.y selects matrix)
__global__ void convert_w4(const float* __restrict__ s0, const float* __restrict__ s1,
                           const float* __restrict__ s2, const float* __restrict__ s3,
                           __nv_bfloat16* __restrict__ h, __nv_bfloat16* __restrict__ l,
                           int n4)
{
    int i = blockIdx.x * blockDim.x + threadIdx.x;
    if (i >= n4) return;
    const int z = blockIdx.y;
    const float* src = (z == 0) ? s0 : ((z == 1) ? s1 : ((z == 2) ? s2 : s3));
    const size_t off2 = (size_t)z * (DM * DM / 2);   // in bf16x2 units
    float4 v = reinterpret_cast<const float4*>(src)[i];
    __nv_bfloat16 h0, h1, h2, h3; float l0, l1, l2, l3;
    bsplit(v.x, h0, l0); bsplit(v.y, h1, l1);
    bsplit(v.z, h2, l2); bsplit(v.w, h3, l3);
    reinterpret_cast<__nv_bfloat162*>(h)[off2 + 2*i]   = __halves2bfloat162(h0, h1);
    reinterpret_cast<__nv_bfloat162*>(h)[off2 + 2*i+1] = __halves2bfloat162(h2, h3);
    reinterpret_cast<__nv_bfloat162*>(l)[off2 + 2*i]   = __floats2bfloat162_rn(l0, l1);
    reinterpret_cast<__nv_bfloat162*>(l)[off2 + 2*i+1] = __floats2bfloat162_rn(l2, l3);
}

// ---------------------------------------------------------------------------
// bf16x3 GEMM (mma.sync), 3-stage cp.async pipeline, ONE barrier per iter.
// MODE 0: QKV (z 0..2; q,k stored bf16 hi/lo; V stored fp16 hi/lo).
// MODE 1: proj (fp32 out).
// ---------------------------------------------------------------------------
#define HST 24
#define ABYTES (128*HST*2)     // 6144 per array
#define GSTG  (4*ABYTES)       // 24576 per stage
#define GSMEM (3*GSTG)         // 73728

template<int MODE>
__global__ __launch_bounds__(256, 2)
void gemm_bf(const __nv_bfloat16* __restrict__ Ah, const __nv_bfloat16* __restrict__ Al,
             const __nv_bfloat16* __restrict__ Whb, const __nv_bfloat16* __restrict__ Wlb,
             const float* __restrict__ b0p, const float* __restrict__ b1p,
             const float* __restrict__ b2p,
             __nv_bfloat16* __restrict__ ChB, __nv_bfloat16* __restrict__ ClB,
             float* __restrict__ outF)
{
    extern __shared__ __align__(16) char gsm[];
    const unsigned sbase = s2u(gsm);

    const int z = blockIdx.z;
    const size_t woff = (size_t)((MODE == 0) ? z : 3) * DM * DM;
    const float* bias = (z == 0) ? b0p : ((z == 1) ? b1p : b2p);

    const int tid  = threadIdx.x;
    const int lane = tid & 31;
    const int wid  = tid >> 5;
    const int m0 = blockIdx.y * 128;
    const int n0 = blockIdx.x * 128;
    const int wm = wid >> 2;
    const int wn = wid & 3;
    const int g  = lane >> 2;
    const int c  = lane & 3;

    const int rowA_ = (lane & 7) + ((lane >> 3) & 1) * 8;
    const int colA_ = (lane >> 4) * 8;
    const int rowB_ = (lane & 7) + ((lane >> 4) & 1) * 8;
    const int colB_ = ((lane >> 3) & 1) * 8;

    const bool isA = tid < 128;
    const int lrow = tid & 127;
    const __nv_bfloat16* ph = (isA ? Ah + (size_t)(m0 + lrow) * DM
                                   : Whb + woff + (size_t)(n0 + lrow) * DM);
    const __nv_bfloat16* pl = (isA ? Al + (size_t)(m0 + lrow) * DM
                                   : Wlb + woff + (size_t)(n0 + lrow) * DM);

    const int arrH = isA ? 0 : 2;
    const unsigned sH = (unsigned)(arrH * ABYTES + lrow * (HST * 2));
    const unsigned sL = sH + ABYTES;

    float acc[4][4][4];
    #pragma unroll
    for (int i = 0; i < 4; i++)
        #pragma unroll
        for (int j = 0; j < 4; j++)
            #pragma unroll
            for (int r = 0; r < 4; r++) acc[i][j][r] = 0.f;

    auto issueG = [&](int itx, int st) {
        const int k0 = itx * 16;
        const unsigned sb = sbase + (unsigned)st * GSTG;
        cp16(sb + sH,      ph + k0);  cp16(sb + sH + 16, ph + k0 + 8);
        cp16(sb + sL,      pl + k0);  cp16(sb + sL + 16, pl + k0 + 8);
    };

    issueG(0, 0); cp_commit();
    issueG(1, 1); cp_commit();

    #pragma unroll 1
    for (int it = 0; it < 48; ++it) {
        const int s = it % 3;
        if (it == 47) { cp_wait<0>(); } else { cp_wait<1>(); }
        __syncthreads();
        if (it + 2 < 48) { issueG(it + 2, (it + 2) % 3); cp_commit(); }

        const unsigned bufo = sbase + (unsigned)s * GSTG;
        unsigned bh[4][2], bl[4][2];
        #pragma unroll
        for (int ntp = 0; ntp < 2; ++ntp) {
            unsigned r[4];
            const int rb = wn * 32 + ntp * 16 + rowB_;
            ldm4(r, bufo + 2u * ABYTES + (unsigned)((rb * HST + colB_) * 2));
            bh[ntp*2][0] = r[0]; bh[ntp*2][1] = r[1];
            bh[ntp*2+1][0] = r[2]; bh[ntp*2+1][1] = r[3];
            ldm4(r, bufo + 3u * ABYTES + (unsigned)((rb * HST + colB_) * 2));
            bl[ntp*2][0] = r[0]; bl[ntp*2][1] = r[1];
            bl[ntp*2+1][0] = r[2]; bl[ntp*2+1][1] = r[3];
        }
        #pragma unroll
        for (int mi = 0; mi < 4; ++mi) {
            const int ra = wm * 64 + mi * 16 + rowA_;
            unsigned ah[4], al[4];
            ldm4(ah, bufo + (unsigned)((ra * HST + colA_) * 2));
            ldm4(al, bufo + 1u * ABYTES + (unsigned)((ra * HST + colA_) * 2));
            #pragma unroll
            for (int ni = 0; ni < 4; ++ni) {
                mma16(acc[mi][ni], ah[0], ah[1], ah[2], ah[3], bh[ni][0], bh[ni][1]);
                mma16(acc[mi][ni], ah[0], ah[1], ah[2], ah[3], bl[ni][0], bl[ni][1]);
                mma16(acc[mi][ni], al[0], al[1], al[2], al[3], bh[ni][0], bh[ni][1]);
            }
        }
    }

    __nv_bfloat16* Ch = (MODE == 0) ? (ChB + (size_t)z * ZSZ) : nullptr;
    __nv_bfloat16* Cl = (MODE == 0) ? (ClB + (size_t)z * ZSZ) : nullptr;
    #pragma unroll
    for (int mi = 0; mi < 4; ++mi) {
        const int row = m0 + wm * 64 + mi * 16 + g;
        #pragma unroll
        for (int ni = 0; ni < 4; ++ni) {
            const int col = n0 + wn * 32 + ni * 8 + c * 2;
            float2 bv = *(const float2*)(bias + col);
            float v0 = acc[mi][ni][0] + bv.x;
            float v1 = acc[mi][ni][1] + bv.y;
            float v2 = acc[mi][ni][2] + bv.x;
            float v3 = acc[mi][ni][3] + bv.y;
            if (MODE == 0) {
                const int bb = row >> 11;
                const int t  = row & 2047;
                const int hd = col >> 6;
                const int d  = col & 63;
                const size_t a0 = ((size_t)(bb * NH + hd) * TT + t) * DH + d;
                unsigned h2, l2;
                if (z == 2) {   // V -> fp16 hi/lo
                    split2h(v0, v1, h2, l2);
                    *(unsigned*)(Ch + a0) = h2;
                    *(unsigned*)(Cl + a0) = l2;
                    split2h(v2, v3, h2, l2);
                    *(unsigned*)(Ch + a0 + 8 * DH) = h2;
                    *(unsigned*)(Cl + a0 + 8 * DH) = l2;
                } else {        // Q,K -> bf16 hi/lo
                    split2(v0, v1, h2, l2);
                    *(unsigned*)(Ch + a0) = h2;
                    *(unsigned*)(Cl + a0) = l2;
                    split2(v2, v3, h2, l2);
                    *(unsigned*)(Ch + a0 + 8 * DH) = h2;
                    *(unsigned*)(Cl + a0 + 8 * DH) = l2;
                }
            } else {
                *(float2*)(outF + (size_t)row * DM + col)       = make_float2(v0, v1);
                *(float2*)(outF + (size_t)(row + 8) * DM + col) = make_float2(v2, v3);
            }
        }
    }
}

// ---------------------------------------------------------------------------
// Flash attention. QK^T bf16x3 (unchanged). Softmax: ex2.approx.f16x2.
// PV: P(fp16, = ex2 output regs) x V(fp16 hi/lo) = 2 mma. Persistent snake.
// ---------------------------------------------------------------------------
#define AKVS 72
#define AARR 9216                  // 64 * 72 * 2 bytes
#define ASTG (4*AARR)              // Kh,Kl,Vh,Vl = 36864
#define A_KH 0
#define A_KL AARR
#define A_VH (2*AARR)
#define A_VL (3*AARR)
#define ASMEM (3*ASTG)             // 110592
#define APERS 296
#define AITEMS 768                 // 16 q-blocks * 48 bh

__global__ __launch_bounds__(256, 2)
void attn_bf(float* __restrict__ dummy)
{
    extern __shared__ __align__(16) char asmz[];
    const unsigned uS = s2u(asmz);

    const int tid  = threadIdx.x;
    const int lane = tid & 31;
    const int wid  = tid >> 5;       // 0..7
    const int g  = lane >> 2;
    const int c  = lane & 3;
    const int kblk = blockIdx.x;     // 0..295

    const int rowB_ = (lane & 7) + ((lane >> 4) & 1) * 8;
    const int colB_ = ((lane >> 3) & 1) * 8;
    const int vkey_ = lane & 15;
    const int vd_   = (lane >> 4) * 8;

    const float SC = 0.125f * 1.4426950408889634f;

    #pragma unroll 1
    for (int p = 0; p < 3; ++p) {
        const int j = p * APERS + ((p & 1) ? (APERS - 1 - kblk) : kblk);
        if (j >= AITEMS) continue;
        const int qb = 15 - (j / 48);    // descending cost order
        const int bh = j % 48;

        // ---- Q fragments (bf16x3, unchanged) ----
        const __nv_bfloat16* qhp = g_h3 + ((size_t)bh * TT + qb * 128 + wid * 16) * DH;
        const __nv_bfloat16* qlp = g_l3 + ((size_t)bh * TT + qb * 128 + wid * 16) * DH;
        unsigned qfh[4][4], qfl[4][4];
        #pragma unroll
        for (int kc = 0; kc < 4; ++kc) {
            #pragma unroll
            for (int jj = 0; jj < 4; ++jj) {
                const int row = g + (jj & 1) * 8;
                const int col = kc * 16 + 2 * c + (jj >> 1) * 8;
                __nv_bfloat162 hh = *(const __nv_bfloat162*)(qhp + (size_t)row * DH + col);
                __nv_bfloat162 ll = *(const __nv_bfloat162*)(qlp + (size_t)row * DH + col);
                float x0 = (__bfloat162float(hh.x) + __bfloat162float(ll.x)) * SC;
                float x1 = (__bfloat162float(hh.y) + __bfloat162float(ll.y)) * SC;
                split2(x0, x1, qfh[kc][jj], qfl[kc][jj]);
            }
        }

        float o[8][4];
        #pragma unroll
        for (int i = 0; i < 8; ++i)
            #pragma unroll
            for (int jj = 0; jj < 4; ++jj) o[i][jj] = 0.f;
        float m_lo = -1e30f, m_hi = -1e30f, l_lo = 0.f, l_hi = 0.f;

        const __nv_bfloat16* kh_b = g_h3 + ZSZ     + (size_t)bh * TT * DH;
        const __nv_bfloat16* kl_b = g_l3 + ZSZ     + (size_t)bh * TT * DH;
        const __nv_bfloat16* vh_b = g_h3 + 2 * ZSZ + (size_t)bh * TT * DH;  // fp16 bits
        const __nv_bfloat16* vl_b = g_l3 + 2 * ZSZ + (size_t)bh * TT * DH;  // fp16 bits

        const int row_lo = qb * 128 + wid * 16 + g;
        const int row_hi = row_lo + 8;
        const int nkb = 2 * qb + 2;

        auto issue = [&](int kb, int st) {
            const unsigned sb = uS + (unsigned)st * ASTG;
            const size_t t0 = (size_t)kb * 64 * DH;
            #pragma unroll
            for (int i = 0; i < 2; ++i) {
                const int ch  = tid + i * 256;
                const int row = ch >> 3;
                const int seg = ch & 7;
                const unsigned ro = (unsigned)(row * (AKVS * 2) + seg * 16);
                const size_t go = t0 + (size_t)ch * 8;
                cp16(sb + A_KH + ro, kh_b + go);
                cp16(sb + A_KL + ro, kl_b + go);
                cp16(sb + A_VH + ro, vh_b + go);
                cp16(sb + A_VL + ro, vl_b + go);
            }
        };

        issue(0, 0); cp_commit();
        issue(1, 1); cp_commit();

        #pragma unroll 1
        for (int kb = 0; kb < nkb; ++kb) {
            const int s = kb % 3;
            if (kb == nkb - 1) { cp_wait<0>(); } else { cp_wait<1>(); }
            __syncthreads();
            if (kb + 2 < nkb) { issue(kb + 2, (kb + 2) % 3); cp_commit(); }

            const unsigned sk = uS + (unsigned)s * ASTG;

            // ---- S = Q K^T (bf16x3) ----
            float sx[8][4];
            #pragma unroll
            for (int i = 0; i < 8; ++i)
                #pragma unroll
                for (int jj = 0; jj < 4; ++jj) sx[i][jj] = 0.f;

            #pragma unroll
            for (int kc = 0; kc < 4; ++kc) {
                #pragma unroll
                for (int ntp = 0; ntp < 4; ++ntp) {
                    const unsigned off = (unsigned)(((ntp * 16 + rowB_) * AKVS + kc * 16 + colB_) * 2);
                    unsigned rh[4], rl[4];
                    ldm4(rh, sk + A_KH + off);
                    ldm4(rl, sk + A_KL + off);
                    float* s0 = sx[ntp * 2];
                    float* s1 = sx[ntp * 2 + 1];
                    mma16(s0, qfh[kc][0], qfh[kc][1], qfh[kc][2], qfh[kc][3], rh[0], rh[1]);
                    mma16(s0, qfh[kc][0], qfh[kc][1], qfh[kc][2], qfh[kc][3], rl[0], rl[1]);
                    mma16(s0, qfl[kc][0], qfl[kc][1], qfl[kc][2], qfl[kc][3], rh[0], rh[1]);
                    mma16(s1, qfh[kc][0], qfh[kc][1], qfh[kc][2], qfh[kc][3], rh[2], rh[3]);
                    mma16(s1, qfh[kc][0], qfh[kc][1], qfh[kc][2], qfh[kc][3], rl[2], rl[3]);
                    mma16(s1, qfl[kc][0], qfl[kc][1], qfl[kc][2], qfl[kc][3], rh[2], rh[3]);
                }
            }

            // ---- causal mask ----
            if (kb * 64 + 63 > qb * 128 + wid * 16) {
                #pragma unroll
                for (int nt = 0; nt < 8; ++nt) {
                    const int k0 = kb * 64 + nt * 8 + c * 2;
                    if (k0 > row_lo)     sx[nt][0] = -1e30f;
                    if (k0 + 1 > row_lo) sx[nt][1] = -1e30f;
                    if (k0 > row_hi)     sx[nt][2] = -1e30f;
                    if (k0 + 1 > row_hi) sx[nt][3] = -1e30f;
                }
            }

            // ---- online softmax (log2 domain; p via ex2.approx.f16x2) ----
            float mx0 = -1e30f, mx1 = -1e30f;
            #pragma unroll
            for (int nt = 0; nt < 8; ++nt) {
                mx0 = fmaxf(mx0, fmaxf(sx[nt][0], sx[nt][1]));
                mx1 = fmaxf(mx1, fmaxf(sx[nt][2], sx[nt][3]));
            }
            mx0 = fmaxf(mx0, __shfl_xor_sync(0xffffffffu, mx0, 1));
            mx0 = fmaxf(mx0, __shfl_xor_sync(0xffffffffu, mx0, 2));
            mx1 = fmaxf(mx1, __shfl_xor_sync(0xffffffffu, mx1, 1));
            mx1 = fmaxf(mx1, __shfl_xor_sync(0xffffffffu, mx1, 2));
            const float mn0 = fmaxf(m_lo, mx0);
            const float al0 = ex2(m_lo - mn0);
            m_lo = mn0;
            const float mn1 = fmaxf(m_hi, mx1);
            const float al1 = ex2(m_hi - mn1);
            m_hi = mn1;

            unsigned pl2[8], ph2[8];
            float ls0 = 0.f, ls1 = 0.f;
            #pragma unroll
            for (int nt = 0; nt < 8; ++nt) {
                __half2 t0 = __floats2half2_rn(sx[nt][0] - mn0, sx[nt][1] - mn0);
                pl2[nt] = ex2h2(*reinterpret_cast<unsigned*>(&t0));
                __half2 t1 = __floats2half2_rn(sx[nt][2] - mn1, sx[nt][3] - mn1);
                ph2[nt] = ex2h2(*reinterpret_cast<unsigned*>(&t1));
                float2 f0 = __half22float2(*reinterpret_cast<__half2*>(&pl2[nt]));
                ls0 += f0.x + f0.y;
                float2 f1 = __half22float2(*reinterpret_cast<__half2*>(&ph2[nt]));
                ls1 += f1.x + f1.y;
                o[nt][0] *= al0; o[nt][1] *= al0;
                o[nt][2] *= al1; o[nt][3] *= al1;
            }
            l_lo = l_lo * al0 + ls0;
            l_hi = l_hi * al1 + ls1;

            // ---- O += P V (fp16 P x fp16 V hi/lo; 2 mma per frag) ----
            #pragma unroll
            for (int kc = 0; kc < 4; ++kc) {
                const unsigned a0 = pl2[2*kc];
                const unsigned a1 = ph2[2*kc];
                const unsigned a2 = pl2[2*kc+1];
                const unsigned a3 = ph2[2*kc+1];
                #pragma unroll
                for (int ntp = 0; ntp < 4; ++ntp) {
                    const unsigned off =
                        (unsigned)(((kc * 16 + vkey_) * AKVS + ntp * 16 + vd_) * 2);
                    unsigned vh[4], vl[4];
                    ldm4t(vh, sk + A_VH + off);
                    ldm4t(vl, sk + A_VL + off);
                    float* o0 = o[ntp * 2];
                    float* o1 = o[ntp * 2 + 1];
                    mma16h(o0, a0, a1, a2, a3, vh[0], vh[1]);
                    mma16h(o0, a0, a1, a2, a3, vl[0], vl[1]);
                    mma16h(o1, a0, a1, a2, a3, vh[2], vh[3]);
                    mma16h(o1, a0, a1, a2, a3, vl[2], vl[3]);
                }
            }
        }

        // ---- epilogue ----
        l_lo += __shfl_xor_sync(0xffffffffu, l_lo, 1);
        l_lo += __shfl_xor_sync(0xffffffffu, l_lo, 2);
        l_hi += __shfl_xor_sync(0xffffffffu, l_hi, 1);
        l_hi += __shfl_xor_sync(0xffffffffu, l_hi, 2);
        const float inv_lo = 1.f / l_lo;
        const float inv_hi = 1.f / l_hi;

        const int bbv = bh / NH;
        const int hd  = bh % NH;
        const size_t alo = ((size_t)bbv * TT + row_lo) * DM + hd * DH + 2 * c;
        const size_t ahi = ((size_t)bbv * TT + row_hi) * DM + hd * DH + 2 * c;
        #pragma unroll
        for (int nt = 0; nt < 8; ++nt) {
            unsigned h2, l2;
            split2(o[nt][0] * inv_lo, o[nt][1] * inv_lo, h2, l2);
            *(unsigned*)(g_yh + alo + nt * 8) = h2;
            *(unsigned*)(g_yl + alo + nt * 8) = l2;
            split2(o[nt][2] * inv_hi, o[nt][3] * inv_hi, h2, l2);
            *(unsigned*)(g_yh + ahi + nt * 8) = h2;
            *(unsigned*)(g_yl + ahi + nt * 8) = l2;
        }

        __syncthreads();   // protect smem stages before next item's prologue
    }
    (void)dummy;
}

// ---------------------------------------------------------------------------
extern "C" void kernel_launch(void* const* d_in, const int* in_sizes, int n_in,
                              void* d_out, int out_size)
{
    const float* x  = (const float*)d_in[0];
    const float* Wq = (const float*)d_in[1];
    const float* bq = (const float*)d_in[2];
    const float* Wk = (const float*)d_in[3];
    const float* bk = (const float*)d_in[4];
    const float* Wv = (const float*)d_in[5];
    const float* bv = (const float*)d_in[6];
    const float* Wp = (const float*)d_in[7];
    const float* bp = (const float*)d_in[8];
    float* out = (float*)d_out;

    __nv_bfloat16 *xh, *xl, *wh, *wl, *h3, *l3, *yh, *yl;
    cudaGetSymbolAddress((void**)&xh, g_xh);
    cudaGetSymbolAddress((void**)&xl, g_xl);
    cudaGetSymbolAddress((void**)&wh, g_wh);
    cudaGetSymbolAddress((void**)&wl, g_wl);
    cudaGetSymbolAddress((void**)&h3, g_h3);
    cudaGetSymbolAddress((void**)&l3, g_l3);
    cudaGetSymbolAddress((void**)&yh, g_yh);
    cudaGetSymbolAddress((void**)&yl, g_yl);

    cudaFuncSetAttribute(gemm_bf<0>, cudaFuncAttributeMaxDynamicSharedMemorySize, GSMEM);
    cudaFuncSetAttribute(gemm_bf<1>, cudaFuncAttributeMaxDynamicSharedMemorySize, GSMEM);
    cudaFuncSetAttribute(attn_bf, cudaFuncAttributeMaxDynamicSharedMemorySize, ASMEM);

    // pre-pass conversions
    const int n4x = MROWS * DM / 4;
    const int n4w = DM * DM / 4;
    convert_split<<<(n4x + 255) / 256, 256>>>(x, xh, xl, n4x);
    dim3 wgrid((n4w + 255) / 256, 4);
    convert_w4<<<wgrid, 256>>>(Wq, Wk, Wv, Wp, wh, wl, n4w);

    // QKV (merged; q,k bf16 hi/lo; v fp16 hi/lo)
    dim3 qkv_grid(DM / 128, MROWS / 128, 3);
    gemm_bf<0><<<qkv_grid, 256, GSMEM>>>(xh, xl, wh, wl, bq, bk, bv, h3, l3, nullptr);

    // attention (persistent, load-balanced)
    attn_bf<<<APERS, 256, ASMEM>>>(nullptr);

    // out-proj (fp32 out)
    dim3 proj_grid(DM / 128, MROWS / 128, 1);
    gemm_bf<1><<<proj_grid, 256, GSMEM>>>(yh, yl, wh, wl, bp, bp, bp, nullptr, nullptr, out);
}

// round 12
// speedup vs baseline: 4.9173x; 1.1312x over previous
#include <cuda_runtime.h>
#include <cuda_bf16.h>
#include <cuda_fp16.h>
#include <math.h>

#define DM 768
#define NH 12
#define DH 64
#define BB 4
#define TT 2048
#define MROWS (BB*TT)   // 8192
#define ZSZ ((size_t)BB*NH*TT*DH)   // per-tensor q/k/v elems

// ---------------- scratch (device globals; no allocation allowed) ----------
__device__ __nv_bfloat16 g_xh[(size_t)MROWS*DM], g_xl[(size_t)MROWS*DM];
__device__ __nv_bfloat16 g_wh[4*(size_t)DM*DM], g_wl[4*(size_t)DM*DM];
__device__ __nv_bfloat16 g_h3[3*ZSZ], g_l3[3*ZSZ];  // q,k fp16 (hi only); v fp16 hi/lo
__device__ __nv_bfloat16 g_yh[(size_t)MROWS*DM], g_yl[(size_t)MROWS*DM];

// ---------------- helpers --------------------------------------------------
__device__ __forceinline__ float ex2(float x) {
    float r; asm("ex2.approx.f32 %0, %1;" : "=f"(r) : "f"(x)); return r;
}
__device__ __forceinline__ unsigned ex2h2(unsigned x) {
    unsigned r; asm("ex2.approx.f16x2 %0, %1;" : "=r"(r) : "r"(x)); return r;
}
// bf16 m16n8k16
__device__ __forceinline__ void mma16(float d[4],
                                      unsigned a0, unsigned a1, unsigned a2, unsigned a3,
                                      unsigned b0, unsigned b1) {
    asm volatile(
        "mma.sync.aligned.m16n8k16.row.col.f32.bf16.bf16.f32 "
        "{%0,%1,%2,%3}, {%4,%5,%6,%7}, {%8,%9}, {%0,%1,%2,%3};\n"
        : "+f"(d[0]), "+f"(d[1]), "+f"(d[2]), "+f"(d[3])
        : "r"(a0), "r"(a1), "r"(a2), "r"(a3), "r"(b0), "r"(b1));
}
// fp16 m16n8k16
__device__ __forceinline__ void mma16h(float d[4],
                                       unsigned a0, unsigned a1, unsigned a2, unsigned a3,
                                       unsigned b0, unsigned b1) {
    asm volatile(
        "mma.sync.aligned.m16n8k16.row.col.f32.f16.f16.f32 "
        "{%0,%1,%2,%3}, {%4,%5,%6,%7}, {%8,%9}, {%0,%1,%2,%3};\n"
        : "+f"(d[0]), "+f"(d[1]), "+f"(d[2]), "+f"(d[3])
        : "r"(a0), "r"(a1), "r"(a2), "r"(a3), "r"(b0), "r"(b1));
}
__device__ __forceinline__ void ldm4(unsigned r[4], unsigned addr) {
    asm volatile("ldmatrix.sync.aligned.m8n8.x4.shared.b16 {%0,%1,%2,%3}, [%4];"
                 : "=r"(r[0]), "=r"(r[1]), "=r"(r[2]), "=r"(r[3]) : "r"(addr));
}
__device__ __forceinline__ void ldm4t(unsigned r[4], unsigned addr) {
    asm volatile("ldmatrix.sync.aligned.m8n8.x4.trans.shared.b16 {%0,%1,%2,%3}, [%4];"
                 : "=r"(r[0]), "=r"(r[1]), "=r"(r[2]), "=r"(r[3]) : "r"(addr));
}
__device__ __forceinline__ unsigned s2u(const void* p) {
    return (unsigned)__cvta_generic_to_shared(p);
}
__device__ __forceinline__ void cp16(unsigned saddr, const void* gptr) {
    asm volatile("cp.async.cg.shared.global [%0], [%1], 16;"
                 :: "r"(saddr), "l"(gptr) : "memory");
}
__device__ __forceinline__ void cp_commit() {
    asm volatile("cp.async.commit_group;" ::: "memory");
}
template<int N>
__device__ __forceinline__ void cp_wait() {
    asm volatile("cp.async.wait_group %0;" :: "n"(N) : "memory");
}
__device__ __forceinline__ void bsplit(float x, __nv_bfloat16& h, float& l) {
    h = __float2bfloat16(x);
    l = x - __bfloat162float(h);
}
// bf16 pair split (bit-identical to bsplit+pack)
__device__ __forceinline__ void split2(float x0, float x1, unsigned& h2, unsigned& l2) {
    __nv_bfloat162 t = __floats2bfloat162_rn(x0, x1);
    h2 = *reinterpret_cast<unsigned*>(&t);
    const float f0 = __uint_as_float(h2 << 16);
    const float f1 = __uint_as_float(h2 & 0xFFFF0000u);
    __nv_bfloat162 tl = __floats2bfloat162_rn(x0 - f0, x1 - f1);
    l2 = *reinterpret_cast<unsigned*>(&tl);
}
// fp16 pair split
__device__ __forceinline__ void split2h(float x0, float x1, unsigned& h2, unsigned& l2) {
    __half2 t = __floats2half2_rn(x0, x1);
    h2 = *reinterpret_cast<unsigned*>(&t);
    const float f0 = __half2float(__low2half(t));
    const float f1 = __half2float(__high2half(t));
    __half2 tl = __floats2half2_rn(x0 - f0, x1 - f1);
    l2 = *reinterpret_cast<unsigned*>(&tl);
}

// ---------------- pre-pass: fp32 -> bf16 hi/lo -----------------------------
__global__ void convert_split(const float* __restrict__ src,
                              __nv_bfloat16* __restrict__ h,
                              __nv_bfloat16* __restrict__ l, int n4)
{
    int i = blockIdx.x * blockDim.x + threadIdx.x;
    if (i >= n4) return;
    float4 v = reinterpret_cast<const float4*>(src)[i];
    __nv_bfloat16 h0, h1, h2, h3; float l0, l1, l2, l3;
    bsplit(v.x, h0, l0); bsplit(v.y, h1, l1);
    bsplit(v.z, h2, l2); bsplit(v.w, h3, l3);
    reinterpret_cast<__nv_bfloat162*>(h)[2*i]   = __halves2bfloat162(h0, h1);
    reinterpret_cast<__nv_bfloat162*>(h)[2*i+1] = __halves2bfloat162(h2, h3);
    reinterpret_cast<__nv_bfloat162*>(l)[2*i]   = __floats2bfloat162_rn(l0, l1);
    reinterpret_cast<__nv_bfloat162*>(l)[2*i+1] = __floats2bfloat162_rn(l2, l3);
}
// all 4 weight matrices in one launch (blockIdx.y selects matrix)
__global__ void convert_w4(const float* __restrict__ s0, const float* __restrict__ s1,
                           const float* __restrict__ s2, const float* __restrict__ s3,
                           __nv_bfloat16* __restrict__ h, __nv_bfloat16* __restrict__ l,
                           int n4)
{
    int i = blockIdx.x * blockDim.x + threadIdx.x;
    if (i >= n4) return;
    const int z = blockIdx.y;
    const float* src = (z == 0) ? s0 : ((z == 1) ? s1 : ((z == 2) ? s2 : s3));
    const size_t off2 = (size_t)z * (DM * DM / 2);   // in bf16x2 units
    float4 v = reinterpret_cast<const float4*>(src)[i];
    __nv_bfloat16 h0, h1, h2, h3; float l0, l1, l2, l3;
    bsplit(v.x, h0, l0); bsplit(v.y, h1, l1);
    bsplit(v.z, h2, l2); bsplit(v.w, h3, l3);
    reinterpret_cast<__nv_bfloat162*>(h)[off2 + 2*i]   = __halves2bfloat162(h0, h1);
    reinterpret_cast<__nv_bfloat162*>(h)[off2 + 2*i+1] = __halves2bfloat162(h2, h3);
    reinterpret_cast<__nv_bfloat162*>(l)[off2 + 2*i]   = __floats2bfloat162_rn(l0, l1);
    reinterpret_cast<__nv_bfloat162*>(l)[off2 + 2*i+1] = __floats2bfloat162_rn(l2, l3);
}

// ---------------------------------------------------------------------------
// bf16x3 GEMM (mma.sync), 3-stage cp.async pipeline, ONE barrier per iter.
// MODE 0: QKV. z=0: Q -> fp16 single, PRE-SCALED by 0.125*log2e. z=1: K -> fp16
// single. z=2: V -> fp16 hi/lo. MODE 1: proj (fp32 out).
// ---------------------------------------------------------------------------
#define HST 24
#define ABYTES (128*HST*2)     // 6144 per array
#define GSTG  (4*ABYTES)       // 24576 per stage
#define GSMEM (3*GSTG)         // 73728
#define QSCALE (0.125f * 1.4426950408889634f)

template<int MODE>
__global__ __launch_bounds__(256, 2)
void gemm_bf(const __nv_bfloat16* __restrict__ Ah, const __nv_bfloat16* __restrict__ Al,
             const __nv_bfloat16* __restrict__ Whb, const __nv_bfloat16* __restrict__ Wlb,
             const float* __restrict__ b0p, const float* __restrict__ b1p,
             const float* __restrict__ b2p,
             __nv_bfloat16* __restrict__ ChB, __nv_bfloat16* __restrict__ ClB,
             float* __restrict__ outF)
{
    extern __shared__ __align__(16) char gsm[];
    const unsigned sbase = s2u(gsm);

    const int z = blockIdx.z;
    const size_t woff = (size_t)((MODE == 0) ? z : 3) * DM * DM;
    const float* bias = (z == 0) ? b0p : ((z == 1) ? b1p : b2p);

    const int tid  = threadIdx.x;
    const int lane = tid & 31;
    const int wid  = tid >> 5;
    const int m0 = blockIdx.y * 128;
    const int n0 = blockIdx.x * 128;
    const int wm = wid >> 2;
    const int wn = wid & 3;
    const int g  = lane >> 2;
    const int c  = lane & 3;

    const int rowA_ = (lane & 7) + ((lane >> 3) & 1) * 8;
    const int colA_ = (lane >> 4) * 8;
    const int rowB_ = (lane & 7) + ((lane >> 4) & 1) * 8;
    const int colB_ = ((lane >> 3) & 1) * 8;

    const bool isA = tid < 128;
    const int lrow = tid & 127;
    const __nv_bfloat16* ph = (isA ? Ah + (size_t)(m0 + lrow) * DM
                                   : Whb + woff + (size_t)(n0 + lrow) * DM);
    const __nv_bfloat16* pl = (isA ? Al + (size_t)(m0 + lrow) * DM
                                   : Wlb + woff + (size_t)(n0 + lrow) * DM);

    const int arrH = isA ? 0 : 2;
    const unsigned sH = (unsigned)(arrH * ABYTES + lrow * (HST * 2));
    const unsigned sL = sH + ABYTES;

    float acc[4][4][4];
    #pragma unroll
    for (int i = 0; i < 4; i++)
        #pragma unroll
        for (int j = 0; j < 4; j++)
            #pragma unroll
            for (int r = 0; r < 4; r++) acc[i][j][r] = 0.f;

    auto issueG = [&](int itx, int st) {
        const int k0 = itx * 16;
        const unsigned sb = sbase + (unsigned)st * GSTG;
        cp16(sb + sH,      ph + k0);  cp16(sb + sH + 16, ph + k0 + 8);
        cp16(sb + sL,      pl + k0);  cp16(sb + sL + 16, pl + k0 + 8);
    };

    issueG(0, 0); cp_commit();
    issueG(1, 1); cp_commit();

    #pragma unroll 1
    for (int it = 0; it < 48; ++it) {
        const int s = it % 3;
        if (it == 47) { cp_wait<0>(); } else { cp_wait<1>(); }
        __syncthreads();
        if (it + 2 < 48) { issueG(it + 2, (it + 2) % 3); cp_commit(); }

        const unsigned bufo = sbase + (unsigned)s * GSTG;
        unsigned bh[4][2], bl[4][2];
        #pragma unroll
        for (int ntp = 0; ntp < 2; ++ntp) {
            unsigned r[4];
            const int rb = wn * 32 + ntp * 16 + rowB_;
            ldm4(r, bufo + 2u * ABYTES + (unsigned)((rb * HST + colB_) * 2));
            bh[ntp*2][0] = r[0]; bh[ntp*2][1] = r[1];
            bh[ntp*2+1][0] = r[2]; bh[ntp*2+1][1] = r[3];
            ldm4(r, bufo + 3u * ABYTES + (unsigned)((rb * HST + colB_) * 2));
            bl[ntp*2][0] = r[0]; bl[ntp*2][1] = r[1];
            bl[ntp*2+1][0] = r[2]; bl[ntp*2+1][1] = r[3];
        }
        #pragma unroll
        for (int mi = 0; mi < 4; ++mi) {
            const int ra = wm * 64 + mi * 16 + rowA_;
            unsigned ah[4], al[4];
            ldm4(ah, bufo + (unsigned)((ra * HST + colA_) * 2));
            ldm4(al, bufo + 1u * ABYTES + (unsigned)((ra * HST + colA_) * 2));
            #pragma unroll
            for (int ni = 0; ni < 4; ++ni) {
                mma16(acc[mi][ni], ah[0], ah[1], ah[2], ah[3], bh[ni][0], bh[ni][1]);
                mma16(acc[mi][ni], ah[0], ah[1], ah[2], ah[3], bl[ni][0], bl[ni][1]);
                mma16(acc[mi][ni], al[0], al[1], al[2], al[3], bh[ni][0], bh[ni][1]);
            }
        }
    }

    __nv_bfloat16* Ch = (MODE == 0) ? (ChB + (size_t)z * ZSZ) : nullptr;
    __nv_bfloat16* Cl = (MODE == 0) ? (ClB + (size_t)z * ZSZ) : nullptr;
    #pragma unroll
    for (int mi = 0; mi < 4; ++mi) {
        const int row = m0 + wm * 64 + mi * 16 + g;
        #pragma unroll
        for (int ni = 0; ni < 4; ++ni) {
            const int col = n0 + wn * 32 + ni * 8 + c * 2;
            float2 bv = *(const float2*)(bias + col);
            float v0 = acc[mi][ni][0] + bv.x;
            float v1 = acc[mi][ni][1] + bv.y;
            float v2 = acc[mi][ni][2] + bv.x;
            float v3 = acc[mi][ni][3] + bv.y;
            if (MODE == 0) {
                const int bb = row >> 11;
                const int t  = row & 2047;
                const int hd = col >> 6;
                const int d  = col & 63;
                const size_t a0 = ((size_t)(bb * NH + hd) * TT + t) * DH + d;
                if (z == 2) {           // V -> fp16 hi/lo
                    unsigned h2, l2;
                    split2h(v0, v1, h2, l2);
                    *(unsigned*)(Ch + a0) = h2;
                    *(unsigned*)(Cl + a0) = l2;
                    split2h(v2, v3, h2, l2);
                    *(unsigned*)(Ch + a0 + 8 * DH) = h2;
                    *(unsigned*)(Cl + a0 + 8 * DH) = l2;
                } else {                // Q (pre-scaled) / K -> fp16 single
                    const float sc = (z == 0) ? QSCALE : 1.0f;
                    __half2 t0 = __floats2half2_rn(v0 * sc, v1 * sc);
                    __half2 t1 = __floats2half2_rn(v2 * sc, v3 * sc);
                    *(unsigned*)(Ch + a0)          = *reinterpret_cast<unsigned*>(&t0);
                    *(unsigned*)(Ch + a0 + 8 * DH) = *reinterpret_cast<unsigned*>(&t1);
                }
            } else {
                *(float2*)(outF + (size_t)row * DM + col)       = make_float2(v0, v1);
                *(float2*)(outF + (size_t)(row + 8) * DM + col) = make_float2(v2, v3);
            }
        }
    }
}

// ---------------------------------------------------------------------------
// Flash attention. QK^T: fp16 x1 (Q pre-scaled). Softmax: ex2.approx.f16x2;
// row sums via ones-column mma. PV: fp16 P x fp16 V hi/lo. Persistent snake.
// ---------------------------------------------------------------------------
#define AKVS 72
#define AARR 9216                  // 64 * 72 * 2 bytes
#define ASTG (3*AARR)              // Kh, Vh, Vl = 27648
#define A_KH 0
#define A_VH AARR
#define A_VL (2*AARR)
#define ASMEM (3*ASTG)             // 82944
#define APERS 296
#define AITEMS 768                 // 16 q-blocks * 48 bh
#define ONESH2 0x3C003C00u

__global__ __launch_bounds__(256, 2)
void attn_bf(float* __restrict__ dummy)
{
    extern __shared__ __align__(16) char asmz[];
    const unsigned uS = s2u(asmz);

    const int tid  = threadIdx.x;
    const int lane = tid & 31;
    const int wid  = tid >> 5;       // 0..7
    const int g  = lane >> 2;
    const int c  = lane & 3;
    const int kblk = blockIdx.x;     // 0..295

    const int rowB_ = (lane & 7) + ((lane >> 4) & 1) * 8;
    const int colB_ = ((lane >> 3) & 1) * 8;
    const int vkey_ = lane & 15;
    const int vd_   = (lane >> 4) * 8;

    #pragma unroll 1
    for (int p = 0; p < 3; ++p) {
        const int j = p * APERS + ((p & 1) ? (APERS - 1 - kblk) : kblk);
        if (j >= AITEMS) continue;
        const int qb = 15 - (j / 48);    // descending cost order
        const int bh = j % 48;

        // ---- Q fragments: raw fp16 bits, already scaled ----
        const unsigned short* qp =
            (const unsigned short*)g_h3 + ((size_t)bh * TT + qb * 128 + wid * 16) * DH;
        unsigned qf[4][4];
        #pragma unroll
        for (int kc = 0; kc < 4; ++kc) {
            #pragma unroll
            for (int jj = 0; jj < 4; ++jj) {
                const int row = g + (jj & 1) * 8;
                const int col = kc * 16 + 2 * c + (jj >> 1) * 8;
                qf[kc][jj] = *(const unsigned*)(qp + (size_t)row * DH + col);
            }
        }

        float o[8][4];
        #pragma unroll
        for (int i = 0; i < 8; ++i)
            #pragma unroll
            for (int jj = 0; jj < 4; ++jj) o[i][jj] = 0.f;
        float m_lo = -1e30f, m_hi = -1e30f, l_lo = 0.f, l_hi = 0.f;

        const __nv_bfloat16* kh_b = g_h3 + ZSZ     + (size_t)bh * TT * DH;  // fp16 bits
        const __nv_bfloat16* vh_b = g_h3 + 2 * ZSZ + (size_t)bh * TT * DH;  // fp16 bits
        const __nv_bfloat16* vl_b = g_l3 + 2 * ZSZ + (size_t)bh * TT * DH;  // fp16 bits

        const int row_lo = qb * 128 + wid * 16 + g;
        const int row_hi = row_lo + 8;
        const int nkb = 2 * qb + 2;

        auto issue = [&](int kb, int st) {
            const unsigned sb = uS + (unsigned)st * ASTG;
            const size_t t0 = (size_t)kb * 64 * DH;
            #pragma unroll
            for (int i = 0; i < 2; ++i) {
                const int ch  = tid + i * 256;
                const int row = ch >> 3;
                const int seg = ch & 7;
                const unsigned ro = (unsigned)(row * (AKVS * 2) + seg * 16);
                const size_t go = t0 + (size_t)ch * 8;
                cp16(sb + A_KH + ro, kh_b + go);
                cp16(sb + A_VH + ro, vh_b + go);
                cp16(sb + A_VL + ro, vl_b + go);
            }
        };

        issue(0, 0); cp_commit();
        issue(1, 1); cp_commit();

        #pragma unroll 1
        for (int kb = 0; kb < nkb; ++kb) {
            const int s = kb % 3;
            if (kb == nkb - 1) { cp_wait<0>(); } else { cp_wait<1>(); }
            __syncthreads();
            if (kb + 2 < nkb) { issue(kb + 2, (kb + 2) % 3); cp_commit(); }

            const unsigned sk = uS + (unsigned)s * ASTG;

            // ---- S = Q K^T (fp16 x1) ----
            float sx[8][4];
            #pragma unroll
            for (int i = 0; i < 8; ++i)
                #pragma unroll
                for (int jj = 0; jj < 4; ++jj) sx[i][jj] = 0.f;

            #pragma unroll
            for (int kc = 0; kc < 4; ++kc) {
                #pragma unroll
                for (int ntp = 0; ntp < 4; ++ntp) {
                    const unsigned off = (unsigned)(((ntp * 16 + rowB_) * AKVS + kc * 16 + colB_) * 2);
                    unsigned rh[4];
                    ldm4(rh, sk + A_KH + off);
                    mma16h(sx[ntp * 2],     qf[kc][0], qf[kc][1], qf[kc][2], qf[kc][3], rh[0], rh[1]);
                    mma16h(sx[ntp * 2 + 1], qf[kc][0], qf[kc][1], qf[kc][2], qf[kc][3], rh[2], rh[3]);
                }
            }

            // ---- causal mask ----
            if (kb * 64 + 63 > qb * 128 + wid * 16) {
                #pragma unroll
                for (int nt = 0; nt < 8; ++nt) {
                    const int k0 = kb * 64 + nt * 8 + c * 2;
                    if (k0 > row_lo)     sx[nt][0] = -1e30f;
                    if (k0 + 1 > row_lo) sx[nt][1] = -1e30f;
                    if (k0 > row_hi)     sx[nt][2] = -1e30f;
                    if (k0 + 1 > row_hi) sx[nt][3] = -1e30f;
                }
            }

            // ---- online softmax (log2 domain; p via ex2.approx.f16x2) ----
            float mx0 = -1e30f, mx1 = -1e30f;
            #pragma unroll
            for (int nt = 0; nt < 8; ++nt) {
                mx0 = fmaxf(mx0, fmaxf(sx[nt][0], sx[nt][1]));
                mx1 = fmaxf(mx1, fmaxf(sx[nt][2], sx[nt][3]));
            }
            mx0 = fmaxf(mx0, __shfl_xor_sync(0xffffffffu, mx0, 1));
            mx0 = fmaxf(mx0, __shfl_xor_sync(0xffffffffu, mx0, 2));
            mx1 = fmaxf(mx1, __shfl_xor_sync(0xffffffffu, mx1, 1));
            mx1 = fmaxf(mx1, __shfl_xor_sync(0xffffffffu, mx1, 2));
            const float mn0 = fmaxf(m_lo, mx0);
            const float al0 = ex2(m_lo - mn0);
            m_lo = mn0;
            const float mn1 = fmaxf(m_hi, mx1);
            const float al1 = ex2(m_hi - mn1);
            m_hi = mn1;

            unsigned pl2[8], ph2[8];
            #pragma unroll
            for (int nt = 0; nt < 8; ++nt) {
                __half2 t0 = __floats2half2_rn(sx[nt][0] - mn0, sx[nt][1] - mn0);
                pl2[nt] = ex2h2(*reinterpret_cast<unsigned*>(&t0));
                __half2 t1 = __floats2half2_rn(sx[nt][2] - mn1, sx[nt][3] - mn1);
                ph2[nt] = ex2h2(*reinterpret_cast<unsigned*>(&t1));
                o[nt][0] *= al0; o[nt][1] *= al0;
                o[nt][2] *= al1; o[nt][3] *= al1;
            }

            // ---- row sums via ones-column mma (exact f32 sum of f16 p) ----
            float ls4[4] = {0.f, 0.f, 0.f, 0.f};
            #pragma unroll
            for (int kc = 0; kc < 4; ++kc)
                mma16h(ls4, pl2[2*kc], ph2[2*kc], pl2[2*kc+1], ph2[2*kc+1], ONESH2, ONESH2);
            l_lo = l_lo * al0 + ls4[0];
            l_hi = l_hi * al1 + ls4[2];

            // ---- O += P V (fp16 P x fp16 V hi/lo) ----
            #pragma unroll
            for (int kc = 0; kc < 4; ++kc) {
                const unsigned a0 = pl2[2*kc];
                const unsigned a1 = ph2[2*kc];
                const unsigned a2 = pl2[2*kc+1];
                const unsigned a3 = ph2[2*kc+1];
                #pragma unroll
                for (int ntp = 0; ntp < 4; ++ntp) {
                    const unsigned off =
                        (unsigned)(((kc * 16 + vkey_) * AKVS + ntp * 16 + vd_) * 2);
                    unsigned vh[4], vl[4];
                    ldm4t(vh, sk + A_VH + off);
                    ldm4t(vl, sk + A_VL + off);
                    float* o0 = o[ntp * 2];
                    float* o1 = o[ntp * 2 + 1];
                    mma16h(o0, a0, a1, a2, a3, vh[0], vh[1]);
                    mma16h(o0, a0, a1, a2, a3, vl[0], vl[1]);
                    mma16h(o1, a0, a1, a2, a3, vh[2], vh[3]);
                    mma16h(o1, a0, a1, a2, a3, vl[2], vl[3]);
                }
            }
        }

        // ---- epilogue (l already full row sums — no shuffles) ----
        const float inv_lo = 1.f / l_lo;
        const float inv_hi = 1.f / l_hi;

        const int bbv = bh / NH;
        const int hd  = bh % NH;
        const size_t alo = ((size_t)bbv * TT + row_lo) * DM + hd * DH + 2 * c;
        const size_t ahi = ((size_t)bbv * TT + row_hi) * DM + hd * DH + 2 * c;
        #pragma unroll
        for (int nt = 0; nt < 8; ++nt) {
            unsigned h2, l2;
            split2(o[nt][0] * inv_lo, o[nt][1] * inv_lo, h2, l2);
            *(unsigned*)(g_yh + alo + nt * 8) = h2;
            *(unsigned*)(g_yl + alo + nt * 8) = l2;
            split2(o[nt][2] * inv_hi, o[nt][3] * inv_hi, h2, l2);
            *(unsigned*)(g_yh + ahi + nt * 8) = h2;
            *(unsigned*)(g_yl + ahi + nt * 8) = l2;
        }

        __syncthreads();   // protect smem stages before next item's prologue
    }
    (void)dummy;
}

// ---------------------------------------------------------------------------
extern "C" void kernel_launch(void* const* d_in, const int* in_sizes, int n_in,
                              void* d_out, int out_size)
{
    const float* x  = (const float*)d_in[0];
    const float* Wq = (const float*)d_in[1];
    const float* bq = (const float*)d_in[2];
    const float* Wk = (const float*)d_in[3];
    const float* bk = (const float*)d_in[4];
    const float* Wv = (const float*)d_in[5];
    const float* bv = (const float*)d_in[6];
    const float* Wp = (const float*)d_in[7];
    const float* bp = (const float*)d_in[8];
    float* out = (float*)d_out;

    __nv_bfloat16 *xh, *xl, *wh, *wl, *h3, *l3, *yh, *yl;
    cudaGetSymbolAddress((void**)&xh, g_xh);
    cudaGetSymbolAddress((void**)&xl, g_xl);
    cudaGetSymbolAddress((void**)&wh, g_wh);
    cudaGetSymbolAddress((void**)&wl, g_wl);
    cudaGetSymbolAddress((void**)&h3, g_h3);
    cudaGetSymbolAddress((void**)&l3, g_l3);
    cudaGetSymbolAddress((void**)&yh, g_yh);
    cudaGetSymbolAddress((void**)&yl, g_yl);

    cudaFuncSetAttribute(gemm_bf<0>, cudaFuncAttributeMaxDynamicSharedMemorySize, GSMEM);
    cudaFuncSetAttribute(gemm_bf<1>, cudaFuncAttributeMaxDynamicSharedMemorySize, GSMEM);
    cudaFuncSetAttribute(attn_bf, cudaFuncAttributeMaxDynamicSharedMemorySize, ASMEM);

    // pre-pass conversions
    const int n4x = MROWS * DM / 4;
    const int n4w = DM * DM / 4;
    convert_split<<<(n4x + 255) / 256, 256>>>(x, xh, xl, n4x);
    dim3 wgrid((n4w + 255) / 256, 4);
    convert_w4<<<wgrid, 256>>>(Wq, Wk, Wv, Wp, wh, wl, n4w);

    // QKV (merged; q,k fp16 single — q pre-scaled; v fp16 hi/lo)
    dim3 qkv_grid(DM / 128, MROWS / 128, 3);
    gemm_bf<0><<<qkv_grid, 256, GSMEM>>>(xh, xl, wh, wl, bq, bk, bv, h3, l3, nullptr);

    // attention (persistent, load-balanced)
    attn_bf<<<APERS, 256, ASMEM>>>(nullptr);

    // out-proj (fp32 out)
    dim3 proj_grid(DM / 128, MROWS / 128, 1);
    gemm_bf<1><<<proj_grid, 256, GSMEM>>>(yh, yl, wh, wl, bp, bp, bp, nullptr, nullptr, out);
}

// round 13
// speedup vs baseline: 6.2373x; 1.2684x over previous
#include <cuda_runtime.h>
#include <cuda_bf16.h>
#include <cuda_fp16.h>
#include <math.h>

#define DM 768
#define NH 12
#define DH 64
#define BB 4
#define TT 2048
#define MROWS (BB*TT)   // 8192
#define ZSZ ((size_t)BB*NH*TT*DH)   // per-tensor q/k/v elems

// ---------------- scratch (device globals; no allocation allowed) ----------
// all arrays hold raw fp16 bits
__device__ unsigned short g_xh[(size_t)MROWS*DM], g_xl[(size_t)MROWS*DM];
__device__ unsigned short g_wh[4*(size_t)DM*DM];
__device__ unsigned short g_h3[3*ZSZ], g_l3[3*ZSZ];  // q,k fp16 single; v fp16 hi/lo
__device__ unsigned short g_yh[(size_t)MROWS*DM], g_yl[(size_t)MROWS*DM];

// ---------------- helpers --------------------------------------------------
__device__ __forceinline__ float ex2(float x) {
    float r; asm("ex2.approx.f32 %0, %1;" : "=f"(r) : "f"(x)); return r;
}
__device__ __forceinline__ unsigned ex2h2(unsigned x) {
    unsigned r; asm("ex2.approx.f16x2 %0, %1;" : "=r"(r) : "r"(x)); return r;
}
// fp16 m16n8k16
__device__ __forceinline__ void mma16h(float d[4],
                                       unsigned a0, unsigned a1, unsigned a2, unsigned a3,
                                       unsigned b0, unsigned b1) {
    asm volatile(
        "mma.sync.aligned.m16n8k16.row.col.f32.f16.f16.f32 "
        "{%0,%1,%2,%3}, {%4,%5,%6,%7}, {%8,%9}, {%0,%1,%2,%3};\n"
        : "+f"(d[0]), "+f"(d[1]), "+f"(d[2]), "+f"(d[3])
        : "r"(a0), "r"(a1), "r"(a2), "r"(a3), "r"(b0), "r"(b1));
}
__device__ __forceinline__ void ldm4(unsigned r[4], unsigned addr) {
    asm volatile("ldmatrix.sync.aligned.m8n8.x4.shared.b16 {%0,%1,%2,%3}, [%4];"
                 : "=r"(r[0]), "=r"(r[1]), "=r"(r[2]), "=r"(r[3]) : "r"(addr));
}
__device__ __forceinline__ void ldm4t(unsigned r[4], unsigned addr) {
    asm volatile("ldmatrix.sync.aligned.m8n8.x4.trans.shared.b16 {%0,%1,%2,%3}, [%4];"
                 : "=r"(r[0]), "=r"(r[1]), "=r"(r[2]), "=r"(r[3]) : "r"(addr));
}
__device__ __forceinline__ unsigned s2u(const void* p) {
    return (unsigned)__cvta_generic_to_shared(p);
}
__device__ __forceinline__ void cp16(unsigned saddr, const void* gptr) {
    asm volatile("cp.async.cg.shared.global [%0], [%1], 16;"
                 :: "r"(saddr), "l"(gptr) : "memory");
}
__device__ __forceinline__ void cp_commit() {
    asm volatile("cp.async.commit_group;" ::: "memory");
}
template<int N>
__device__ __forceinline__ void cp_wait() {
    asm volatile("cp.async.wait_group %0;" :: "n"(N) : "memory");
}
// fp16 pair split
__device__ __forceinline__ void split2h(float x0, float x1, unsigned& h2, unsigned& l2) {
    __half2 t = __floats2half2_rn(x0, x1);
    h2 = *reinterpret_cast<unsigned*>(&t);
    const float f0 = __half2float(__low2half(t));
    const float f1 = __half2float(__high2half(t));
    __half2 tl = __floats2half2_rn(x0 - f0, x1 - f1);
    l2 = *reinterpret_cast<unsigned*>(&tl);
}
__device__ __forceinline__ unsigned packh2(float x0, float x1) {
    __half2 t = __floats2half2_rn(x0, x1);
    return *reinterpret_cast<unsigned*>(&t);
}

// ---------------- pre-pass converts ----------------------------------------
// x -> fp16 hi/lo
__global__ void convert_x(const float* __restrict__ src,
                          unsigned short* __restrict__ h,
                          unsigned short* __restrict__ l, int n4)
{
    int i = blockIdx.x * blockDim.x + threadIdx.x;
    if (i >= n4) return;
    float4 v = reinterpret_cast<const float4*>(src)[i];
    unsigned h0, l0, h1, l1;
    split2h(v.x, v.y, h0, l0);
    split2h(v.z, v.w, h1, l1);
    reinterpret_cast<unsigned*>(h)[2*i]   = h0;
    reinterpret_cast<unsigned*>(h)[2*i+1] = h1;
    reinterpret_cast<unsigned*>(l)[2*i]   = l0;
    reinterpret_cast<unsigned*>(l)[2*i+1] = l1;
}
// 4 weights -> fp16 single (blockIdx.y selects matrix)
__global__ void convert_w4(const float* __restrict__ s0, const float* __restrict__ s1,
                           const float* __restrict__ s2, const float* __restrict__ s3,
                           unsigned short* __restrict__ h, int n4)
{
    int i = blockIdx.x * blockDim.x + threadIdx.x;
    if (i >= n4) return;
    const int z = blockIdx.y;
    const float* src = (z == 0) ? s0 : ((z == 1) ? s1 : ((z == 2) ? s2 : s3));
    const size_t off2 = (size_t)z * (DM * DM / 2);
    float4 v = reinterpret_cast<const float4*>(src)[i];
    reinterpret_cast<unsigned*>(h)[off2 + 2*i]   = packh2(v.x, v.y);
    reinterpret_cast<unsigned*>(h)[off2 + 2*i+1] = packh2(v.z, v.w);
}

// ---------------------------------------------------------------------------
// fp16 GEMM (mma.sync), 3-stage cp.async, ONE barrier per iter. BM=BN=128 BK=16.
// A = fp16 hi/lo arrays; B = fp16 hi only.
// MODE 0 (QKV): z=0 -> V (2 mma, fp16 hi/lo out, heavy-first),
//               z=1 -> Q (1 mma, fp16 out * QSCALE), z=2 -> K (1 mma, fp16 out).
// MODE 1 (proj): 2 mma, fp32 out.
// ---------------------------------------------------------------------------
#define HST 24
#define ABYTES (128*HST*2)     // 6144 per array
#define GSTG  (3*ABYTES)       // 18432 per stage: Ah, Al, Bh
#define GSMEM (3*GSTG)         // 55296
#define QSCALE (0.125f * 1.4426950408889634f)

template<int MODE>
__global__ __launch_bounds__(256, 2)
void gemm_f16(const unsigned short* __restrict__ Ah, const unsigned short* __restrict__ Al,
              const unsigned short* __restrict__ Whb,
              const float* __restrict__ b0p, const float* __restrict__ b1p,
              const float* __restrict__ b2p,
              unsigned short* __restrict__ ChB, unsigned short* __restrict__ ClB,
              float* __restrict__ outF)
{
    extern __shared__ __align__(16) char gsm[];
    const unsigned sbase = s2u(gsm);

    const int z = blockIdx.z;
    // MODE 0: z=0->Wv(idx2), z=1->Wq(0), z=2->Wk(1). MODE 1: Wp(3).
    const int widx = (MODE == 1) ? 3 : ((z == 0) ? 2 : ((z == 1) ? 0 : 1));
    const size_t woff = (size_t)widx * DM * DM;
    const float* bias = (MODE == 1) ? b0p : ((z == 0) ? b2p : ((z == 1) ? b0p : b1p));
    const bool use_lo = (MODE == 1) || (z == 0);

    const int tid  = threadIdx.x;
    const int lane = tid & 31;
    const int wid  = tid >> 5;
    const int m0 = blockIdx.y * 128;
    const int n0 = blockIdx.x * 128;
    const int wm = wid >> 2;
    const int wn = wid & 3;
    const int g  = lane >> 2;
    const int c  = lane & 3;

    const int rowA_ = (lane & 7) + ((lane >> 3) & 1) * 8;
    const int colA_ = (lane >> 4) * 8;
    const int rowB_ = (lane & 7) + ((lane >> 4) & 1) * 8;
    const int colB_ = ((lane >> 3) & 1) * 8;

    const bool isA = tid < 128;
    const int lrow = tid & 127;
    const unsigned short* ph = (isA ? Ah + (size_t)(m0 + lrow) * DM
                                    : Whb + woff + (size_t)(n0 + lrow) * DM);
    const unsigned short* pl = Al + (size_t)(m0 + lrow) * DM;   // A threads only

    const unsigned sRow = (unsigned)((isA ? 0 : 2 * ABYTES) + lrow * (HST * 2));

    float acc[4][4][4];
    #pragma unroll
    for (int i = 0; i < 4; i++)
        #pragma unroll
        for (int j = 0; j < 4; j++)
            #pragma unroll
            for (int r = 0; r < 4; r++) acc[i][j][r] = 0.f;

    auto issueG = [&](int itx, int st) {
        const int k0 = itx * 16;
        const unsigned sb = sbase + (unsigned)st * GSTG;
        cp16(sb + sRow,      ph + k0);
        cp16(sb + sRow + 16, ph + k0 + 8);
        if (isA && use_lo) {
            cp16(sb + ABYTES + sRow,      pl + k0);
            cp16(sb + ABYTES + sRow + 16, pl + k0 + 8);
        }
    };

    issueG(0, 0); cp_commit();
    issueG(1, 1); cp_commit();

    #pragma unroll 1
    for (int it = 0; it < 48; ++it) {
        const int s = it % 3;
        if (it == 47) { cp_wait<0>(); } else { cp_wait<1>(); }
        __syncthreads();
        if (it + 2 < 48) { issueG(it + 2, (it + 2) % 3); cp_commit(); }

        const unsigned bufo = sbase + (unsigned)s * GSTG;
        unsigned bh[4][2];
        #pragma unroll
        for (int ntp = 0; ntp < 2; ++ntp) {
            unsigned r[4];
            const int rb = wn * 32 + ntp * 16 + rowB_;
            ldm4(r, bufo + 2u * ABYTES + (unsigned)((rb * HST + colB_) * 2));
            bh[ntp*2][0] = r[0]; bh[ntp*2][1] = r[1];
            bh[ntp*2+1][0] = r[2]; bh[ntp*2+1][1] = r[3];
        }
        #pragma unroll
        for (int mi = 0; mi < 4; ++mi) {
            const int ra = wm * 64 + mi * 16 + rowA_;
            unsigned ah[4];
            ldm4(ah, bufo + (unsigned)((ra * HST + colA_) * 2));
            #pragma unroll
            for (int ni = 0; ni < 4; ++ni)
                mma16h(acc[mi][ni], ah[0], ah[1], ah[2], ah[3], bh[ni][0], bh[ni][1]);
            if (use_lo) {
                unsigned al[4];
                ldm4(al, bufo + 1u * ABYTES + (unsigned)((ra * HST + colA_) * 2));
                #pragma unroll
                for (int ni = 0; ni < 4; ++ni)
                    mma16h(acc[mi][ni], al[0], al[1], al[2], al[3], bh[ni][0], bh[ni][1]);
            }
        }
    }

    // ---- epilogue ----
    const size_t zoff = (MODE == 0) ? ((z == 0) ? 2 * ZSZ : ((z == 1) ? 0 : ZSZ)) : 0;
    #pragma unroll
    for (int mi = 0; mi < 4; ++mi) {
        const int row = m0 + wm * 64 + mi * 16 + g;
        #pragma unroll
        for (int ni = 0; ni < 4; ++ni) {
            const int col = n0 + wn * 32 + ni * 8 + c * 2;
            float2 bv = *(const float2*)(bias + col);
            float v0 = acc[mi][ni][0] + bv.x;
            float v1 = acc[mi][ni][1] + bv.y;
            float v2 = acc[mi][ni][2] + bv.x;
            float v3 = acc[mi][ni][3] + bv.y;
            if (MODE == 0) {
                const int bb = row >> 11;
                const int t  = row & 2047;
                const int hd = col >> 6;
                const int d  = col & 63;
                const size_t a0 = zoff + ((size_t)(bb * NH + hd) * TT + t) * DH + d;
                if (z == 0) {           // V -> fp16 hi/lo
                    unsigned h2, l2;
                    split2h(v0, v1, h2, l2);
                    *(unsigned*)(ChB + a0) = h2;
                    *(unsigned*)(ClB + a0) = l2;
                    split2h(v2, v3, h2, l2);
                    *(unsigned*)(ChB + a0 + 8 * DH) = h2;
                    *(unsigned*)(ClB + a0 + 8 * DH) = l2;
                } else {                // Q (scaled) / K -> fp16 single
                    const float sc = (z == 1) ? QSCALE : 1.0f;
                    *(unsigned*)(ChB + a0)          = packh2(v0 * sc, v1 * sc);
                    *(unsigned*)(ChB + a0 + 8 * DH) = packh2(v2 * sc, v3 * sc);
                }
            } else {
                *(float2*)(outF + (size_t)row * DM + col)       = make_float2(v0, v1);
                *(float2*)(outF + (size_t)(row + 8) * DM + col) = make_float2(v2, v3);
            }
        }
    }
}

// ---------------------------------------------------------------------------
// Flash attention (identical math to R12). QK^T fp16 x1; softmax ex2.f16x2;
// row sums via ones-column mma; PV fp16 P x fp16 V hi/lo. Persistent snake.
// Epilogue writes y as fp16 hi/lo.
// ---------------------------------------------------------------------------
#define AKVS 72
#define AARR 9216                  // 64 * 72 * 2 bytes
#define ASTG (3*AARR)              // Kh, Vh, Vl = 27648
#define A_KH 0
#define A_VH AARR
#define A_VL (2*AARR)
#define ASMEM (3*ASTG)             // 82944
#define APERS 296
#define AITEMS 768                 // 16 q-blocks * 48 bh
#define ONESH2 0x3C003C00u

__global__ __launch_bounds__(256, 2)
void attn_bf(float* __restrict__ dummy)
{
    extern __shared__ __align__(16) char asmz[];
    const unsigned uS = s2u(asmz);

    const int tid  = threadIdx.x;
    const int lane = tid & 31;
    const int wid  = tid >> 5;       // 0..7
    const int g  = lane >> 2;
    const int c  = lane & 3;
    const int kblk = blockIdx.x;     // 0..295

    const int rowB_ = (lane & 7) + ((lane >> 4) & 1) * 8;
    const int colB_ = ((lane >> 3) & 1) * 8;
    const int vkey_ = lane & 15;
    const int vd_   = (lane >> 4) * 8;

    #pragma unroll 1
    for (int p = 0; p < 3; ++p) {
        const int j = p * APERS + ((p & 1) ? (APERS - 1 - kblk) : kblk);
        if (j >= AITEMS) continue;
        const int qb = 15 - (j / 48);    // descending cost order
        const int bh = j % 48;

        // ---- Q fragments: raw fp16 bits, already scaled ----
        const unsigned short* qp = g_h3 + ((size_t)bh * TT + qb * 128 + wid * 16) * DH;
        unsigned qf[4][4];
        #pragma unroll
        for (int kc = 0; kc < 4; ++kc) {
            #pragma unroll
            for (int jj = 0; jj < 4; ++jj) {
                const int row = g + (jj & 1) * 8;
                const int col = kc * 16 + 2 * c + (jj >> 1) * 8;
                qf[kc][jj] = *(const unsigned*)(qp + (size_t)row * DH + col);
            }
        }

        float o[8][4];
        #pragma unroll
        for (int i = 0; i < 8; ++i)
            #pragma unroll
            for (int jj = 0; jj < 4; ++jj) o[i][jj] = 0.f;
        float m_lo = -1e30f, m_hi = -1e30f, l_lo = 0.f, l_hi = 0.f;

        const unsigned short* kh_b = g_h3 + ZSZ     + (size_t)bh * TT * DH;
        const unsigned short* vh_b = g_h3 + 2 * ZSZ + (size_t)bh * TT * DH;
        const unsigned short* vl_b = g_l3 + 2 * ZSZ + (size_t)bh * TT * DH;

        const int row_lo = qb * 128 + wid * 16 + g;
        const int row_hi = row_lo + 8;
        const int nkb = 2 * qb + 2;

        auto issue = [&](int kb, int st) {
            const unsigned sb = uS + (unsigned)st * ASTG;
            const size_t t0 = (size_t)kb * 64 * DH;
            #pragma unroll
            for (int i = 0; i < 2; ++i) {
                const int ch  = tid + i * 256;
                const int row = ch >> 3;
                const int seg = ch & 7;
                const unsigned ro = (unsigned)(row * (AKVS * 2) + seg * 16);
                const size_t go = t0 + (size_t)ch * 8;
                cp16(sb + A_KH + ro, kh_b + go);
                cp16(sb + A_VH + ro, vh_b + go);
                cp16(sb + A_VL + ro, vl_b + go);
            }
        };

        issue(0, 0); cp_commit();
        issue(1, 1); cp_commit();

        #pragma unroll 1
        for (int kb = 0; kb < nkb; ++kb) {
            const int s = kb % 3;
            if (kb == nkb - 1) { cp_wait<0>(); } else { cp_wait<1>(); }
            __syncthreads();
            if (kb + 2 < nkb) { issue(kb + 2, (kb + 2) % 3); cp_commit(); }

            const unsigned sk = uS + (unsigned)s * ASTG;

            // ---- S = Q K^T (fp16 x1) ----
            float sx[8][4];
            #pragma unroll
            for (int i = 0; i < 8; ++i)
                #pragma unroll
                for (int jj = 0; jj < 4; ++jj) sx[i][jj] = 0.f;

            #pragma unroll
            for (int kc = 0; kc < 4; ++kc) {
                #pragma unroll
                for (int ntp = 0; ntp < 4; ++ntp) {
                    const unsigned off = (unsigned)(((ntp * 16 + rowB_) * AKVS + kc * 16 + colB_) * 2);
                    unsigned rh[4];
                    ldm4(rh, sk + A_KH + off);
                    mma16h(sx[ntp * 2],     qf[kc][0], qf[kc][1], qf[kc][2], qf[kc][3], rh[0], rh[1]);
                    mma16h(sx[ntp * 2 + 1], qf[kc][0], qf[kc][1], qf[kc][2], qf[kc][3], rh[2], rh[3]);
                }
            }

            // ---- causal mask ----
            if (kb * 64 + 63 > qb * 128 + wid * 16) {
                #pragma unroll
                for (int nt = 0; nt < 8; ++nt) {
                    const int k0 = kb * 64 + nt * 8 + c * 2;
                    if (k0 > row_lo)     sx[nt][0] = -1e30f;
                    if (k0 + 1 > row_lo) sx[nt][1] = -1e30f;
                    if (k0 > row_hi)     sx[nt][2] = -1e30f;
                    if (k0 + 1 > row_hi) sx[nt][3] = -1e30f;
                }
            }

            // ---- online softmax (log2 domain; p via ex2.approx.f16x2) ----
            float mx0 = -1e30f, mx1 = -1e30f;
            #pragma unroll
            for (int nt = 0; nt < 8; ++nt) {
                mx0 = fmaxf(mx0, fmaxf(sx[nt][0], sx[nt][1]));
                mx1 = fmaxf(mx1, fmaxf(sx[nt][2], sx[nt][3]));
            }
            mx0 = fmaxf(mx0, __shfl_xor_sync(0xffffffffu, mx0, 1));
            mx0 = fmaxf(mx0, __shfl_xor_sync(0xffffffffu, mx0, 2));
            mx1 = fmaxf(mx1, __shfl_xor_sync(0xffffffffu, mx1, 1));
            mx1 = fmaxf(mx1, __shfl_xor_sync(0xffffffffu, mx1, 2));
            const float mn0 = fmaxf(m_lo, mx0);
            const float al0 = ex2(m_lo - mn0);
            m_lo = mn0;
            const float mn1 = fmaxf(m_hi, mx1);
            const float al1 = ex2(m_hi - mn1);
            m_hi = mn1;

            unsigned pl2[8], ph2[8];
            #pragma unroll
            for (int nt = 0; nt < 8; ++nt) {
                __half2 t0 = __floats2half2_rn(sx[nt][0] - mn0, sx[nt][1] - mn0);
                pl2[nt] = ex2h2(*reinterpret_cast<unsigned*>(&t0));
                __half2 t1 = __floats2half2_rn(sx[nt][2] - mn1, sx[nt][3] - mn1);
                ph2[nt] = ex2h2(*reinterpret_cast<unsigned*>(&t1));
                o[nt][0] *= al0; o[nt][1] *= al0;
                o[nt][2] *= al1; o[nt][3] *= al1;
            }

            // ---- row sums via ones-column mma (exact f32 sum of f16 p) ----
            float ls4[4] = {0.f, 0.f, 0.f, 0.f};
            #pragma unroll
            for (int kc = 0; kc < 4; ++kc)
                mma16h(ls4, pl2[2*kc], ph2[2*kc], pl2[2*kc+1], ph2[2*kc+1], ONESH2, ONESH2);
            l_lo = l_lo * al0 + ls4[0];
            l_hi = l_hi * al1 + ls4[2];

            // ---- O += P V (fp16 P x fp16 V hi/lo) ----
            #pragma unroll
            for (int kc = 0; kc < 4; ++kc) {
                const unsigned a0 = pl2[2*kc];
                const unsigned a1 = ph2[2*kc];
                const unsigned a2 = pl2[2*kc+1];
                const unsigned a3 = ph2[2*kc+1];
                #pragma unroll
                for (int ntp = 0; ntp < 4; ++ntp) {
                    const unsigned off =
                        (unsigned)(((kc * 16 + vkey_) * AKVS + ntp * 16 + vd_) * 2);
                    unsigned vh[4], vl[4];
                    ldm4t(vh, sk + A_VH + off);
                    ldm4t(vl, sk + A_VL + off);
                    float* o0 = o[ntp * 2];
                    float* o1 = o[ntp * 2 + 1];
                    mma16h(o0, a0, a1, a2, a3, vh[0], vh[1]);
                    mma16h(o0, a0, a1, a2, a3, vl[0], vl[1]);
                    mma16h(o1, a0, a1, a2, a3, vh[2], vh[3]);
                    mma16h(o1, a0, a1, a2, a3, vl[2], vl[3]);
                }
            }
        }

        // ---- epilogue (y as fp16 hi/lo) ----
        const float inv_lo = 1.f / l_lo;
        const float inv_hi = 1.f / l_hi;

        const int bbv = bh / NH;
        const int hd  = bh % NH;
        const size_t alo = ((size_t)bbv * TT + row_lo) * DM + hd * DH + 2 * c;
        const size_t ahi = ((size_t)bbv * TT + row_hi) * DM + hd * DH + 2 * c;
        #pragma unroll
        for (int nt = 0; nt < 8; ++nt) {
            unsigned h2, l2;
            split2h(o[nt][0] * inv_lo, o[nt][1] * inv_lo, h2, l2);
            *(unsigned*)(g_yh + alo + nt * 8) = h2;
            *(unsigned*)(g_yl + alo + nt * 8) = l2;
            split2h(o[nt][2] * inv_hi, o[nt][3] * inv_hi, h2, l2);
            *(unsigned*)(g_yh + ahi + nt * 8) = h2;
            *(unsigned*)(g_yl + ahi + nt * 8) = l2;
        }

        __syncthreads();   // protect smem stages before next item's prologue
    }
    (void)dummy;
}

// ---------------------------------------------------------------------------
extern "C" void kernel_launch(void* const* d_in, const int* in_sizes, int n_in,
                              void* d_out, int out_size)
{
    const float* x  = (const float*)d_in[0];
    const float* Wq = (const float*)d_in[1];
    const float* bq = (const float*)d_in[2];
    const float* Wk = (const float*)d_in[3];
    const float* bk = (const float*)d_in[4];
    const float* Wv = (const float*)d_in[5];
    const float* bv = (const float*)d_in[6];
    const float* Wp = (const float*)d_in[7];
    const float* bp = (const float*)d_in[8];
    float* out = (float*)d_out;

    unsigned short *xh, *xl, *wh, *h3, *l3, *yh, *yl;
    cudaGetSymbolAddress((void**)&xh, g_xh);
    cudaGetSymbolAddress((void**)&xl, g_xl);
    cudaGetSymbolAddress((void**)&wh, g_wh);
    cudaGetSymbolAddress((void**)&h3, g_h3);
    cudaGetSymbolAddress((void**)&l3, g_l3);
    cudaGetSymbolAddress((void**)&yh, g_yh);
    cudaGetSymbolAddress((void**)&yl, g_yl);

    cudaFuncSetAttribute(gemm_f16<0>, cudaFuncAttributeMaxDynamicSharedMemorySize, GSMEM);
    cudaFuncSetAttribute(gemm_f16<1>, cudaFuncAttributeMaxDynamicSharedMemorySize, GSMEM);
    cudaFuncSetAttribute(attn_bf, cudaFuncAttributeMaxDynamicSharedMemorySize, ASMEM);

    // pre-pass conversions
    const int n4x = MROWS * DM / 4;
    const int n4w = DM * DM / 4;
    convert_x<<<(n4x + 255) / 256, 256>>>(x, xh, xl, n4x);
    dim3 wgrid((n4w + 255) / 256, 4);
    convert_w4<<<wgrid, 256>>>(Wq, Wk, Wv, Wp, wh, n4w);

    // QKV: z=0 -> V (heavy, first), z=1 -> Q, z=2 -> K
    dim3 qkv_grid(DM / 128, MROWS / 128, 3);
    gemm_f16<0><<<qkv_grid, 256, GSMEM>>>(xh, xl, wh, bq, bk, bv, h3, l3, nullptr);

    // attention (persistent, load-balanced)
    attn_bf<<<APERS, 256, ASMEM>>>(nullptr);

    // out-proj (fp32 out)
    dim3 proj_grid(DM / 128, MROWS / 128, 1);
    gemm_f16<1><<<proj_grid, 256, GSMEM>>>(yh, yl, wh, bp, bp, bp, nullptr, nullptr, out);
}

// round 14
// speedup vs baseline: 9.1625x; 1.4690x over previous
#include <cuda_runtime.h>
#include <cuda_bf16.h>
#include <cuda_fp16.h>
#include <math.h>

#define DM 768
#define NH 12
#define DH 64
#define BB 4
#define TT 2048
#define MROWS (BB*TT)   // 8192
#define ZSZ ((size_t)BB*NH*TT*DH)   // per-tensor q/k/v elems

// ---------------- scratch (device globals; no allocation allowed) ----------
// all arrays hold raw fp16 bits
__device__ unsigned short g_xh[(size_t)MROWS*DM];
__device__ unsigned short g_wh[4*(size_t)DM*DM];
__device__ unsigned short g_h3[3*ZSZ], g_l3[3*ZSZ];  // q,k fp16 single; v fp16 hi/lo
__device__ unsigned short g_yh[(size_t)MROWS*DM];

// ---------------- helpers --------------------------------------------------
__device__ __forceinline__ float ex2(float x) {
    float r; asm("ex2.approx.f32 %0, %1;" : "=f"(r) : "f"(x)); return r;
}
__device__ __forceinline__ unsigned ex2h2(unsigned x) {
    unsigned r; asm("ex2.approx.f16x2 %0, %1;" : "=r"(r) : "r"(x)); return r;
}
// fp16 m16n8k16
__device__ __forceinline__ void mma16h(float d[4],
                                       unsigned a0, unsigned a1, unsigned a2, unsigned a3,
                                       unsigned b0, unsigned b1) {
    asm volatile(
        "mma.sync.aligned.m16n8k16.row.col.f32.f16.f16.f32 "
        "{%0,%1,%2,%3}, {%4,%5,%6,%7}, {%8,%9}, {%0,%1,%2,%3};\n"
        : "+f"(d[0]), "+f"(d[1]), "+f"(d[2]), "+f"(d[3])
        : "r"(a0), "r"(a1), "r"(a2), "r"(a3), "r"(b0), "r"(b1));
}
__device__ __forceinline__ void ldm4(unsigned r[4], unsigned addr) {
    asm volatile("ldmatrix.sync.aligned.m8n8.x4.shared.b16 {%0,%1,%2,%3}, [%4];"
                 : "=r"(r[0]), "=r"(r[1]), "=r"(r[2]), "=r"(r[3]) : "r"(addr));
}
__device__ __forceinline__ void ldm4t(unsigned r[4], unsigned addr) {
    asm volatile("ldmatrix.sync.aligned.m8n8.x4.trans.shared.b16 {%0,%1,%2,%3}, [%4];"
                 : "=r"(r[0]), "=r"(r[1]), "=r"(r[2]), "=r"(r[3]) : "r"(addr));
}
__device__ __forceinline__ unsigned s2u(const void* p) {
    return (unsigned)__cvta_generic_to_shared(p);
}
__device__ __forceinline__ void cp16(unsigned saddr, const void* gptr) {
    asm volatile("cp.async.cg.shared.global [%0], [%1], 16;"
                 :: "r"(saddr), "l"(gptr) : "memory");
}
__device__ __forceinline__ void cp_commit() {
    asm volatile("cp.async.commit_group;" ::: "memory");
}
template<int N>
__device__ __forceinline__ void cp_wait() {
    asm volatile("cp.async.wait_group %0;" :: "n"(N) : "memory");
}
// fp16 pair split
__device__ __forceinline__ void split2h(float x0, float x1, unsigned& h2, unsigned& l2) {
    __half2 t = __floats2half2_rn(x0, x1);
    h2 = *reinterpret_cast<unsigned*>(&t);
    const float f0 = __half2float(__low2half(t));
    const float f1 = __half2float(__high2half(t));
    __half2 tl = __floats2half2_rn(x0 - f0, x1 - f1);
    l2 = *reinterpret_cast<unsigned*>(&tl);
}
__device__ __forceinline__ unsigned packh2(float x0, float x1) {
    __half2 t = __floats2half2_rn(x0, x1);
    return *reinterpret_cast<unsigned*>(&t);
}

// ---------------- pre-pass converts ----------------------------------------
// x -> fp16 single
__global__ void convert_x(const float* __restrict__ src,
                          unsigned short* __restrict__ h, int n4)
{
    int i = blockIdx.x * blockDim.x + threadIdx.x;
    if (i >= n4) return;
    float4 v = reinterpret_cast<const float4*>(src)[i];
    reinterpret_cast<unsigned*>(h)[2*i]   = packh2(v.x, v.y);
    reinterpret_cast<unsigned*>(h)[2*i+1] = packh2(v.z, v.w);
}
// 4 weights -> fp16 single (blockIdx.y selects matrix)
__global__ void convert_w4(const float* __restrict__ s0, const float* __restrict__ s1,
                           const float* __restrict__ s2, const float* __restrict__ s3,
                           unsigned short* __restrict__ h, int n4)
{
    int i = blockIdx.x * blockDim.x + threadIdx.x;
    if (i >= n4) return;
    const int z = blockIdx.y;
    const float* src = (z == 0) ? s0 : ((z == 1) ? s1 : ((z == 2) ? s2 : s3));
    const size_t off2 = (size_t)z * (DM * DM / 2);
    float4 v = reinterpret_cast<const float4*>(src)[i];
    reinterpret_cast<unsigned*>(h)[off2 + 2*i]   = packh2(v.x, v.y);
    reinterpret_cast<unsigned*>(h)[off2 + 2*i+1] = packh2(v.z, v.w);
}

// ---------------------------------------------------------------------------
// fp16 1-mma GEMM (mma.sync), BK=32, 3-stage cp.async, ONE barrier per iter.
// BM=BN=128. 8 warps (2m x 4n). smem row stride 40 halves (conflict-free).
// MODE 0 (QKV): z=0 -> V (fp16 hi/lo out), z=1 -> Q (fp16*QSCALE), z=2 -> K.
// MODE 1 (proj): fp32 out.
// ---------------------------------------------------------------------------
#define HST2 40
#define AB2  (128*HST2*2)      // 10240 per array
#define GSTG2 (2*AB2)          // 20480 per stage: A, B
#define GSMEM2 (3*GSTG2)       // 61440
#define QSCALE (0.125f * 1.4426950408889634f)

template<int MODE>
__global__ __launch_bounds__(256, 2)
void gemm_f16(const unsigned short* __restrict__ Ah,
              const unsigned short* __restrict__ Whb,
              const float* __restrict__ b0p, const float* __restrict__ b1p,
              const float* __restrict__ b2p,
              unsigned short* __restrict__ ChB, unsigned short* __restrict__ ClB,
              float* __restrict__ outF)
{
    extern __shared__ __align__(16) char gsm[];
    const unsigned sbase = s2u(gsm);

    const int z = blockIdx.z;
    // MODE 0: z=0->Wv(idx2), z=1->Wq(0), z=2->Wk(1). MODE 1: Wp(3).
    const int widx = (MODE == 1) ? 3 : ((z == 0) ? 2 : ((z == 1) ? 0 : 1));
    const size_t woff = (size_t)widx * DM * DM;
    const float* bias = (MODE == 1) ? b0p : ((z == 0) ? b2p : ((z == 1) ? b0p : b1p));

    const int tid  = threadIdx.x;
    const int lane = tid & 31;
    const int wid  = tid >> 5;
    const int m0 = blockIdx.y * 128;
    const int n0 = blockIdx.x * 128;
    const int wm = wid >> 2;
    const int wn = wid & 3;
    const int g  = lane >> 2;
    const int c  = lane & 3;

    const int rowA_ = (lane & 7) + ((lane >> 3) & 1) * 8;
    const int colA_ = (lane >> 4) * 8;
    const int rowB_ = (lane & 7) + ((lane >> 4) & 1) * 8;
    const int colB_ = ((lane >> 3) & 1) * 8;

    // loader: thread -> row = tid>>1, k-half = (tid&1)*16 halves (32B)
    const int lrow  = tid >> 1;
    const int lkoff = (tid & 1) * 16;          // halves
    const unsigned short* pa = Ah + (size_t)(m0 + lrow) * DM + lkoff;
    const unsigned short* pb = Whb + woff + (size_t)(n0 + lrow) * DM + lkoff;
    const unsigned sRowA = (unsigned)(lrow * (HST2 * 2) + lkoff * 2);
    const unsigned sRowB = sRowA + AB2;

    float acc[4][4][4];
    #pragma unroll
    for (int i = 0; i < 4; i++)
        #pragma unroll
        for (int j = 0; j < 4; j++)
            #pragma unroll
            for (int r = 0; r < 4; r++) acc[i][j][r] = 0.f;

    auto issueG = [&](int itx, int st) {
        const int k0 = itx * 32;
        const unsigned sb = sbase + (unsigned)st * GSTG2;
        cp16(sb + sRowA,      pa + k0);
        cp16(sb + sRowA + 16, pa + k0 + 8);
        cp16(sb + sRowB,      pb + k0);
        cp16(sb + sRowB + 16, pb + k0 + 8);
    };

    issueG(0, 0); cp_commit();
    issueG(1, 1); cp_commit();

    #pragma unroll 1
    for (int it = 0; it < 24; ++it) {
        const int s = it % 3;
        if (it == 23) { cp_wait<0>(); } else { cp_wait<1>(); }
        __syncthreads();
        if (it + 2 < 24) { issueG(it + 2, (it + 2) % 3); cp_commit(); }

        const unsigned bufo = sbase + (unsigned)s * GSTG2;
        #pragma unroll
        for (int kh = 0; kh < 2; ++kh) {
            unsigned bh[4][2];
            #pragma unroll
            for (int ntp = 0; ntp < 2; ++ntp) {
                unsigned r[4];
                const int rb = wn * 32 + ntp * 16 + rowB_;
                ldm4(r, bufo + AB2 + (unsigned)((rb * HST2 + kh * 16 + colB_) * 2));
                bh[ntp*2][0] = r[0]; bh[ntp*2][1] = r[1];
                bh[ntp*2+1][0] = r[2]; bh[ntp*2+1][1] = r[3];
            }
            #pragma unroll
            for (int mi = 0; mi < 4; ++mi) {
                const int ra = wm * 64 + mi * 16 + rowA_;
                unsigned ah[4];
                ldm4(ah, bufo + (unsigned)((ra * HST2 + kh * 16 + colA_) * 2));
                #pragma unroll
                for (int ni = 0; ni < 4; ++ni)
                    mma16h(acc[mi][ni], ah[0], ah[1], ah[2], ah[3], bh[ni][0], bh[ni][1]);
            }
        }
    }

    // ---- epilogue ----
    const size_t zoff = (MODE == 0) ? ((z == 0) ? 2 * ZSZ : ((z == 1) ? 0 : ZSZ)) : 0;
    #pragma unroll
    for (int mi = 0; mi < 4; ++mi) {
        const int row = m0 + wm * 64 + mi * 16 + g;
        #pragma unroll
        for (int ni = 0; ni < 4; ++ni) {
            const int col = n0 + wn * 32 + ni * 8 + c * 2;
            float2 bv = *(const float2*)(bias + col);
            float v0 = acc[mi][ni][0] + bv.x;
            float v1 = acc[mi][ni][1] + bv.y;
            float v2 = acc[mi][ni][2] + bv.x;
            float v3 = acc[mi][ni][3] + bv.y;
            if (MODE == 0) {
                const int bb = row >> 11;
                const int t  = row & 2047;
                const int hd = col >> 6;
                const int d  = col & 63;
                const size_t a0 = zoff + ((size_t)(bb * NH + hd) * TT + t) * DH + d;
                if (z == 0) {           // V -> fp16 hi/lo
                    unsigned h2, l2;
                    split2h(v0, v1, h2, l2);
                    *(unsigned*)(ChB + a0) = h2;
                    *(unsigned*)(ClB + a0) = l2;
                    split2h(v2, v3, h2, l2);
                    *(unsigned*)(ChB + a0 + 8 * DH) = h2;
                    *(unsigned*)(ClB + a0 + 8 * DH) = l2;
                } else {                // Q (scaled) / K -> fp16 single
                    const float sc = (z == 1) ? QSCALE : 1.0f;
                    *(unsigned*)(ChB + a0)          = packh2(v0 * sc, v1 * sc);
                    *(unsigned*)(ChB + a0 + 8 * DH) = packh2(v2 * sc, v3 * sc);
                }
            } else {
                *(float2*)(outF + (size_t)row * DM + col)       = make_float2(v0, v1);
                *(float2*)(outF + (size_t)(row + 8) * DM + col) = make_float2(v2, v3);
            }
        }
    }
}

// ---------------------------------------------------------------------------
// Flash attention (math identical to R13). QK^T fp16 x1; softmax ex2.f16x2;
// row sums via ones-column mma; PV fp16 P x fp16 V hi/lo. Persistent snake.
// Epilogue writes y as fp16 single.
// ---------------------------------------------------------------------------
#define AKVS 72
#define AARR 9216                  // 64 * 72 * 2 bytes
#define ASTG (3*AARR)              // Kh, Vh, Vl = 27648
#define A_KH 0
#define A_VH AARR
#define A_VL (2*AARR)
#define ASMEM (3*ASTG)             // 82944
#define APERS 296
#define AITEMS 768                 // 16 q-blocks * 48 bh
#define ONESH2 0x3C003C00u

__global__ __launch_bounds__(256, 2)
void attn_bf(float* __restrict__ dummy)
{
    extern __shared__ __align__(16) char asmz[];
    const unsigned uS = s2u(asmz);

    const int tid  = threadIdx.x;
    const int lane = tid & 31;
    const int wid  = tid >> 5;       // 0..7
    const int g  = lane >> 2;
    const int c  = lane & 3;
    const int kblk = blockIdx.x;     // 0..295

    const int rowB_ = (lane & 7) + ((lane >> 4) & 1) * 8;
    const int colB_ = ((lane >> 3) & 1) * 8;
    const int vkey_ = lane & 15;
    const int vd_   = (lane >> 4) * 8;

    #pragma unroll 1
    for (int p = 0; p < 3; ++p) {
        const int j = p * APERS + ((p & 1) ? (APERS - 1 - kblk) : kblk);
        if (j >= AITEMS) continue;
        const int qb = 15 - (j / 48);    // descending cost order
        const int bh = j % 48;

        // ---- Q fragments: raw fp16 bits, already scaled ----
        const unsigned short* qp = g_h3 + ((size_t)bh * TT + qb * 128 + wid * 16) * DH;
        unsigned qf[4][4];
        #pragma unroll
        for (int kc = 0; kc < 4; ++kc) {
            #pragma unroll
            for (int jj = 0; jj < 4; ++jj) {
                const int row = g + (jj & 1) * 8;
                const int col = kc * 16 + 2 * c + (jj >> 1) * 8;
                qf[kc][jj] = *(const unsigned*)(qp + (size_t)row * DH + col);
            }
        }

        float o[8][4];
        #pragma unroll
        for (int i = 0; i < 8; ++i)
            #pragma unroll
            for (int jj = 0; jj < 4; ++jj) o[i][jj] = 0.f;
        float m_lo = -1e30f, m_hi = -1e30f, l_lo = 0.f, l_hi = 0.f;

        const unsigned short* kh_b = g_h3 + ZSZ     + (size_t)bh * TT * DH;
        const unsigned short* vh_b = g_h3 + 2 * ZSZ + (size_t)bh * TT * DH;
        const unsigned short* vl_b = g_l3 + 2 * ZSZ + (size_t)bh * TT * DH;

        const int row_lo = qb * 128 + wid * 16 + g;
        const int row_hi = row_lo + 8;
        const int nkb = 2 * qb + 2;

        auto issue = [&](int kb, int st) {
            const unsigned sb = uS + (unsigned)st * ASTG;
            const size_t t0 = (size_t)kb * 64 * DH;
            #pragma unroll
            for (int i = 0; i < 2; ++i) {
                const int ch  = tid + i * 256;
                const int row = ch >> 3;
                const int seg = ch & 7;
                const unsigned ro = (unsigned)(row * (AKVS * 2) + seg * 16);
                const size_t go = t0 + (size_t)ch * 8;
                cp16(sb + A_KH + ro, kh_b + go);
                cp16(sb + A_VH + ro, vh_b + go);
                cp16(sb + A_VL + ro, vl_b + go);
            }
        };

        issue(0, 0); cp_commit();
        issue(1, 1); cp_commit();

        #pragma unroll 1
        for (int kb = 0; kb < nkb; ++kb) {
            const int s = kb % 3;
            if (kb == nkb - 1) { cp_wait<0>(); } else { cp_wait<1>(); }
            __syncthreads();
            if (kb + 2 < nkb) { issue(kb + 2, (kb + 2) % 3); cp_commit(); }

            const unsigned sk = uS + (unsigned)s * ASTG;

            // ---- S = Q K^T (fp16 x1) ----
            float sx[8][4];
            #pragma unroll
            for (int i = 0; i < 8; ++i)
                #pragma unroll
                for (int jj = 0; jj < 4; ++jj) sx[i][jj] = 0.f;

            #pragma unroll
            for (int kc = 0; kc < 4; ++kc) {
                #pragma unroll
                for (int ntp = 0; ntp < 4; ++ntp) {
                    const unsigned off = (unsigned)(((ntp * 16 + rowB_) * AKVS + kc * 16 + colB_) * 2);
                    unsigned rh[4];
                    ldm4(rh, sk + A_KH + off);
                    mma16h(sx[ntp * 2],     qf[kc][0], qf[kc][1], qf[kc][2], qf[kc][3], rh[0], rh[1]);
                    mma16h(sx[ntp * 2 + 1], qf[kc][0], qf[kc][1], qf[kc][2], qf[kc][3], rh[2], rh[3]);
                }
            }

            // ---- causal mask ----
            if (kb * 64 + 63 > qb * 128 + wid * 16) {
                #pragma unroll
                for (int nt = 0; nt < 8; ++nt) {
                    const int k0 = kb * 64 + nt * 8 + c * 2;
                    if (k0 > row_lo)     sx[nt][0] = -1e30f;
                    if (k0 + 1 > row_lo) sx[nt][1] = -1e30f;
                    if (k0 > row_hi)     sx[nt][2] = -1e30f;
                    if (k0 + 1 > row_hi) sx[nt][3] = -1e30f;
                }
            }

            // ---- online softmax (log2 domain; p via ex2.approx.f16x2) ----
            float mx0 = -1e30f, mx1 = -1e30f;
            #pragma unroll
            for (int nt = 0; nt < 8; ++nt) {
                mx0 = fmaxf(mx0, fmaxf(sx[nt][0], sx[nt][1]));
                mx1 = fmaxf(mx1, fmaxf(sx[nt][2], sx[nt][3]));
            }
            mx0 = fmaxf(mx0, __shfl_xor_sync(0xffffffffu, mx0, 1));
            mx0 = fmaxf(mx0, __shfl_xor_sync(0xffffffffu, mx0, 2));
            mx1 = fmaxf(mx1, __shfl_xor_sync(0xffffffffu, mx1, 1));
            mx1 = fmaxf(mx1, __shfl_xor_sync(0xffffffffu, mx1, 2));
            const float mn0 = fmaxf(m_lo, mx0);
            const float al0 = ex2(m_lo - mn0);
            m_lo = mn0;
            const float mn1 = fmaxf(m_hi, mx1);
            const float al1 = ex2(m_hi - mn1);
            m_hi = mn1;

            unsigned pl2[8], ph2[8];
            #pragma unroll
            for (int nt = 0; nt < 8; ++nt) {
                __half2 t0 = __floats2half2_rn(sx[nt][0] - mn0, sx[nt][1] - mn0);
                pl2[nt] = ex2h2(*reinterpret_cast<unsigned*>(&t0));
                __half2 t1 = __floats2half2_rn(sx[nt][2] - mn1, sx[nt][3] - mn1);
                ph2[nt] = ex2h2(*reinterpret_cast<unsigned*>(&t1));
                o[nt][0] *= al0; o[nt][1] *= al0;
                o[nt][2] *= al1; o[nt][3] *= al1;
            }

            // ---- row sums via ones-column mma (exact f32 sum of f16 p) ----
            float ls4[4] = {0.f, 0.f, 0.f, 0.f};
            #pragma unroll
            for (int kc = 0; kc < 4; ++kc)
                mma16h(ls4, pl2[2*kc], ph2[2*kc], pl2[2*kc+1], ph2[2*kc+1], ONESH2, ONESH2);
            l_lo = l_lo * al0 + ls4[0];
            l_hi = l_hi * al1 + ls4[2];

            // ---- O += P V (fp16 P x fp16 V hi/lo) ----
            #pragma unroll
            for (int kc = 0; kc < 4; ++kc) {
                const unsigned a0 = pl2[2*kc];
                const unsigned a1 = ph2[2*kc];
                const unsigned a2 = pl2[2*kc+1];
                const unsigned a3 = ph2[2*kc+1];
                #pragma unroll
                for (int ntp = 0; ntp < 4; ++ntp) {
                    const unsigned off =
                        (unsigned)(((kc * 16 + vkey_) * AKVS + ntp * 16 + vd_) * 2);
                    unsigned vh[4], vl[4];
                    ldm4t(vh, sk + A_VH + off);
                    ldm4t(vl, sk + A_VL + off);
                    float* o0 = o[ntp * 2];
                    float* o1 = o[ntp * 2 + 1];
                    mma16h(o0, a0, a1, a2, a3, vh[0], vh[1]);
                    mma16h(o0, a0, a1, a2, a3, vl[0], vl[1]);
                    mma16h(o1, a0, a1, a2, a3, vh[2], vh[3]);
                    mma16h(o1, a0, a1, a2, a3, vl[2], vl[3]);
                }
            }
        }

        // ---- epilogue (y as fp16 single) ----
        const float inv_lo = 1.f / l_lo;
        const float inv_hi = 1.f / l_hi;

        const int bbv = bh / NH;
        const int hd  = bh % NH;
        const size_t alo = ((size_t)bbv * TT + row_lo) * DM + hd * DH + 2 * c;
        const size_t ahi = ((size_t)bbv * TT + row_hi) * DM + hd * DH + 2 * c;
        #pragma unroll
        for (int nt = 0; nt < 8; ++nt) {
            *(unsigned*)(g_yh + alo + nt * 8) = packh2(o[nt][0] * inv_lo, o[nt][1] * inv_lo);
            *(unsigned*)(g_yh + ahi + nt * 8) = packh2(o[nt][2] * inv_hi, o[nt][3] * inv_hi);
        }

        __syncthreads();   // protect smem stages before next item's prologue
    }
    (void)dummy;
}

// ---------------------------------------------------------------------------
extern "C" void kernel_launch(void* const* d_in, const int* in_sizes, int n_in,
                              void* d_out, int out_size)
{
    const float* x  = (const float*)d_in[0];
    const float* Wq = (const float*)d_in[1];
    const float* bq = (const float*)d_in[2];
    const float* Wk = (const float*)d_in[3];
    const float* bk = (const float*)d_in[4];
    const float* Wv = (const float*)d_in[5];
    const float* bv = (const float*)d_in[6];
    const float* Wp = (const float*)d_in[7];
    const float* bp = (const float*)d_in[8];
    float* out = (float*)d_out;

    unsigned short *xh, *wh, *h3, *l3, *yh;
    cudaGetSymbolAddress((void**)&xh, g_xh);
    cudaGetSymbolAddress((void**)&wh, g_wh);
    cudaGetSymbolAddress((void**)&h3, g_h3);
    cudaGetSymbolAddress((void**)&l3, g_l3);
    cudaGetSymbolAddress((void**)&yh, g_yh);

    cudaFuncSetAttribute(gemm_f16<0>, cudaFuncAttributeMaxDynamicSharedMemorySize, GSMEM2);
    cudaFuncSetAttribute(gemm_f16<1>, cudaFuncAttributeMaxDynamicSharedMemorySize, GSMEM2);
    cudaFuncSetAttribute(attn_bf, cudaFuncAttributeMaxDynamicSharedMemorySize, ASMEM);

    // pre-pass conversions
    const int n4x = MROWS * DM / 4;
    const int n4w = DM * DM / 4;
    convert_x<<<(n4x + 255) / 256, 256>>>(x, xh, n4x);
    dim3 wgrid((n4w + 255) / 256, 4);
    convert_w4<<<wgrid, 256>>>(Wq, Wk, Wv, Wp, wh, n4w);

    // QKV: z=0 -> V (hi/lo out), z=1 -> Q, z=2 -> K
    dim3 qkv_grid(DM / 128, MROWS / 128, 3);
    gemm_f16<0><<<qkv_grid, 256, GSMEM2>>>(xh, wh, bq, bk, bv, h3, l3, nullptr);

    // attention (persistent, load-balanced)
    attn_bf<<<APERS, 256, ASMEM>>>(nullptr);

    // out-proj (fp32 out)
    dim3 proj_grid(DM / 128, MROWS / 128, 1);
    gemm_f16<1><<<proj_grid, 256, GSMEM2>>>(yh, wh, bp, bp, bp, nullptr, nullptr, out);
}

// round 15
// speedup vs baseline: 10.3467x; 1.1292x over previous
#include <cuda_runtime.h>
#include <cuda_bf16.h>
#include <cuda_fp16.h>
#include <math.h>

#define DM 768
#define NH 12
#define DH 64
#define BB 4
#define TT 2048
#define MROWS (BB*TT)   // 8192
#define ZSZ ((size_t)BB*NH*TT*DH)   // per-tensor q/k/v elems

// ---------------- scratch (device globals; no allocation allowed) ----------
// all arrays hold raw fp16 bits
__device__ unsigned short g_xh[(size_t)MROWS*DM];
__device__ unsigned short g_wh[4*(size_t)DM*DM];
__device__ unsigned short g_h3[3*ZSZ];              // q (scaled), k, v — fp16 single
__device__ unsigned short g_yh[(size_t)MROWS*DM];

// ---------------- helpers --------------------------------------------------
__device__ __forceinline__ float ex2(float x) {
    float r; asm("ex2.approx.f32 %0, %1;" : "=f"(r) : "f"(x)); return r;
}
__device__ __forceinline__ unsigned ex2h2(unsigned x) {
    unsigned r; asm("ex2.approx.f16x2 %0, %1;" : "=r"(r) : "r"(x)); return r;
}
// fp16 m16n8k16
__device__ __forceinline__ void mma16h(float d[4],
                                       unsigned a0, unsigned a1, unsigned a2, unsigned a3,
                                       unsigned b0, unsigned b1) {
    asm volatile(
        "mma.sync.aligned.m16n8k16.row.col.f32.f16.f16.f32 "
        "{%0,%1,%2,%3}, {%4,%5,%6,%7}, {%8,%9}, {%0,%1,%2,%3};\n"
        : "+f"(d[0]), "+f"(d[1]), "+f"(d[2]), "+f"(d[3])
        : "r"(a0), "r"(a1), "r"(a2), "r"(a3), "r"(b0), "r"(b1));
}
__device__ __forceinline__ void ldm4(unsigned r[4], unsigned addr) {
    asm volatile("ldmatrix.sync.aligned.m8n8.x4.shared.b16 {%0,%1,%2,%3}, [%4];"
                 : "=r"(r[0]), "=r"(r[1]), "=r"(r[2]), "=r"(r[3]) : "r"(addr));
}
__device__ __forceinline__ void ldm4t(unsigned r[4], unsigned addr) {
    asm volatile("ldmatrix.sync.aligned.m8n8.x4.trans.shared.b16 {%0,%1,%2,%3}, [%4];"
                 : "=r"(r[0]), "=r"(r[1]), "=r"(r[2]), "=r"(r[3]) : "r"(addr));
}
__device__ __forceinline__ unsigned s2u(const void* p) {
    return (unsigned)__cvta_generic_to_shared(p);
}
__device__ __forceinline__ void cp16(unsigned saddr, const void* gptr) {
    asm volatile("cp.async.cg.shared.global [%0], [%1], 16;"
                 :: "r"(saddr), "l"(gptr) : "memory");
}
__device__ __forceinline__ void cp_commit() {
    asm volatile("cp.async.commit_group;" ::: "memory");
}
template<int N>
__device__ __forceinline__ void cp_wait() {
    asm volatile("cp.async.wait_group %0;" :: "n"(N) : "memory");
}
__device__ __forceinline__ unsigned packh2(float x0, float x1) {
    __half2 t = __floats2half2_rn(x0, x1);
    return *reinterpret_cast<unsigned*>(&t);
}

// ---------------- pre-pass converts ----------------------------------------
// x -> fp16 single
__global__ void convert_x(const float* __restrict__ src,
                          unsigned short* __restrict__ h, int n4)
{
    int i = blockIdx.x * blockDim.x + threadIdx.x;
    if (i >= n4) return;
    float4 v = reinterpret_cast<const float4*>(src)[i];
    reinterpret_cast<unsigned*>(h)[2*i]   = packh2(v.x, v.y);
    reinterpret_cast<unsigned*>(h)[2*i+1] = packh2(v.z, v.w);
}
// 4 weights -> fp16 single (blockIdx.y selects matrix)
__global__ void convert_w4(const float* __restrict__ s0, const float* __restrict__ s1,
                           const float* __restrict__ s2, const float* __restrict__ s3,
                           unsigned short* __restrict__ h, int n4)
{
    int i = blockIdx.x * blockDim.x + threadIdx.x;
    if (i >= n4) return;
    const int z = blockIdx.y;
    const float* src = (z == 0) ? s0 : ((z == 1) ? s1 : ((z == 2) ? s2 : s3));
    const size_t off2 = (size_t)z * (DM * DM / 2);
    float4 v = reinterpret_cast<const float4*>(src)[i];
    reinterpret_cast<unsigned*>(h)[off2 + 2*i]   = packh2(v.x, v.y);
    reinterpret_cast<unsigned*>(h)[off2 + 2*i+1] = packh2(v.z, v.w);
}

// ---------------------------------------------------------------------------
// fp16 1-mma GEMM (mma.sync), BK=32, 3-stage cp.async, ONE barrier per iter.
// BM=BN=128. 8 warps (2m x 4n). smem row stride 40 halves (conflict-free).
// MODE 0 (QKV): z=0 -> Q (fp16*QSCALE), z=1 -> K, z=2 -> V (fp16 single).
// MODE 1 (proj): fp32 out.
// ---------------------------------------------------------------------------
#define HST2 40
#define AB2  (128*HST2*2)      // 10240 per array
#define GSTG2 (2*AB2)          // 20480 per stage: A, B
#define GSMEM2 (3*GSTG2)       // 61440
#define QSCALE (0.125f * 1.4426950408889634f)

template<int MODE>
__global__ __launch_bounds__(256, 2)
void gemm_f16(const unsigned short* __restrict__ Ah,
              const unsigned short* __restrict__ Whb,
              const float* __restrict__ b0p, const float* __restrict__ b1p,
              const float* __restrict__ b2p,
              unsigned short* __restrict__ ChB,
              float* __restrict__ outF)
{
    extern __shared__ __align__(16) char gsm[];
    const unsigned sbase = s2u(gsm);

    const int z = blockIdx.z;
    // MODE 0: z -> W index directly (0=Wq,1=Wk,2=Wv). MODE 1: Wp(3).
    const int widx = (MODE == 1) ? 3 : z;
    const size_t woff = (size_t)widx * DM * DM;
    const float* bias = (MODE == 1) ? b0p : ((z == 0) ? b0p : ((z == 1) ? b1p : b2p));

    const int tid  = threadIdx.x;
    const int lane = tid & 31;
    const int wid  = tid >> 5;
    const int m0 = blockIdx.y * 128;
    const int n0 = blockIdx.x * 128;
    const int wm = wid >> 2;
    const int wn = wid & 3;
    const int g  = lane >> 2;
    const int c  = lane & 3;

    const int rowA_ = (lane & 7) + ((lane >> 3) & 1) * 8;
    const int colA_ = (lane >> 4) * 8;
    const int rowB_ = (lane & 7) + ((lane >> 4) & 1) * 8;
    const int colB_ = ((lane >> 3) & 1) * 8;

    // loader: thread -> row = tid>>1, k-half = (tid&1)*16 halves (32B)
    const int lrow  = tid >> 1;
    const int lkoff = (tid & 1) * 16;          // halves
    const unsigned short* pa = Ah + (size_t)(m0 + lrow) * DM + lkoff;
    const unsigned short* pb = Whb + woff + (size_t)(n0 + lrow) * DM + lkoff;
    const unsigned sRowA = (unsigned)(lrow * (HST2 * 2) + lkoff * 2);
    const unsigned sRowB = sRowA + AB2;

    float acc[4][4][4];
    #pragma unroll
    for (int i = 0; i < 4; i++)
        #pragma unroll
        for (int j = 0; j < 4; j++)
            #pragma unroll
            for (int r = 0; r < 4; r++) acc[i][j][r] = 0.f;

    auto issueG = [&](int itx, int st) {
        const int k0 = itx * 32;
        const unsigned sb = sbase + (unsigned)st * GSTG2;
        cp16(sb + sRowA,      pa + k0);
        cp16(sb + sRowA + 16, pa + k0 + 8);
        cp16(sb + sRowB,      pb + k0);
        cp16(sb + sRowB + 16, pb + k0 + 8);
    };

    issueG(0, 0); cp_commit();
    issueG(1, 1); cp_commit();

    #pragma unroll 1
    for (int it = 0; it < 24; ++it) {
        const int s = it % 3;
        if (it == 23) { cp_wait<0>(); } else { cp_wait<1>(); }
        __syncthreads();
        if (it + 2 < 24) { issueG(it + 2, (it + 2) % 3); cp_commit(); }

        const unsigned bufo = sbase + (unsigned)s * GSTG2;
        #pragma unroll
        for (int kh = 0; kh < 2; ++kh) {
            unsigned bh[4][2];
            #pragma unroll
            for (int ntp = 0; ntp < 2; ++ntp) {
                unsigned r[4];
                const int rb = wn * 32 + ntp * 16 + rowB_;
                ldm4(r, bufo + AB2 + (unsigned)((rb * HST2 + kh * 16 + colB_) * 2));
                bh[ntp*2][0] = r[0]; bh[ntp*2][1] = r[1];
                bh[ntp*2+1][0] = r[2]; bh[ntp*2+1][1] = r[3];
            }
            #pragma unroll
            for (int mi = 0; mi < 4; ++mi) {
                const int ra = wm * 64 + mi * 16 + rowA_;
                unsigned ah[4];
                ldm4(ah, bufo + (unsigned)((ra * HST2 + kh * 16 + colA_) * 2));
                #pragma unroll
                for (int ni = 0; ni < 4; ++ni)
                    mma16h(acc[mi][ni], ah[0], ah[1], ah[2], ah[3], bh[ni][0], bh[ni][1]);
            }
        }
    }

    // ---- epilogue ----
    #pragma unroll
    for (int mi = 0; mi < 4; ++mi) {
        const int row = m0 + wm * 64 + mi * 16 + g;
        #pragma unroll
        for (int ni = 0; ni < 4; ++ni) {
            const int col = n0 + wn * 32 + ni * 8 + c * 2;
            float2 bv = *(const float2*)(bias + col);
            float v0 = acc[mi][ni][0] + bv.x;
            float v1 = acc[mi][ni][1] + bv.y;
            float v2 = acc[mi][ni][2] + bv.x;
            float v3 = acc[mi][ni][3] + bv.y;
            if (MODE == 0) {
                const int bb = row >> 11;
                const int t  = row & 2047;
                const int hd = col >> 6;
                const int d  = col & 63;
                const size_t a0 = (size_t)z * ZSZ + ((size_t)(bb * NH + hd) * TT + t) * DH + d;
                const float sc = (z == 0) ? QSCALE : 1.0f;
                *(unsigned*)(ChB + a0)          = packh2(v0 * sc, v1 * sc);
                *(unsigned*)(ChB + a0 + 8 * DH) = packh2(v2 * sc, v3 * sc);
            } else {
                *(float2*)(outF + (size_t)row * DM + col)       = make_float2(v0, v1);
                *(float2*)(outF + (size_t)(row + 8) * DM + col) = make_float2(v2, v3);
            }
        }
    }
}

// ---------------------------------------------------------------------------
// Flash attention. QK^T fp16 x1; softmax ex2.f16x2; row sums via ones-column
// mma; PV fp16 P x fp16 V (single). Persistent snake. y as fp16 single.
// ---------------------------------------------------------------------------
#define AKVS 72
#define AARR 9216                  // 64 * 72 * 2 bytes
#define ASTG (2*AARR)              // Kh, Vh = 18432
#define A_KH 0
#define A_VH AARR
#define ASMEM (3*ASTG)             // 55296
#define APERS 296
#define AITEMS 768                 // 16 q-blocks * 48 bh
#define ONESH2 0x3C003C00u

__global__ __launch_bounds__(256, 2)
void attn_bf(float* __restrict__ dummy)
{
    extern __shared__ __align__(16) char asmz[];
    const unsigned uS = s2u(asmz);

    const int tid  = threadIdx.x;
    const int lane = tid & 31;
    const int wid  = tid >> 5;       // 0..7
    const int g  = lane >> 2;
    const int c  = lane & 3;
    const int kblk = blockIdx.x;     // 0..295

    const int rowB_ = (lane & 7) + ((lane >> 4) & 1) * 8;
    const int colB_ = ((lane >> 3) & 1) * 8;
    const int vkey_ = lane & 15;
    const int vd_   = (lane >> 4) * 8;

    #pragma unroll 1
    for (int p = 0; p < 3; ++p) {
        const int j = p * APERS + ((p & 1) ? (APERS - 1 - kblk) : kblk);
        if (j >= AITEMS) continue;
        const int qb = 15 - (j / 48);    // descending cost order
        const int bh = j % 48;

        // ---- Q fragments: raw fp16 bits, already scaled ----
        const unsigned short* qp = g_h3 + ((size_t)bh * TT + qb * 128 + wid * 16) * DH;
        unsigned qf[4][4];
        #pragma unroll
        for (int kc = 0; kc < 4; ++kc) {
            #pragma unroll
            for (int jj = 0; jj < 4; ++jj) {
                const int row = g + (jj & 1) * 8;
                const int col = kc * 16 + 2 * c + (jj >> 1) * 8;
                qf[kc][jj] = *(const unsigned*)(qp + (size_t)row * DH + col);
            }
        }

        float o[8][4];
        #pragma unroll
        for (int i = 0; i < 8; ++i)
            #pragma unroll
            for (int jj = 0; jj < 4; ++jj) o[i][jj] = 0.f;
        float m_lo = -1e30f, m_hi = -1e30f, l_lo = 0.f, l_hi = 0.f;

        const unsigned short* kh_b = g_h3 + ZSZ     + (size_t)bh * TT * DH;
        const unsigned short* vh_b = g_h3 + 2 * ZSZ + (size_t)bh * TT * DH;

        const int row_lo = qb * 128 + wid * 16 + g;
        const int row_hi = row_lo + 8;
        const int nkb = 2 * qb + 2;

        auto issue = [&](int kb, int st) {
            const unsigned sb = uS + (unsigned)st * ASTG;
            const size_t t0 = (size_t)kb * 64 * DH;
            #pragma unroll
            for (int i = 0; i < 2; ++i) {
                const int ch  = tid + i * 256;
                const int row = ch >> 3;
                const int seg = ch & 7;
                const unsigned ro = (unsigned)(row * (AKVS * 2) + seg * 16);
                const size_t go = t0 + (size_t)ch * 8;
                cp16(sb + A_KH + ro, kh_b + go);
                cp16(sb + A_VH + ro, vh_b + go);
            }
        };

        issue(0, 0); cp_commit();
        issue(1, 1); cp_commit();

        #pragma unroll 1
        for (int kb = 0; kb < nkb; ++kb) {
            const int s = kb % 3;
            if (kb == nkb - 1) { cp_wait<0>(); } else { cp_wait<1>(); }
            __syncthreads();
            if (kb + 2 < nkb) { issue(kb + 2, (kb + 2) % 3); cp_commit(); }

            const unsigned sk = uS + (unsigned)s * ASTG;

            // ---- S = Q K^T (fp16 x1) ----
            float sx[8][4];
            #pragma unroll
            for (int i = 0; i < 8; ++i)
                #pragma unroll
                for (int jj = 0; jj < 4; ++jj) sx[i][jj] = 0.f;

            #pragma unroll
            for (int kc = 0; kc < 4; ++kc) {
                #pragma unroll
                for (int ntp = 0; ntp < 4; ++ntp) {
                    const unsigned off = (unsigned)(((ntp * 16 + rowB_) * AKVS + kc * 16 + colB_) * 2);
                    unsigned rh[4];
                    ldm4(rh, sk + A_KH + off);
                    mma16h(sx[ntp * 2],     qf[kc][0], qf[kc][1], qf[kc][2], qf[kc][3], rh[0], rh[1]);
                    mma16h(sx[ntp * 2 + 1], qf[kc][0], qf[kc][1], qf[kc][2], qf[kc][3], rh[2], rh[3]);
                }
            }

            // ---- causal mask ----
            if (kb * 64 + 63 > qb * 128 + wid * 16) {
                #pragma unroll
                for (int nt = 0; nt < 8; ++nt) {
                    const int k0 = kb * 64 + nt * 8 + c * 2;
                    if (k0 > row_lo)     sx[nt][0] = -1e30f;
                    if (k0 + 1 > row_lo) sx[nt][1] = -1e30f;
                    if (k0 > row_hi)     sx[nt][2] = -1e30f;
                    if (k0 + 1 > row_hi) sx[nt][3] = -1e30f;
                }
            }

            // ---- online softmax (log2 domain; p via ex2.approx.f16x2) ----
            float mx0 = -1e30f, mx1 = -1e30f;
            #pragma unroll
            for (int nt = 0; nt < 8; ++nt) {
                mx0 = fmaxf(mx0, fmaxf(sx[nt][0], sx[nt][1]));
                mx1 = fmaxf(mx1, fmaxf(sx[nt][2], sx[nt][3]));
            }
            mx0 = fmaxf(mx0, __shfl_xor_sync(0xffffffffu, mx0, 1));
            mx0 = fmaxf(mx0, __shfl_xor_sync(0xffffffffu, mx0, 2));
            mx1 = fmaxf(mx1, __shfl_xor_sync(0xffffffffu, mx1, 1));
            mx1 = fmaxf(mx1, __shfl_xor_sync(0xffffffffu, mx1, 2));
            const float mn0 = fmaxf(m_lo, mx0);
            const float al0 = ex2(m_lo - mn0);
            m_lo = mn0;
            const float mn1 = fmaxf(m_hi, mx1);
            const float al1 = ex2(m_hi - mn1);
            m_hi = mn1;

            unsigned pl2[8], ph2[8];
            #pragma unroll
            for (int nt = 0; nt < 8; ++nt) {
                __half2 t0 = __floats2half2_rn(sx[nt][0] - mn0, sx[nt][1] - mn0);
                pl2[nt] = ex2h2(*reinterpret_cast<unsigned*>(&t0));
                __half2 t1 = __floats2half2_rn(sx[nt][2] - mn1, sx[nt][3] - mn1);
                ph2[nt] = ex2h2(*reinterpret_cast<unsigned*>(&t1));
                o[nt][0] *= al0; o[nt][1] *= al0;
                o[nt][2] *= al1; o[nt][3] *= al1;
            }

            // ---- row sums via ones-column mma (exact f32 sum of f16 p) ----
            float ls4[4] = {0.f, 0.f, 0.f, 0.f};
            #pragma unroll
            for (int kc = 0; kc < 4; ++kc)
                mma16h(ls4, pl2[2*kc], ph2[2*kc], pl2[2*kc+1], ph2[2*kc+1], ONESH2, ONESH2);
            l_lo = l_lo * al0 + ls4[0];
            l_hi = l_hi * al1 + ls4[2];

            // ---- O += P V (fp16 P x fp16 V single) ----
            #pragma unroll
            for (int kc = 0; kc < 4; ++kc) {
                const unsigned a0 = pl2[2*kc];
                const unsigned a1 = ph2[2*kc];
                const unsigned a2 = pl2[2*kc+1];
                const unsigned a3 = ph2[2*kc+1];
                #pragma unroll
                for (int ntp = 0; ntp < 4; ++ntp) {
                    const unsigned off =
                        (unsigned)(((kc * 16 + vkey_) * AKVS + ntp * 16 + vd_) * 2);
                    unsigned vh[4];
                    ldm4t(vh, sk + A_VH + off);
                    mma16h(o[ntp * 2],     a0, a1, a2, a3, vh[0], vh[1]);
                    mma16h(o[ntp * 2 + 1], a0, a1, a2, a3, vh[2], vh[3]);
                }
            }
        }

        // ---- epilogue (y as fp16 single) ----
        const float inv_lo = 1.f / l_lo;
        const float inv_hi = 1.f / l_hi;

        const int bbv = bh / NH;
        const int hd  = bh % NH;
        const size_t alo = ((size_t)bbv * TT + row_lo) * DM + hd * DH + 2 * c;
        const size_t ahi = ((size_t)bbv * TT + row_hi) * DM + hd * DH + 2 * c;
        #pragma unroll
        for (int nt = 0; nt < 8; ++nt) {
            *(unsigned*)(g_yh + alo + nt * 8) = packh2(o[nt][0] * inv_lo, o[nt][1] * inv_lo);
            *(unsigned*)(g_yh + ahi + nt * 8) = packh2(o[nt][2] * inv_hi, o[nt][3] * inv_hi);
        }

        __syncthreads();   // protect smem stages before next item's prologue
    }
    (void)dummy;
}

// ---------------------------------------------------------------------------
extern "C" void kernel_launch(void* const* d_in, const int* in_sizes, int n_in,
                              void* d_out, int out_size)
{
    const float* x  = (const float*)d_in[0];
    const float* Wq = (const float*)d_in[1];
    const float* bq = (const float*)d_in[2];
    const float* Wk = (const float*)d_in[3];
    const float* bk = (const float*)d_in[4];
    const float* Wv = (const float*)d_in[5];
    const float* bv = (const float*)d_in[6];
    const float* Wp = (const float*)d_in[7];
    const float* bp = (const float*)d_in[8];
    float* out = (float*)d_out;

    unsigned short *xh, *wh, *h3, *yh;
    cudaGetSymbolAddress((void**)&xh, g_xh);
    cudaGetSymbolAddress((void**)&wh, g_wh);
    cudaGetSymbolAddress((void**)&h3, g_h3);
    cudaGetSymbolAddress((void**)&yh, g_yh);

    cudaFuncSetAttribute(gemm_f16<0>, cudaFuncAttributeMaxDynamicSharedMemorySize, GSMEM2);
    cudaFuncSetAttribute(gemm_f16<1>, cudaFuncAttributeMaxDynamicSharedMemorySize, GSMEM2);
    cudaFuncSetAttribute(attn_bf, cudaFuncAttributeMaxDynamicSharedMemorySize, ASMEM);

    // pre-pass conversions
    const int n4x = MROWS * DM / 4;
    const int n4w = DM * DM / 4;
    convert_x<<<(n4x + 255) / 256, 256>>>(x, xh, n4x);
    dim3 wgrid((n4w + 255) / 256, 4);
    convert_w4<<<wgrid, 256>>>(Wq, Wk, Wv, Wp, wh, n4w);

    // QKV: z=0 -> Q (scaled), z=1 -> K, z=2 -> V (all fp16 single)
    dim3 qkv_grid(DM / 128, MROWS / 128, 3);
    gemm_f16<0><<<qkv_grid, 256, GSMEM2>>>(xh, wh, bq, bk, bv, h3, nullptr);

    // attention (persistent, load-balanced)
    attn_bf<<<APERS, 256, ASMEM>>>(nullptr);

    // out-proj (fp32 out)
    dim3 proj_grid(DM / 128, MROWS / 128, 1);
    gemm_f16<1><<<proj_grid, 256, GSMEM2>>>(yh, wh, bp, bp, bp, nullptr, out);
}